// round 1
// baseline (speedup 1.0000x reference)
#include <cuda_runtime.h>
#include <cuda_bf16.h>
#include <math.h>

#define BATCH 8
#define NPTS 2048
#define DMODEL 384
#define NHEAD 6
#define DHEAD 64
#define KNN 8
#define MTOK (BATCH * NPTS)   // 16384

// ---------------- scratch (device globals; no allocation allowed) ----------
__device__ float g_f[MTOK * DMODEL];        // residual stream [M,384]
__device__ float g_nf[MTOK * DMODEL];       // ln1 output
__device__ float g_qkv[MTOK * 3 * DMODEL];  // [M,1152]
__device__ float g_attn[MTOK * DMODEL];     // attention pre-projection
__device__ float g_gq[MTOK * DMODEL];
__device__ float g_gk[MTOK * DMODEL];
__device__ float g_gv[MTOK * DMODEL];
__device__ float g_merged[MTOK * 2 * DMODEL]; // [M,768]: cols0-383 attn proj, 384-767 geom
__device__ float g_h[MTOK * DMODEL];        // ln2 output
__device__ float g_t[MTOK * 2 * DMODEL];    // ffn hidden
__device__ int   g_idx[MTOK * KNN];

// ---------------- LN1 + transpose: features [B,D,N] -> f,nf [B,N,D] --------
__global__ void prep_ln1(const float* __restrict__ feat,
                         const float* __restrict__ g, const float* __restrict__ b,
                         float* __restrict__ f, float* __restrict__ nf) {
    int m = blockIdx.x;
    int bb = m >> 11, n = m & 2047;
    const float* src = feat + (size_t)bb * DMODEL * NPTS + n;
    float v[3];
    float s = 0.f, s2 = 0.f;
#pragma unroll
    for (int i = 0; i < 3; i++) {
        int d = threadIdx.x + i * 128;
        float x = src[(size_t)d * NPTS];
        v[i] = x; s += x; s2 += x * x;
    }
#pragma unroll
    for (int o = 16; o; o >>= 1) {
        s  += __shfl_xor_sync(0xffffffffu, s, o);
        s2 += __shfl_xor_sync(0xffffffffu, s2, o);
    }
    __shared__ float sh[8];
    int w = threadIdx.x >> 5;
    if ((threadIdx.x & 31) == 0) { sh[w] = s; sh[4 + w] = s2; }
    __syncthreads();
    s  = sh[0] + sh[1] + sh[2] + sh[3];
    s2 = sh[4] + sh[5] + sh[6] + sh[7];
    float mean = s * (1.f / DMODEL);
    float var  = s2 * (1.f / DMODEL) - mean * mean;
    float rstd = rsqrtf(var + 1e-5f);
#pragma unroll
    for (int i = 0; i < 3; i++) {
        int d = threadIdx.x + i * 128;
        float x = v[i];
        f[(size_t)m * DMODEL + d]  = x;
        nf[(size_t)m * DMODEL + d] = (x - mean) * rstd * g[d] + b[d];
    }
}

// ---------------- LN2: f [M,384] -> h --------------------------------------
__global__ void ln2_k(const float* __restrict__ f,
                      const float* __restrict__ g, const float* __restrict__ b,
                      float* __restrict__ h) {
    int m = blockIdx.x;
    const float* row = f + (size_t)m * DMODEL;
    float v[3];
    float s = 0.f, s2 = 0.f;
#pragma unroll
    for (int i = 0; i < 3; i++) {
        int d = threadIdx.x + i * 128;
        float x = row[d];
        v[i] = x; s += x; s2 += x * x;
    }
#pragma unroll
    for (int o = 16; o; o >>= 1) {
        s  += __shfl_xor_sync(0xffffffffu, s, o);
        s2 += __shfl_xor_sync(0xffffffffu, s2, o);
    }
    __shared__ float sh[8];
    int w = threadIdx.x >> 5;
    if ((threadIdx.x & 31) == 0) { sh[w] = s; sh[4 + w] = s2; }
    __syncthreads();
    s  = sh[0] + sh[1] + sh[2] + sh[3];
    s2 = sh[4] + sh[5] + sh[6] + sh[7];
    float mean = s * (1.f / DMODEL);
    float var  = s2 * (1.f / DMODEL) - mean * mean;
    float rstd = rsqrtf(var + 1e-5f);
#pragma unroll
    for (int i = 0; i < 3; i++) {
        int d = threadIdx.x + i * 128;
        h[(size_t)m * DMODEL + d] = (v[i] - mean) * rstd * g[d] + b[d];
    }
}

// ---------------- brute force KNN top-8 ------------------------------------
__global__ void knn_kernel(const float* __restrict__ coords, int* __restrict__ idxout) {
    int bb = blockIdx.y;
    __shared__ float cx[NPTS], cy[NPTS], cz[NPTS], sq[NPTS];
    const float* cb = coords + (size_t)bb * 3 * NPTS;
    for (int i = threadIdx.x; i < NPTS; i += 256) {
        float x = cb[i], y = cb[NPTS + i], z = cb[2 * NPTS + i];
        cx[i] = x; cy[i] = y; cz[i] = z;
        sq[i] = x * x + y * y + z * z;
    }
    __syncthreads();
    int q = blockIdx.x * 256 + threadIdx.x;
    float qx = cx[q], qy = cy[q], qz = cz[q], qsq = sq[q];
    float bd[KNN]; int bi[KNN];
#pragma unroll
    for (int k = 0; k < KNN; k++) { bd[k] = 3.0e38f; bi[k] = 0; }
    for (int mi = 0; mi < NPTS; mi++) {
        float d = qsq + sq[mi] - 2.f * (qx * cx[mi] + qy * cy[mi] + qz * cz[mi]);
        if (d < bd[KNN - 1]) {
            int p = KNN - 1;
            while (p > 0 && bd[p - 1] > d) { bd[p] = bd[p - 1]; bi[p] = bi[p - 1]; p--; }
            bd[p] = d; bi[p] = mi;
        }
    }
#pragma unroll
    for (int k = 0; k < KNN; k++)
        idxout[((size_t)bb * NPTS + q) * KNN + k] = bi[k];
}

// ---------------- generic SIMT GEMM  C[M,N] = A[M,K] @ W[K,N] --------------
// EPI: 0 = store (+bias if non-null), 1 = bias+gelu(tanh), 2 = bias + add into C
template <int EPI>
__global__ __launch_bounds__(256)
void gemm_k(const float* __restrict__ A, const float* __restrict__ W,
            const float* __restrict__ bias, float* __restrict__ C,
            int M, int K, int N, int ldc) {
    __shared__ float As[16][65];
    __shared__ float Ws[16][64];
    int tid = threadIdx.x, tx = tid & 15, ty = tid >> 4;
    int rowBase = blockIdx.y * 64, colBase = blockIdx.x * 64;
    float acc[4][4];
#pragma unroll
    for (int i = 0; i < 4; i++)
#pragma unroll
        for (int j = 0; j < 4; j++) acc[i][j] = 0.f;

    for (int k0 = 0; k0 < K; k0 += 16) {
        __syncthreads();
        for (int i = tid; i < 1024; i += 256) {
            int r = i >> 4, c = i & 15;
            As[c][r] = A[(size_t)(rowBase + r) * K + k0 + c];
        }
        for (int i = tid; i < 1024; i += 256) {
            int c = i >> 6, jj = i & 63;
            Ws[c][jj] = W[(size_t)(k0 + c) * N + colBase + jj];
        }
        __syncthreads();
#pragma unroll
        for (int k = 0; k < 16; k++) {
            float a[4], w[4];
#pragma unroll
            for (int i = 0; i < 4; i++) a[i] = As[k][ty * 4 + i];
#pragma unroll
            for (int j = 0; j < 4; j++) w[j] = Ws[k][tx * 4 + j];
#pragma unroll
            for (int i = 0; i < 4; i++)
#pragma unroll
                for (int j = 0; j < 4; j++) acc[i][j] += a[i] * w[j];
        }
    }
#pragma unroll
    for (int i = 0; i < 4; i++) {
        int row = rowBase + ty * 4 + i;
#pragma unroll
        for (int j = 0; j < 4; j++) {
            int col = colBase + tx * 4 + j;
            float v = acc[i][j];
            if (bias) v += bias[col];
            if (EPI == 1) {
                float x3 = v * v * v;
                v = 0.5f * v * (1.f + tanhf(0.7978845608028654f * (v + 0.044715f * x3)));
            }
            size_t o = (size_t)row * ldc + col;
            if (EPI == 2) C[o] += v;
            else          C[o] = v;
        }
    }
}

// ---------------- flash attention (fp32, Br=Bc=64) -------------------------
// smem: Qs[64][65] | KP[64][65] (K tile, reused for P) | Vs[64][64]
#define ATT_SMEM ((64 * 65 + 64 * 65 + 64 * 64) * 4)

__global__ __launch_bounds__(256)
void attn_kernel(const float* __restrict__ qkv, float* __restrict__ attn_o) {
    extern __shared__ float sm[];
    float* Qs = sm;
    float* KP = sm + 64 * 65;
    float* Vs = sm + 2 * 64 * 65;
    int qt = blockIdx.x, h = blockIdx.y, bb = blockIdx.z;
    int tid = threadIdx.x, tx = tid & 15, ty = tid >> 4;
    const float* base = qkv + (size_t)bb * NPTS * (3 * DMODEL);

    for (int i = tid; i < 64 * 64; i += 256) {
        int r = i >> 6, d = i & 63;
        Qs[r * 65 + d] = base[(size_t)(qt * 64 + r) * 1152 + h * 64 + d];
    }
    float acc[4][4], mrow[4], lrow[4];
#pragma unroll
    for (int i = 0; i < 4; i++) {
        mrow[i] = -1e30f; lrow[i] = 0.f;
#pragma unroll
        for (int j = 0; j < 4; j++) acc[i][j] = 0.f;
    }

    for (int jt = 0; jt < NPTS / 64; jt++) {
        __syncthreads();
        for (int i = tid; i < 64 * 64; i += 256) {
            int r = i >> 6, d = i & 63;
            size_t rowo = (size_t)(jt * 64 + r) * 1152;
            KP[r * 65 + d] = base[rowo + 384 + h * 64 + d];
            Vs[r * 64 + d] = base[rowo + 768 + h * 64 + d];
        }
        __syncthreads();
        float s[4][4];
#pragma unroll
        for (int i = 0; i < 4; i++)
#pragma unroll
            for (int j = 0; j < 4; j++) s[i][j] = 0.f;
#pragma unroll 8
        for (int d = 0; d < 64; d++) {
            float qv[4], kv[4];
#pragma unroll
            for (int i = 0; i < 4; i++) qv[i] = Qs[(ty * 4 + i) * 65 + d];
#pragma unroll
            for (int j = 0; j < 4; j++) kv[j] = KP[(tx * 4 + j) * 65 + d];
#pragma unroll
            for (int i = 0; i < 4; i++)
#pragma unroll
                for (int j = 0; j < 4; j++) s[i][j] += qv[i] * kv[j];
        }
        // online softmax per q-row; 16 lanes with same ty cooperate (xor<16)
#pragma unroll
        for (int i = 0; i < 4; i++) {
            float mx = s[i][0];
#pragma unroll
            for (int j = 1; j < 4; j++) mx = fmaxf(mx, s[i][j]);
            mx *= 0.125f;
#pragma unroll
            for (int o = 8; o; o >>= 1) mx = fmaxf(mx, __shfl_xor_sync(0xffffffffu, mx, o));
            float mnew = fmaxf(mrow[i], mx);
            float corr = expf(mrow[i] - mnew);
            float rsum = 0.f;
#pragma unroll
            for (int j = 0; j < 4; j++) {
                s[i][j] = expf(s[i][j] * 0.125f - mnew);
                rsum += s[i][j];
            }
#pragma unroll
            for (int o = 8; o; o >>= 1) rsum += __shfl_xor_sync(0xffffffffu, rsum, o);
            lrow[i] = lrow[i] * corr + rsum;
            mrow[i] = mnew;
#pragma unroll
            for (int j = 0; j < 4; j++) acc[i][j] *= corr;
        }
        __syncthreads();   // everyone done reading KP as K
#pragma unroll
        for (int i = 0; i < 4; i++)
#pragma unroll
            for (int j = 0; j < 4; j++)
                KP[(ty * 4 + i) * 65 + tx * 4 + j] = s[i][j];   // P
        __syncthreads();
#pragma unroll 8
        for (int kc = 0; kc < 64; kc++) {
            float pv[4], vv[4];
#pragma unroll
            for (int i = 0; i < 4; i++) pv[i] = KP[(ty * 4 + i) * 65 + kc];
#pragma unroll
            for (int j = 0; j < 4; j++) vv[j] = Vs[kc * 64 + tx * 4 + j];
#pragma unroll
            for (int i = 0; i < 4; i++)
#pragma unroll
                for (int j = 0; j < 4; j++) acc[i][j] += pv[i] * vv[j];
        }
    }
#pragma unroll
    for (int i = 0; i < 4; i++) {
        float inv = 1.f / lrow[i];
        int n = qt * 64 + ty * 4 + i;
#pragma unroll
        for (int j = 0; j < 4; j++)
            attn_o[((size_t)(bb * NPTS + n)) * DMODEL + h * 64 + tx * 4 + j] = acc[i][j] * inv;
    }
}

// ---------------- geom branch: gather + softmax(K=8) -----------------------
__global__ void geom_kernel(const float* __restrict__ gq, const float* __restrict__ gk,
                            const float* __restrict__ gv, const int* __restrict__ idx,
                            float* __restrict__ merged) {
    int m = blockIdx.x;
    int bb = m >> 11;
    __shared__ float dots[KNN];
    __shared__ int nb[KNN];
    int tid = threadIdx.x, w = tid >> 5, lane = tid & 31;
    if (tid < KNN) nb[tid] = idx[(size_t)m * KNN + tid];
    __syncthreads();
    const float* qrow = gq + (size_t)m * DMODEL;
    const float* krow = gk + ((size_t)bb * NPTS + nb[w]) * DMODEL;
    float s = 0.f;
    for (int d = lane; d < DMODEL; d += 32) s += qrow[d] * krow[d];
#pragma unroll
    for (int o = 16; o; o >>= 1) s += __shfl_xor_sync(0xffffffffu, s, o);
    if (lane == 0) dots[w] = s * 0.05103103630798287f;  // 1/sqrt(384)
    __syncthreads();
    float mx = dots[0];
#pragma unroll
    for (int k = 1; k < KNN; k++) mx = fmaxf(mx, dots[k]);
    float p[KNN], sum = 0.f;
#pragma unroll
    for (int k = 0; k < KNN; k++) { p[k] = expf(dots[k] - mx); sum += p[k]; }
    float inv = 1.f / sum;
    for (int d = tid; d < DMODEL; d += 256) {
        float a = 0.f;
#pragma unroll
        for (int k = 0; k < KNN; k++)
            a += p[k] * gv[((size_t)bb * NPTS + nb[k]) * DMODEL + d];
        merged[(size_t)m * 768 + 384 + d] = a * inv;
    }
}

// ---------------- output transpose f [B,N,D] -> out [B,D,N] ----------------
__global__ void out_transpose(const float* __restrict__ f, float* __restrict__ out) {
    __shared__ float tile[32][33];
    int bb = blockIdx.z;
    int n0 = blockIdx.x * 32, d0 = blockIdx.y * 32;
    int tx = threadIdx.x, ty = threadIdx.y;
#pragma unroll
    for (int i = 0; i < 32; i += 8)
        tile[ty + i][tx] = f[((size_t)bb * NPTS + n0 + ty + i) * DMODEL + d0 + tx];
    __syncthreads();
#pragma unroll
    for (int i = 0; i < 32; i += 8)
        out[((size_t)bb * DMODEL + d0 + ty + i) * NPTS + n0 + tx] = tile[tx][ty + i];
}

// ---------------- launch ----------------------------------------------------
extern "C" void kernel_launch(void* const* d_in, const int* in_sizes, int n_in,
                              void* d_out, int out_size) {
    const float* coords     = (const float*)d_in[0];
    const float* features   = (const float*)d_in[1];
    const float* ln1_g      = (const float*)d_in[2];
    const float* ln1_b      = (const float*)d_in[3];
    const float* w_qkv      = (const float*)d_in[4];
    const float* w_attn_out = (const float*)d_in[5];
    const float* b_attn_out = (const float*)d_in[6];
    const float* ga_wq      = (const float*)d_in[7];
    const float* ga_wk      = (const float*)d_in[8];
    const float* ga_wv      = (const float*)d_in[9];
    const float* merge_w    = (const float*)d_in[10];
    const float* merge_b    = (const float*)d_in[11];
    const float* ln2_g      = (const float*)d_in[12];
    const float* ln2_b      = (const float*)d_in[13];
    const float* ff_w1      = (const float*)d_in[14];
    const float* ff_b1      = (const float*)d_in[15];
    const float* ff_w2      = (const float*)d_in[16];
    const float* ff_b2      = (const float*)d_in[17];
    float* out = (float*)d_out;

    float *pf, *pnf, *pqkv, *pattn, *pgq, *pgk, *pgv, *pmerged, *ph, *pt;
    int* pidx;
    cudaGetSymbolAddress((void**)&pf, g_f);
    cudaGetSymbolAddress((void**)&pnf, g_nf);
    cudaGetSymbolAddress((void**)&pqkv, g_qkv);
    cudaGetSymbolAddress((void**)&pattn, g_attn);
    cudaGetSymbolAddress((void**)&pgq, g_gq);
    cudaGetSymbolAddress((void**)&pgk, g_gk);
    cudaGetSymbolAddress((void**)&pgv, g_gv);
    cudaGetSymbolAddress((void**)&pmerged, g_merged);
    cudaGetSymbolAddress((void**)&ph, g_h);
    cudaGetSymbolAddress((void**)&pt, g_t);
    cudaGetSymbolAddress((void**)&pidx, g_idx);

    cudaFuncSetAttribute(attn_kernel, cudaFuncAttributeMaxDynamicSharedMemorySize, ATT_SMEM);

    // LN1 + transpose
    prep_ln1<<<MTOK, 128>>>(features, ln1_g, ln1_b, pf, pnf);
    // KNN indices
    knn_kernel<<<dim3(NPTS / 256, BATCH), 256>>>(coords, pidx);
    // QKV projection
    gemm_k<0><<<dim3(1152 / 64, MTOK / 64), 256>>>(pnf, w_qkv, nullptr, pqkv, MTOK, 384, 1152, 1152);
    // dense attention
    attn_kernel<<<dim3(NPTS / 64, NHEAD, BATCH), 256, ATT_SMEM>>>(pqkv, pattn);
    // attention output projection -> merged[:, :384]
    gemm_k<0><<<dim3(384 / 64, MTOK / 64), 256>>>(pattn, w_attn_out, b_attn_out, pmerged, MTOK, 384, 384, 768);
    // graph-attention projections (gather commutes with GEMM: project first, gather later)
    gemm_k<0><<<dim3(384 / 64, MTOK / 64), 256>>>(pnf, ga_wq, nullptr, pgq, MTOK, 384, 384, 384);
    gemm_k<0><<<dim3(384 / 64, MTOK / 64), 256>>>(pnf, ga_wk, nullptr, pgk, MTOK, 384, 384, 384);
    gemm_k<0><<<dim3(384 / 64, MTOK / 64), 256>>>(pnf, ga_wv, nullptr, pgv, MTOK, 384, 384, 384);
    // geom branch -> merged[:, 384:]
    geom_kernel<<<MTOK, 256>>>(pgq, pgk, pgv, pidx, pmerged);
    // merge projection + residual add into f
    gemm_k<2><<<dim3(384 / 64, MTOK / 64), 256>>>(pmerged, merge_w, merge_b, pf, MTOK, 768, 384, 384);
    // LN2
    ln2_k<<<MTOK, 128>>>(pf, ln2_g, ln2_b, ph);
    // FFN
    gemm_k<1><<<dim3(768 / 64, MTOK / 64), 256>>>(ph, ff_w1, ff_b1, pt, MTOK, 384, 768, 768);
    gemm_k<2><<<dim3(384 / 64, MTOK / 64), 256>>>(pt, ff_w2, ff_b2, pf, MTOK, 768, 384, 384);
    // final transpose to [B, D, N]
    out_transpose<<<dim3(NPTS / 32, DMODEL / 32, BATCH), dim3(32, 8)>>>(pf, out);
}

// round 3
// speedup vs baseline: 1.0440x; 1.0440x over previous
#include <cuda_runtime.h>
#include <cuda_bf16.h>
#include <math.h>

#define BATCH 8
#define NPTS 2048
#define DMODEL 384
#define NHEAD 6
#define DHEAD 64
#define KNN 8
#define MTOK (BATCH * NPTS)   // 16384

// ---------------- scratch (device globals; no allocation allowed) ----------
__device__ float g_f[MTOK * DMODEL];
__device__ float g_nf[MTOK * DMODEL];
__device__ float g_qkv[MTOK * 3 * DMODEL];
__device__ float g_attn[MTOK * DMODEL];
__device__ float g_gq[MTOK * DMODEL];
__device__ float g_gk[MTOK * DMODEL];
__device__ float g_gv[MTOK * DMODEL];
__device__ float g_merged[MTOK * 2 * DMODEL];
__device__ float g_h[MTOK * DMODEL];
__device__ float g_t[MTOK * 2 * DMODEL];
__device__ int   g_idx[MTOK * KNN];

// ---------------- tf32 helpers ---------------------------------------------
__device__ __forceinline__ float2 tf32_split(float x) {
    unsigned hb; asm("cvt.rna.tf32.f32 %0, %1;" : "=r"(hb) : "f"(x));
    float h = __uint_as_float(hb);
    float r = x - h;
    unsigned lb; asm("cvt.rna.tf32.f32 %0, %1;" : "=r"(lb) : "f"(r));
    return make_float2(h, __uint_as_float(lb));
}

__device__ __forceinline__ void mma_tf32(float* c, const unsigned* a, unsigned b0, unsigned b1) {
    asm volatile("mma.sync.aligned.m16n8k8.row.col.f32.tf32.tf32.f32 "
        "{%0,%1,%2,%3}, {%4,%5,%6,%7}, {%8,%9}, {%0,%1,%2,%3};"
        : "+f"(c[0]), "+f"(c[1]), "+f"(c[2]), "+f"(c[3])
        : "r"(a[0]), "r"(a[1]), "r"(a[2]), "r"(a[3]), "r"(b0), "r"(b1));
}

// ---------------- LN1 + transpose ------------------------------------------
__global__ void prep_ln1(const float* __restrict__ feat,
                         const float* __restrict__ g, const float* __restrict__ b,
                         float* __restrict__ f, float* __restrict__ nf) {
    int m = blockIdx.x;
    int bb = m >> 11, n = m & 2047;
    const float* src = feat + (size_t)bb * DMODEL * NPTS + n;
    float v[3];
    float s = 0.f, s2 = 0.f;
#pragma unroll
    for (int i = 0; i < 3; i++) {
        int d = threadIdx.x + i * 128;
        float x = src[(size_t)d * NPTS];
        v[i] = x; s += x; s2 += x * x;
    }
#pragma unroll
    for (int o = 16; o; o >>= 1) {
        s  += __shfl_xor_sync(0xffffffffu, s, o);
        s2 += __shfl_xor_sync(0xffffffffu, s2, o);
    }
    __shared__ float sh[8];
    int w = threadIdx.x >> 5;
    if ((threadIdx.x & 31) == 0) { sh[w] = s; sh[4 + w] = s2; }
    __syncthreads();
    s  = sh[0] + sh[1] + sh[2] + sh[3];
    s2 = sh[4] + sh[5] + sh[6] + sh[7];
    float mean = s * (1.f / DMODEL);
    float var  = s2 * (1.f / DMODEL) - mean * mean;
    float rstd = rsqrtf(var + 1e-5f);
#pragma unroll
    for (int i = 0; i < 3; i++) {
        int d = threadIdx.x + i * 128;
        float x = v[i];
        f[(size_t)m * DMODEL + d]  = x;
        nf[(size_t)m * DMODEL + d] = (x - mean) * rstd * g[d] + b[d];
    }
}

// ---------------- LN2 -------------------------------------------------------
__global__ void ln2_k(const float* __restrict__ f,
                      const float* __restrict__ g, const float* __restrict__ b,
                      float* __restrict__ h) {
    int m = blockIdx.x;
    const float* row = f + (size_t)m * DMODEL;
    float v[3];
    float s = 0.f, s2 = 0.f;
#pragma unroll
    for (int i = 0; i < 3; i++) {
        int d = threadIdx.x + i * 128;
        float x = row[d];
        v[i] = x; s += x; s2 += x * x;
    }
#pragma unroll
    for (int o = 16; o; o >>= 1) {
        s  += __shfl_xor_sync(0xffffffffu, s, o);
        s2 += __shfl_xor_sync(0xffffffffu, s2, o);
    }
    __shared__ float sh[8];
    int w = threadIdx.x >> 5;
    if ((threadIdx.x & 31) == 0) { sh[w] = s; sh[4 + w] = s2; }
    __syncthreads();
    s  = sh[0] + sh[1] + sh[2] + sh[3];
    s2 = sh[4] + sh[5] + sh[6] + sh[7];
    float mean = s * (1.f / DMODEL);
    float var  = s2 * (1.f / DMODEL) - mean * mean;
    float rstd = rsqrtf(var + 1e-5f);
#pragma unroll
    for (int i = 0; i < 3; i++) {
        int d = threadIdx.x + i * 128;
        h[(size_t)m * DMODEL + d] = (v[i] - mean) * rstd * g[d] + b[d];
    }
}

// ---------------- brute force KNN top-8 ------------------------------------
__global__ void knn_kernel(const float* __restrict__ coords, int* __restrict__ idxout) {
    int bb = blockIdx.y;
    __shared__ float cx[NPTS], cy[NPTS], cz[NPTS], sq[NPTS];
    const float* cb = coords + (size_t)bb * 3 * NPTS;
    for (int i = threadIdx.x; i < NPTS; i += 256) {
        float x = cb[i], y = cb[NPTS + i], z = cb[2 * NPTS + i];
        cx[i] = x; cy[i] = y; cz[i] = z;
        sq[i] = x * x + y * y + z * z;
    }
    __syncthreads();
    int q = blockIdx.x * 256 + threadIdx.x;
    float qx = cx[q], qy = cy[q], qz = cz[q], qsq = sq[q];
    float bd[KNN]; int bi[KNN];
#pragma unroll
    for (int k = 0; k < KNN; k++) { bd[k] = 3.0e38f; bi[k] = 0; }
    for (int mi = 0; mi < NPTS; mi++) {
        float d = qsq + sq[mi] - 2.f * (qx * cx[mi] + qy * cy[mi] + qz * cz[mi]);
        if (d < bd[KNN - 1]) {
            int p = KNN - 1;
            while (p > 0 && bd[p - 1] > d) { bd[p] = bd[p - 1]; bi[p] = bi[p - 1]; p--; }
            bd[p] = d; bi[p] = mi;
        }
    }
#pragma unroll
    for (int k = 0; k < KNN; k++)
        idxout[((size_t)bb * NPTS + q) * KNN + k] = bi[k];
}

// ---------------- tensor-core GEMM (tf32x3)  C[M,N] = A[M,K] @ W[K,N] -------
// Block 128x64, 8 warps in 4x2 grid, warp tile 32x32, BK=32.
// smem (dynamic): Ah[32][132] Al[32][132] Bh[32][68] Bl[32][68]  = 51200 B
#define GEMM_SMEM ((2 * 32 * 132 + 2 * 32 * 68) * 4)

template <int EPI>
__global__ __launch_bounds__(256)
void gemm_tc(const float* __restrict__ A, const float* __restrict__ W,
             const float* __restrict__ bias, float* __restrict__ C,
             int M, int K, int N, int ldc) {
    extern __shared__ float sm[];
    float* Ah = sm;                  // [k][row] stride 132
    float* Al = Ah + 32 * 132;
    float* Bh = Al + 32 * 132;       // [k][col] stride 68
    float* Bl = Bh + 32 * 68;
    const unsigned* Ahu = (const unsigned*)Ah;
    const unsigned* Alu = (const unsigned*)Al;
    const unsigned* Bhu = (const unsigned*)Bh;
    const unsigned* Blu = (const unsigned*)Bl;

    int tid = threadIdx.x;
    int w = tid >> 5, lane = tid & 31;
    int gid = lane >> 2, tig = lane & 3;
    int wm = w >> 1, wn = w & 1;
    int rowBase = blockIdx.y * 128, colBase = blockIdx.x * 64;

    float c[2][4][4];
#pragma unroll
    for (int mt = 0; mt < 2; mt++)
#pragma unroll
        for (int j = 0; j < 4; j++)
#pragma unroll
            for (int e = 0; e < 4; e++) c[mt][j][e] = 0.f;

    for (int k0 = 0; k0 < K; k0 += 32) {
        __syncthreads();
        // load A tile 128x32 (coalesced rows of 32)
#pragma unroll
        for (int i = 0; i < 16; i++) {
            int e = tid + i * 256;
            int r = e >> 5, kk = e & 31;
            float2 hl = tf32_split(A[(size_t)(rowBase + r) * K + k0 + kk]);
            Ah[kk * 132 + r] = hl.x;
            Al[kk * 132 + r] = hl.y;
        }
        // load B tile 32x64
#pragma unroll
        for (int i = 0; i < 8; i++) {
            int e = tid + i * 256;
            int kk = e >> 6, cc = e & 63;
            float2 hl = tf32_split(W[(size_t)(k0 + kk) * N + colBase + cc]);
            Bh[kk * 68 + cc] = hl.x;
            Bl[kk * 68 + cc] = hl.y;
        }
        __syncthreads();
#pragma unroll
        for (int ks = 0; ks < 32; ks += 8) {
            unsigned ah[2][4], al[2][4];
#pragma unroll
            for (int mt = 0; mt < 2; mt++) {
                int r0 = wm * 32 + mt * 16 + gid;
                ah[mt][0] = Ahu[(ks + tig) * 132 + r0];
                ah[mt][1] = Ahu[(ks + tig) * 132 + r0 + 8];
                ah[mt][2] = Ahu[(ks + tig + 4) * 132 + r0];
                ah[mt][3] = Ahu[(ks + tig + 4) * 132 + r0 + 8];
                al[mt][0] = Alu[(ks + tig) * 132 + r0];
                al[mt][1] = Alu[(ks + tig) * 132 + r0 + 8];
                al[mt][2] = Alu[(ks + tig + 4) * 132 + r0];
                al[mt][3] = Alu[(ks + tig + 4) * 132 + r0 + 8];
            }
#pragma unroll
            for (int j = 0; j < 4; j++) {
                int nc = wn * 32 + j * 8 + gid;
                unsigned bh0 = Bhu[(ks + tig) * 68 + nc];
                unsigned bh1 = Bhu[(ks + tig + 4) * 68 + nc];
                unsigned bl0 = Blu[(ks + tig) * 68 + nc];
                unsigned bl1 = Blu[(ks + tig + 4) * 68 + nc];
#pragma unroll
                for (int mt = 0; mt < 2; mt++) {
                    mma_tf32(c[mt][j], ah[mt], bh0, bh1);
                    mma_tf32(c[mt][j], ah[mt], bl0, bl1);
                    mma_tf32(c[mt][j], al[mt], bh0, bh1);
                }
            }
        }
    }
    // epilogue: each (mt,j): rows r,r+8 ; cols cc,cc+1 (float2)
#pragma unroll
    for (int mt = 0; mt < 2; mt++) {
#pragma unroll
        for (int j = 0; j < 4; j++) {
            int r = rowBase + wm * 32 + mt * 16 + gid;
            int cc = colBase + wn * 32 + j * 8 + tig * 2;
            float b0 = bias ? bias[cc] : 0.f;
            float b1 = bias ? bias[cc + 1] : 0.f;
#pragma unroll
            for (int half = 0; half < 2; half++) {
                int rr = r + half * 8;
                float v0 = c[mt][j][half * 2 + 0] + b0;
                float v1 = c[mt][j][half * 2 + 1] + b1;
                if (EPI == 1) {
                    float x3 = v0 * v0 * v0;
                    v0 = 0.5f * v0 * (1.f + tanhf(0.7978845608028654f * (v0 + 0.044715f * x3)));
                    x3 = v1 * v1 * v1;
                    v1 = 0.5f * v1 * (1.f + tanhf(0.7978845608028654f * (v1 + 0.044715f * x3)));
                }
                float2* dst = (float2*)(C + (size_t)rr * ldc + cc);
                if (EPI == 2) {
                    float2 old = *dst;
                    dst->x = old.x + v0; dst->y = old.y + v1;
                } else {
                    *dst = make_float2(v0, v1);
                }
            }
        }
    }
}

// ---------------- tensor-core flash attention (tf32x3) ----------------------
// Block: 64 q-rows x one head. 8 warps. Chunks of 64 kv.
// smem: Qh Ql Kh Kl Vh Vl SP Pl each [64][68] + mrow/lrow/crow[64]
#define AST 68
#define ATT_SMEM ((8 * 64 * AST + 3 * 64) * 4)

__global__ __launch_bounds__(256, 1)
void attn_tc(const float* __restrict__ qkv, float* __restrict__ attn_o) {
    extern __shared__ float sm[];
    float* Qh = sm;
    float* Ql = Qh + 64 * AST;
    float* Kh = Ql + 64 * AST;
    float* Kl = Kh + 64 * AST;
    float* Vh = Kl + 64 * AST;
    float* Vl = Vh + 64 * AST;
    float* SP = Vl + 64 * AST;   // S scores, then P-hi (alias safe)
    float* Pl = SP + 64 * AST;
    float* mrow = Pl + 64 * AST;
    float* lrow = mrow + 64;
    float* crow = lrow + 64;
    const unsigned* Qhu = (const unsigned*)Qh;
    const unsigned* Qlu = (const unsigned*)Ql;
    const unsigned* Khu = (const unsigned*)Kh;
    const unsigned* Klu = (const unsigned*)Kl;
    const unsigned* Vhu = (const unsigned*)Vh;
    const unsigned* Vlu = (const unsigned*)Vl;
    const unsigned* SPu = (const unsigned*)SP;
    const unsigned* Plu = (const unsigned*)Pl;

    int qt = blockIdx.x, h = blockIdx.y, bb = blockIdx.z;
    int tid = threadIdx.x;
    int w = tid >> 5, lane = tid & 31;
    int gid = lane >> 2, tig = lane & 3;
    int qs = (w >> 1) * 16;        // q strip for this warp
    int hs = (w & 1) * 32;         // kv-half (S) / d-half (O)
    const float* base = qkv + (size_t)bb * NPTS * 1152;

    // load Q (64x64) hi/lo
#pragma unroll
    for (int i = 0; i < 16; i++) {
        int e = tid + i * 256;
        int r = e >> 6, d = e & 63;
        float2 hl = tf32_split(base[(size_t)(qt * 64 + r) * 1152 + h * 64 + d]);
        Qh[r * AST + d] = hl.x;
        Ql[r * AST + d] = hl.y;
    }
    if (tid < 64) { mrow[tid] = -1e30f; lrow[tid] = 0.f; }

    float oc[4][4];
#pragma unroll
    for (int j = 0; j < 4; j++)
#pragma unroll
        for (int e = 0; e < 4; e++) oc[j][e] = 0.f;

    for (int jt = 0; jt < NPTS / 64; jt++) {
        __syncthreads();   // previous chunk's P@V done; safe to overwrite K/V
#pragma unroll
        for (int i = 0; i < 16; i++) {
            int e = tid + i * 256;
            int r = e >> 6, d = e & 63;
            size_t rowo = (size_t)(jt * 64 + r) * 1152 + h * 64 + d;
            float2 khl = tf32_split(base[rowo + 384]);
            Kh[r * AST + d] = khl.x;
            Kl[r * AST + d] = khl.y;
            float2 vhl = tf32_split(base[rowo + 768]);
            Vh[r * AST + d] = vhl.x;
            Vl[r * AST + d] = vhl.y;
        }
        __syncthreads();

        // --- S = Q @ K^T (warp: 16q x 32kv) ---
        float sc[4][4];
#pragma unroll
        for (int j = 0; j < 4; j++)
#pragma unroll
            for (int e = 0; e < 4; e++) sc[j][e] = 0.f;
#pragma unroll
        for (int d0 = 0; d0 < 64; d0 += 8) {
            unsigned ah[4], al[4];
            ah[0] = Qhu[(qs + gid) * AST + d0 + tig];
            ah[1] = Qhu[(qs + gid + 8) * AST + d0 + tig];
            ah[2] = Qhu[(qs + gid) * AST + d0 + tig + 4];
            ah[3] = Qhu[(qs + gid + 8) * AST + d0 + tig + 4];
            al[0] = Qlu[(qs + gid) * AST + d0 + tig];
            al[1] = Qlu[(qs + gid + 8) * AST + d0 + tig];
            al[2] = Qlu[(qs + gid) * AST + d0 + tig + 4];
            al[3] = Qlu[(qs + gid + 8) * AST + d0 + tig + 4];
#pragma unroll
            for (int j = 0; j < 4; j++) {
                int kv = hs + j * 8 + gid;
                unsigned bh0 = Khu[kv * AST + d0 + tig];
                unsigned bh1 = Khu[kv * AST + d0 + tig + 4];
                unsigned bl0 = Klu[kv * AST + d0 + tig];
                unsigned bl1 = Klu[kv * AST + d0 + tig + 4];
                mma_tf32(sc[j], ah, bh0, bh1);
                mma_tf32(sc[j], ah, bl0, bl1);
                mma_tf32(sc[j], al, bh0, bh1);
            }
        }
        // store scaled S to smem
#pragma unroll
        for (int j = 0; j < 4; j++) {
            int cc = hs + j * 8 + tig * 2;
            SP[(qs + gid) * AST + cc]     = sc[j][0] * 0.125f;
            SP[(qs + gid) * AST + cc + 1] = sc[j][1] * 0.125f;
            SP[(qs + gid + 8) * AST + cc]     = sc[j][2] * 0.125f;
            SP[(qs + gid + 8) * AST + cc + 1] = sc[j][3] * 0.125f;
        }
        __syncthreads();

        // --- online softmax: 4 threads per row, 16 cols each ---
        {
            int row = tid >> 2, q4 = tid & 3;
            float sv[16];
            float mx = -1e30f;
#pragma unroll
            for (int i = 0; i < 16; i++) {
                sv[i] = SP[row * AST + q4 * 16 + i];
                mx = fmaxf(mx, sv[i]);
            }
            mx = fmaxf(mx, __shfl_xor_sync(0xffffffffu, mx, 1));
            mx = fmaxf(mx, __shfl_xor_sync(0xffffffffu, mx, 2));
            float mold = mrow[row];
            float mnew = fmaxf(mold, mx);
            float sum = 0.f;
#pragma unroll
            for (int i = 0; i < 16; i++) {
                float p = __expf(sv[i] - mnew);
                sum += p;
                float2 hl = tf32_split(p);
                SP[row * AST + q4 * 16 + i] = hl.x;
                Pl[row * AST + q4 * 16 + i] = hl.y;
            }
            sum += __shfl_xor_sync(0xffffffffu, sum, 1);
            sum += __shfl_xor_sync(0xffffffffu, sum, 2);
            if (q4 == 0) {
                float corr = __expf(mold - mnew);
                crow[row] = corr;
                lrow[row] = lrow[row] * corr + sum;
                mrow[row] = mnew;
            }
        }
        __syncthreads();

        // --- rescale O, then O += P @ V (warp: 16q x 32d) ---
        {
            float c0 = crow[qs + gid];
            float c1 = crow[qs + gid + 8];
#pragma unroll
            for (int j = 0; j < 4; j++) {
                oc[j][0] *= c0; oc[j][1] *= c0;
                oc[j][2] *= c1; oc[j][3] *= c1;
            }
        }
#pragma unroll
        for (int kv0 = 0; kv0 < 64; kv0 += 8) {
            unsigned ah[4], al[4];
            ah[0] = SPu[(qs + gid) * AST + kv0 + tig];
            ah[1] = SPu[(qs + gid + 8) * AST + kv0 + tig];
            ah[2] = SPu[(qs + gid) * AST + kv0 + tig + 4];
            ah[3] = SPu[(qs + gid + 8) * AST + kv0 + tig + 4];
            al[0] = Plu[(qs + gid) * AST + kv0 + tig];
            al[1] = Plu[(qs + gid + 8) * AST + kv0 + tig];
            al[2] = Plu[(qs + gid) * AST + kv0 + tig + 4];
            al[3] = Plu[(qs + gid + 8) * AST + kv0 + tig + 4];
#pragma unroll
            for (int j = 0; j < 4; j++) {
                int dc = hs + j * 8 + gid;
                unsigned bh0 = Vhu[(kv0 + tig) * AST + dc];
                unsigned bh1 = Vhu[(kv0 + tig + 4) * AST + dc];
                unsigned bl0 = Vlu[(kv0 + tig) * AST + dc];
                unsigned bl1 = Vlu[(kv0 + tig + 4) * AST + dc];
                mma_tf32(oc[j], ah, bh0, bh1);
                mma_tf32(oc[j], ah, bl0, bl1);
                mma_tf32(oc[j], al, bh0, bh1);
            }
        }
    }
    __syncthreads();
    // epilogue: normalize and store
    {
        float inv0 = 1.f / lrow[qs + gid];
        float inv1 = 1.f / lrow[qs + gid + 8];
#pragma unroll
        for (int j = 0; j < 4; j++) {
            int cc = h * 64 + hs + j * 8 + tig * 2;
            int r0 = bb * NPTS + qt * 64 + qs + gid;
            float2* d0 = (float2*)(attn_o + (size_t)r0 * DMODEL + cc);
            *d0 = make_float2(oc[j][0] * inv0, oc[j][1] * inv0);
            float2* d1 = (float2*)(attn_o + (size_t)(r0 + 8) * DMODEL + cc);
            *d1 = make_float2(oc[j][2] * inv1, oc[j][3] * inv1);
        }
    }
}

// ---------------- geom branch: gather + softmax(K=8) -----------------------
__global__ void geom_kernel(const float* __restrict__ gq, const float* __restrict__ gk,
                            const float* __restrict__ gv, const int* __restrict__ idx,
                            float* __restrict__ merged) {
    int m = blockIdx.x;
    int bb = m >> 11;
    __shared__ float dots[KNN];
    __shared__ int nb[KNN];
    int tid = threadIdx.x, w = tid >> 5, lane = tid & 31;
    if (tid < KNN) nb[tid] = idx[(size_t)m * KNN + tid];
    __syncthreads();
    const float* qrow = gq + (size_t)m * DMODEL;
    const float* krow = gk + ((size_t)bb * NPTS + nb[w]) * DMODEL;
    float s = 0.f;
    for (int d = lane; d < DMODEL; d += 32) s += qrow[d] * krow[d];
#pragma unroll
    for (int o = 16; o; o >>= 1) s += __shfl_xor_sync(0xffffffffu, s, o);
    if (lane == 0) dots[w] = s * 0.05103103630798287f;
    __syncthreads();
    float mx = dots[0];
#pragma unroll
    for (int k = 1; k < KNN; k++) mx = fmaxf(mx, dots[k]);
    float p[KNN], sum = 0.f;
#pragma unroll
    for (int k = 0; k < KNN; k++) { p[k] = expf(dots[k] - mx); sum += p[k]; }
    float inv = 1.f / sum;
    for (int d = tid; d < DMODEL; d += 256) {
        float a = 0.f;
#pragma unroll
        for (int k = 0; k < KNN; k++)
            a += p[k] * gv[((size_t)bb * NPTS + nb[k]) * DMODEL + d];
        merged[(size_t)m * 768 + 384 + d] = a * inv;
    }
}

// ---------------- output transpose -----------------------------------------
__global__ void out_transpose(const float* __restrict__ f, float* __restrict__ out) {
    __shared__ float tile[32][33];
    int bb = blockIdx.z;
    int n0 = blockIdx.x * 32, d0 = blockIdx.y * 32;
    int tx = threadIdx.x, ty = threadIdx.y;
#pragma unroll
    for (int i = 0; i < 32; i += 8)
        tile[ty + i][tx] = f[((size_t)bb * NPTS + n0 + ty + i) * DMODEL + d0 + tx];
    __syncthreads();
#pragma unroll
    for (int i = 0; i < 32; i += 8)
        out[((size_t)bb * DMODEL + d0 + ty + i) * NPTS + n0 + tx] = tile[tx][ty + i];
}

// ---------------- launch ----------------------------------------------------
extern "C" void kernel_launch(void* const* d_in, const int* in_sizes, int n_in,
                              void* d_out, int out_size) {
    const float* coords     = (const float*)d_in[0];
    const float* features   = (const float*)d_in[1];
    const float* ln1_g      = (const float*)d_in[2];
    const float* ln1_b      = (const float*)d_in[3];
    const float* w_qkv      = (const float*)d_in[4];
    const float* w_attn_out = (const float*)d_in[5];
    const float* b_attn_out = (const float*)d_in[6];
    const float* ga_wq      = (const float*)d_in[7];
    const float* ga_wk      = (const float*)d_in[8];
    const float* ga_wv      = (const float*)d_in[9];
    const float* merge_w    = (const float*)d_in[10];
    const float* merge_b    = (const float*)d_in[11];
    const float* ln2_g      = (const float*)d_in[12];
    const float* ln2_b      = (const float*)d_in[13];
    const float* ff_w1      = (const float*)d_in[14];
    const float* ff_b1      = (const float*)d_in[15];
    const float* ff_w2      = (const float*)d_in[16];
    const float* ff_b2      = (const float*)d_in[17];
    float* out = (float*)d_out;

    float *pf, *pnf, *pqkv, *pattn, *pgq, *pgk, *pgv, *pmerged, *ph, *pt;
    int* pidx;
    cudaGetSymbolAddress((void**)&pf, g_f);
    cudaGetSymbolAddress((void**)&pnf, g_nf);
    cudaGetSymbolAddress((void**)&pqkv, g_qkv);
    cudaGetSymbolAddress((void**)&pattn, g_attn);
    cudaGetSymbolAddress((void**)&pgq, g_gq);
    cudaGetSymbolAddress((void**)&pgk, g_gk);
    cudaGetSymbolAddress((void**)&pgv, g_gv);
    cudaGetSymbolAddress((void**)&pmerged, g_merged);
    cudaGetSymbolAddress((void**)&ph, g_h);
    cudaGetSymbolAddress((void**)&pt, g_t);
    cudaGetSymbolAddress((void**)&pidx, g_idx);

    cudaFuncSetAttribute(attn_tc, cudaFuncAttributeMaxDynamicSharedMemorySize, ATT_SMEM);
    cudaFuncSetAttribute(gemm_tc<0>, cudaFuncAttributeMaxDynamicSharedMemorySize, GEMM_SMEM);
    cudaFuncSetAttribute(gemm_tc<1>, cudaFuncAttributeMaxDynamicSharedMemorySize, GEMM_SMEM);
    cudaFuncSetAttribute(gemm_tc<2>, cudaFuncAttributeMaxDynamicSharedMemorySize, GEMM_SMEM);

    prep_ln1<<<MTOK, 128>>>(features, ln1_g, ln1_b, pf, pnf);
    knn_kernel<<<dim3(NPTS / 256, BATCH), 256>>>(coords, pidx);
    gemm_tc<0><<<dim3(1152 / 64, MTOK / 128), 256, GEMM_SMEM>>>(pnf, w_qkv, nullptr, pqkv, MTOK, 384, 1152, 1152);
    attn_tc<<<dim3(NPTS / 64, NHEAD, BATCH), 256, ATT_SMEM>>>(pqkv, pattn);
    gemm_tc<0><<<dim3(384 / 64, MTOK / 128), 256, GEMM_SMEM>>>(pattn, w_attn_out, b_attn_out, pmerged, MTOK, 384, 384, 768);
    gemm_tc<0><<<dim3(384 / 64, MTOK / 128), 256, GEMM_SMEM>>>(pnf, ga_wq, nullptr, pgq, MTOK, 384, 384, 384);
    gemm_tc<0><<<dim3(384 / 64, MTOK / 128), 256, GEMM_SMEM>>>(pnf, ga_wk, nullptr, pgk, MTOK, 384, 384, 384);
    gemm_tc<0><<<dim3(384 / 64, MTOK / 128), 256, GEMM_SMEM>>>(pnf, ga_wv, nullptr, pgv, MTOK, 384, 384, 384);
    geom_kernel<<<MTOK, 256>>>(pgq, pgk, pgv, pidx, pmerged);
    gemm_tc<2><<<dim3(384 / 64, MTOK / 128), 256, GEMM_SMEM>>>(pmerged, merge_w, merge_b, pf, MTOK, 768, 384, 384);
    ln2_k<<<MTOK, 128>>>(pf, ln2_g, ln2_b, ph);
    gemm_tc<1><<<dim3(768 / 64, MTOK / 128), 256, GEMM_SMEM>>>(ph, ff_w1, ff_b1, pt, MTOK, 384, 768, 768);
    gemm_tc<2><<<dim3(384 / 64, MTOK / 128), 256, GEMM_SMEM>>>(pt, ff_w2, ff_b2, pf, MTOK, 768, 384, 384);
    out_transpose<<<dim3(NPTS / 32, DMODEL / 32, BATCH), dim3(32, 8)>>>(pf, out);
}

// round 6
// speedup vs baseline: 1.7172x; 1.6448x over previous
#include <cuda_runtime.h>
#include <cuda_bf16.h>
#include <math.h>

#define BATCH 8
#define NPTS 2048
#define DMODEL 384
#define NHEAD 6
#define DHEAD 64
#define KNN 8
#define MTOK (BATCH * NPTS)   // 16384

// ---------------- scratch (device globals; no allocation allowed) ----------
__device__ float g_f[MTOK * DMODEL];
__device__ float g_nf[MTOK * DMODEL];
__device__ float g_qkv[MTOK * 3 * DMODEL];
__device__ float g_attn[MTOK * DMODEL];
__device__ float g_gq[MTOK * DMODEL];
__device__ float g_gk[MTOK * DMODEL];
__device__ float g_gv[MTOK * DMODEL];
__device__ float g_merged[MTOK * 2 * DMODEL];
__device__ float g_h[MTOK * DMODEL];
__device__ float g_t[MTOK * 2 * DMODEL];
__device__ int   g_idx[MTOK * KNN];

// ---------------- tf32 helpers ---------------------------------------------
__device__ __forceinline__ float tf32r(float x) {
    unsigned r; asm("cvt.rna.tf32.f32 %0, %1;" : "=r"(r) : "f"(x));
    return __uint_as_float(r);
}

__device__ __forceinline__ void mma_tf32(float* c, const unsigned* a, unsigned b0, unsigned b1) {
    asm volatile("mma.sync.aligned.m16n8k8.row.col.f32.tf32.tf32.f32 "
        "{%0,%1,%2,%3}, {%4,%5,%6,%7}, {%8,%9}, {%0,%1,%2,%3};"
        : "+f"(c[0]), "+f"(c[1]), "+f"(c[2]), "+f"(c[3])
        : "r"(a[0]), "r"(a[1]), "r"(a[2]), "r"(a[3]), "r"(b0), "r"(b1));
}

// ---------------- LN1 + transpose ------------------------------------------
__global__ void prep_ln1(const float* __restrict__ feat,
                         const float* __restrict__ g, const float* __restrict__ b,
                         float* __restrict__ f, float* __restrict__ nf) {
    int m = blockIdx.x;
    int bb = m >> 11, n = m & 2047;
    const float* src = feat + (size_t)bb * DMODEL * NPTS + n;
    float v[3];
    float s = 0.f, s2 = 0.f;
#pragma unroll
    for (int i = 0; i < 3; i++) {
        int d = threadIdx.x + i * 128;
        float x = src[(size_t)d * NPTS];
        v[i] = x; s += x; s2 += x * x;
    }
#pragma unroll
    for (int o = 16; o; o >>= 1) {
        s  += __shfl_xor_sync(0xffffffffu, s, o);
        s2 += __shfl_xor_sync(0xffffffffu, s2, o);
    }
    __shared__ float sh[8];
    int w = threadIdx.x >> 5;
    if ((threadIdx.x & 31) == 0) { sh[w] = s; sh[4 + w] = s2; }
    __syncthreads();
    s  = sh[0] + sh[1] + sh[2] + sh[3];
    s2 = sh[4] + sh[5] + sh[6] + sh[7];
    float mean = s * (1.f / DMODEL);
    float var  = s2 * (1.f / DMODEL) - mean * mean;
    float rstd = rsqrtf(var + 1e-5f);
#pragma unroll
    for (int i = 0; i < 3; i++) {
        int d = threadIdx.x + i * 128;
        float x = v[i];
        f[(size_t)m * DMODEL + d]  = x;
        nf[(size_t)m * DMODEL + d] = (x - mean) * rstd * g[d] + b[d];
    }
}

// ---------------- LN2 -------------------------------------------------------
__global__ void ln2_k(const float* __restrict__ f,
                      const float* __restrict__ g, const float* __restrict__ b,
                      float* __restrict__ h) {
    int m = blockIdx.x;
    const float* row = f + (size_t)m * DMODEL;
    float v[3];
    float s = 0.f, s2 = 0.f;
#pragma unroll
    for (int i = 0; i < 3; i++) {
        int d = threadIdx.x + i * 128;
        float x = row[d];
        v[i] = x; s += x; s2 += x * x;
    }
#pragma unroll
    for (int o = 16; o; o >>= 1) {
        s  += __shfl_xor_sync(0xffffffffu, s, o);
        s2 += __shfl_xor_sync(0xffffffffu, s2, o);
    }
    __shared__ float sh[8];
    int w = threadIdx.x >> 5;
    if ((threadIdx.x & 31) == 0) { sh[w] = s; sh[4 + w] = s2; }
    __syncthreads();
    s  = sh[0] + sh[1] + sh[2] + sh[3];
    s2 = sh[4] + sh[5] + sh[6] + sh[7];
    float mean = s * (1.f / DMODEL);
    float var  = s2 * (1.f / DMODEL) - mean * mean;
    float rstd = rsqrtf(var + 1e-5f);
#pragma unroll
    for (int i = 0; i < 3; i++) {
        int d = threadIdx.x + i * 128;
        h[(size_t)m * DMODEL + d] = (v[i] - mean) * rstd * g[d] + b[d];
    }
}

// ---------------- brute force KNN top-8 ------------------------------------
__global__ void knn_kernel(const float* __restrict__ coords, int* __restrict__ idxout) {
    int bb = blockIdx.y;
    __shared__ float cx[NPTS], cy[NPTS], cz[NPTS], sq[NPTS];
    const float* cb = coords + (size_t)bb * 3 * NPTS;
    for (int i = threadIdx.x; i < NPTS; i += 256) {
        float x = cb[i], y = cb[NPTS + i], z = cb[2 * NPTS + i];
        cx[i] = x; cy[i] = y; cz[i] = z;
        sq[i] = x * x + y * y + z * z;
    }
    __syncthreads();
    int q = blockIdx.x * 256 + threadIdx.x;
    float qx = cx[q], qy = cy[q], qz = cz[q], qsq = sq[q];
    float bd[KNN]; int bi[KNN];
#pragma unroll
    for (int k = 0; k < KNN; k++) { bd[k] = 3.0e38f; bi[k] = 0; }
    for (int mi = 0; mi < NPTS; mi++) {
        float d = qsq + sq[mi] - 2.f * (qx * cx[mi] + qy * cy[mi] + qz * cz[mi]);
        if (d < bd[KNN - 1]) {
            int p = KNN - 1;
            while (p > 0 && bd[p - 1] > d) { bd[p] = bd[p - 1]; bi[p] = bi[p - 1]; p--; }
            bd[p] = d; bi[p] = mi;
        }
    }
#pragma unroll
    for (int k = 0; k < KNN; k++)
        idxout[((size_t)bb * NPTS + q) * KNN + k] = bi[k];
}

// ---------------- tensor-core GEMM (plain tf32)  C = A @ W ------------------
// Block 128x64, 8 warps 4x2, warp tile 32x32, BK=32.
// smem: Ah[32][132] + Bh[32][68] = 25600 B  -> high occupancy
#define GEMM_SMEM ((32 * 132 + 32 * 68) * 4)

template <int EPI>
__global__ __launch_bounds__(256)
void gemm_tc(const float* __restrict__ A, const float* __restrict__ W,
             const float* __restrict__ bias, float* __restrict__ C,
             int M, int K, int N, int ldc) {
    extern __shared__ float sm[];
    float* Ah = sm;                  // [k][row] stride 132
    float* Bh = Ah + 32 * 132;       // [k][col] stride 68
    const unsigned* Ahu = (const unsigned*)Ah;
    const unsigned* Bhu = (const unsigned*)Bh;

    int tid = threadIdx.x;
    int w = tid >> 5, lane = tid & 31;
    int gid = lane >> 2, tig = lane & 3;
    int wm = w >> 1, wn = w & 1;
    int rowBase = blockIdx.y * 128, colBase = blockIdx.x * 64;

    float c[2][4][4];
#pragma unroll
    for (int mt = 0; mt < 2; mt++)
#pragma unroll
        for (int j = 0; j < 4; j++)
#pragma unroll
            for (int e = 0; e < 4; e++) c[mt][j][e] = 0.f;

    for (int k0 = 0; k0 < K; k0 += 32) {
        __syncthreads();
#pragma unroll
        for (int i = 0; i < 16; i++) {
            int e = tid + i * 256;
            int r = e >> 5, kk = e & 31;
            Ah[kk * 132 + r] = tf32r(A[(size_t)(rowBase + r) * K + k0 + kk]);
        }
#pragma unroll
        for (int i = 0; i < 8; i++) {
            int e = tid + i * 256;
            int kk = e >> 6, cc = e & 63;
            Bh[kk * 68 + cc] = tf32r(W[(size_t)(k0 + kk) * N + colBase + cc]);
        }
        __syncthreads();
#pragma unroll
        for (int ks = 0; ks < 32; ks += 8) {
            unsigned ah[2][4];
#pragma unroll
            for (int mt = 0; mt < 2; mt++) {
                int r0 = wm * 32 + mt * 16 + gid;
                ah[mt][0] = Ahu[(ks + tig) * 132 + r0];
                ah[mt][1] = Ahu[(ks + tig) * 132 + r0 + 8];
                ah[mt][2] = Ahu[(ks + tig + 4) * 132 + r0];
                ah[mt][3] = Ahu[(ks + tig + 4) * 132 + r0 + 8];
            }
#pragma unroll
            for (int j = 0; j < 4; j++) {
                int nc = wn * 32 + j * 8 + gid;
                unsigned bh0 = Bhu[(ks + tig) * 68 + nc];
                unsigned bh1 = Bhu[(ks + tig + 4) * 68 + nc];
#pragma unroll
                for (int mt = 0; mt < 2; mt++)
                    mma_tf32(c[mt][j], ah[mt], bh0, bh1);
            }
        }
    }
#pragma unroll
    for (int mt = 0; mt < 2; mt++) {
#pragma unroll
        for (int j = 0; j < 4; j++) {
            int r = rowBase + wm * 32 + mt * 16 + gid;
            int cc = colBase + wn * 32 + j * 8 + tig * 2;
            float b0 = bias ? bias[cc] : 0.f;
            float b1 = bias ? bias[cc + 1] : 0.f;
#pragma unroll
            for (int half = 0; half < 2; half++) {
                int rr = r + half * 8;
                float v0 = c[mt][j][half * 2 + 0] + b0;
                float v1 = c[mt][j][half * 2 + 1] + b1;
                if (EPI == 1) {
                    float x3 = v0 * v0 * v0;
                    v0 = 0.5f * v0 * (1.f + tanhf(0.7978845608028654f * (v0 + 0.044715f * x3)));
                    x3 = v1 * v1 * v1;
                    v1 = 0.5f * v1 * (1.f + tanhf(0.7978845608028654f * (v1 + 0.044715f * x3)));
                }
                float2* dst = (float2*)(C + (size_t)rr * ldc + cc);
                if (EPI == 2) {
                    float2 old = *dst;
                    dst->x = old.x + v0; dst->y = old.y + v1;
                } else {
                    *dst = make_float2(v0, v1);
                }
            }
        }
    }
}

// ---------------- tensor-core flash attention (plain tf32) ------------------
// Block: 64 q-rows x one head. 8 warps (4x2: q-strip x kv/d-half).
// smem: Q,K,V,SP each [64][68] + mrow/lrow/crow[64]  = 70400 B -> 3 CTAs/SM
#define AST 68
#define ATT_SMEM ((4 * 64 * AST + 3 * 64) * 4)

__global__ __launch_bounds__(256, 3)
void attn_tc(const float* __restrict__ qkv, float* __restrict__ attn_o) {
    extern __shared__ float sm[];
    float* Qs = sm;
    float* Ks = Qs + 64 * AST;
    float* Vs = Ks + 64 * AST;
    float* SP = Vs + 64 * AST;   // S scores, then tf32 P (in place)
    float* mrow = SP + 64 * AST;
    float* lrow = mrow + 64;
    float* crow = lrow + 64;
    const unsigned* Qu = (const unsigned*)Qs;
    const unsigned* Ku = (const unsigned*)Ks;
    const unsigned* Vu = (const unsigned*)Vs;
    const unsigned* Pu = (const unsigned*)SP;

    int qt = blockIdx.x, h = blockIdx.y, bb = blockIdx.z;
    int tid = threadIdx.x;
    int w = tid >> 5, lane = tid & 31;
    int gid = lane >> 2, tig = lane & 3;
    int qs = (w >> 1) * 16;        // q strip for this warp
    int hs = (w & 1) * 32;         // kv-half (S) / d-half (O)
    const float* base = qkv + (size_t)bb * NPTS * 1152;

    // load Q (64x64), rounded to tf32
#pragma unroll
    for (int i = 0; i < 16; i++) {
        int e = tid + i * 256;
        int r = e >> 6, d = e & 63;
        Qs[r * AST + d] = tf32r(base[(size_t)(qt * 64 + r) * 1152 + h * 64 + d]);
    }
    if (tid < 64) { mrow[tid] = -1e30f; lrow[tid] = 0.f; }

    float oc[4][4];
#pragma unroll
    for (int j = 0; j < 4; j++)
#pragma unroll
        for (int e = 0; e < 4; e++) oc[j][e] = 0.f;

    for (int jt = 0; jt < NPTS / 64; jt++) {
        __syncthreads();   // previous chunk's P@V done
#pragma unroll
        for (int i = 0; i < 16; i++) {
            int e = tid + i * 256;
            int r = e >> 6, d = e & 63;
            size_t rowo = (size_t)(jt * 64 + r) * 1152 + h * 64 + d;
            Ks[r * AST + d] = tf32r(base[rowo + 384]);
            Vs[r * AST + d] = tf32r(base[rowo + 768]);
        }
        __syncthreads();

        // --- S = Q @ K^T (warp: 16q x 32kv) ---
        float sc[4][4];
#pragma unroll
        for (int j = 0; j < 4; j++)
#pragma unroll
            for (int e = 0; e < 4; e++) sc[j][e] = 0.f;
#pragma unroll
        for (int d0 = 0; d0 < 64; d0 += 8) {
            unsigned ah[4];
            ah[0] = Qu[(qs + gid) * AST + d0 + tig];
            ah[1] = Qu[(qs + gid + 8) * AST + d0 + tig];
            ah[2] = Qu[(qs + gid) * AST + d0 + tig + 4];
            ah[3] = Qu[(qs + gid + 8) * AST + d0 + tig + 4];
#pragma unroll
            for (int j = 0; j < 4; j++) {
                int kv = hs + j * 8 + gid;
                unsigned bh0 = Ku[kv * AST + d0 + tig];
                unsigned bh1 = Ku[kv * AST + d0 + tig + 4];
                mma_tf32(sc[j], ah, bh0, bh1);
            }
        }
#pragma unroll
        for (int j = 0; j < 4; j++) {
            int cc = hs + j * 8 + tig * 2;
            SP[(qs + gid) * AST + cc]         = sc[j][0] * 0.125f;
            SP[(qs + gid) * AST + cc + 1]     = sc[j][1] * 0.125f;
            SP[(qs + gid + 8) * AST + cc]     = sc[j][2] * 0.125f;
            SP[(qs + gid + 8) * AST + cc + 1] = sc[j][3] * 0.125f;
        }
        __syncthreads();

        // --- online softmax: 4 threads per row ---
        {
            int row = tid >> 2, q4 = tid & 3;
            float sv[16];
            float mx = -1e30f;
#pragma unroll
            for (int i = 0; i < 16; i++) {
                sv[i] = SP[row * AST + q4 * 16 + i];
                mx = fmaxf(mx, sv[i]);
            }
            mx = fmaxf(mx, __shfl_xor_sync(0xffffffffu, mx, 1));
            mx = fmaxf(mx, __shfl_xor_sync(0xffffffffu, mx, 2));
            float mold = mrow[row];
            float mnew = fmaxf(mold, mx);
            float sum = 0.f;
#pragma unroll
            for (int i = 0; i < 16; i++) {
                float p = __expf(sv[i] - mnew);
                sum += p;
                SP[row * AST + q4 * 16 + i] = tf32r(p);
            }
            sum += __shfl_xor_sync(0xffffffffu, sum, 1);
            sum += __shfl_xor_sync(0xffffffffu, sum, 2);
            if (q4 == 0) {
                float corr = __expf(mold - mnew);
                crow[row] = corr;
                lrow[row] = lrow[row] * corr + sum;
                mrow[row] = mnew;
            }
        }
        __syncthreads();

        // --- rescale O, then O += P @ V (warp: 16q x 32d) ---
        {
            float c0 = crow[qs + gid];
            float c1 = crow[qs + gid + 8];
#pragma unroll
            for (int j = 0; j < 4; j++) {
                oc[j][0] *= c0; oc[j][1] *= c0;
                oc[j][2] *= c1; oc[j][3] *= c1;
            }
        }
#pragma unroll
        for (int kv0 = 0; kv0 < 64; kv0 += 8) {
            unsigned ah[4];
            ah[0] = Pu[(qs + gid) * AST + kv0 + tig];
            ah[1] = Pu[(qs + gid + 8) * AST + kv0 + tig];
            ah[2] = Pu[(qs + gid) * AST + kv0 + tig + 4];
            ah[3] = Pu[(qs + gid + 8) * AST + kv0 + tig + 4];
#pragma unroll
            for (int j = 0; j < 4; j++) {
                int dc = hs + j * 8 + gid;
                unsigned bh0 = Vu[(kv0 + tig) * AST + dc];
                unsigned bh1 = Vu[(kv0 + tig + 4) * AST + dc];
                mma_tf32(oc[j], ah, bh0, bh1);
            }
        }
    }
    __syncthreads();
    {
        float inv0 = 1.f / lrow[qs + gid];
        float inv1 = 1.f / lrow[qs + gid + 8];
#pragma unroll
        for (int j = 0; j < 4; j++) {
            int cc = h * 64 + hs + j * 8 + tig * 2;
            int r0 = bb * NPTS + qt * 64 + qs + gid;
            float2* d0 = (float2*)(attn_o + (size_t)r0 * DMODEL + cc);
            *d0 = make_float2(oc[j][0] * inv0, oc[j][1] * inv0);
            float2* d1 = (float2*)(attn_o + (size_t)(r0 + 8) * DMODEL + cc);
            *d1 = make_float2(oc[j][2] * inv1, oc[j][3] * inv1);
        }
    }
}

// ---------------- geom branch: gather + softmax(K=8) -----------------------
__global__ void geom_kernel(const float* __restrict__ gq, const float* __restrict__ gk,
                            const float* __restrict__ gv, const int* __restrict__ idx,
                            float* __restrict__ merged) {
    int m = blockIdx.x;
    int bb = m >> 11;
    __shared__ float dots[KNN];
    __shared__ int nb[KNN];
    int tid = threadIdx.x, w = tid >> 5, lane = tid & 31;
    if (tid < KNN) nb[tid] = idx[(size_t)m * KNN + tid];
    __syncthreads();
    const float* qrow = gq + (size_t)m * DMODEL;
    const float* krow = gk + ((size_t)bb * NPTS + nb[w]) * DMODEL;
    float s = 0.f;
    for (int d = lane; d < DMODEL; d += 32) s += qrow[d] * krow[d];
#pragma unroll
    for (int o = 16; o; o >>= 1) s += __shfl_xor_sync(0xffffffffu, s, o);
    if (lane == 0) dots[w] = s * 0.05103103630798287f;
    __syncthreads();
    float mx = dots[0];
#pragma unroll
    for (int k = 1; k < KNN; k++) mx = fmaxf(mx, dots[k]);
    float p[KNN], sum = 0.f;
#pragma unroll
    for (int k = 0; k < KNN; k++) { p[k] = expf(dots[k] - mx); sum += p[k]; }
    float inv = 1.f / sum;
    for (int d = tid; d < DMODEL; d += 256) {
        float a = 0.f;
#pragma unroll
        for (int k = 0; k < KNN; k++)
            a += p[k] * gv[((size_t)bb * NPTS + nb[k]) * DMODEL + d];
        merged[(size_t)m * 768 + 384 + d] = a * inv;
    }
}

// ---------------- output transpose -----------------------------------------
__global__ void out_transpose(const float* __restrict__ f, float* __restrict__ out) {
    __shared__ float tile[32][33];
    int bb = blockIdx.z;
    int n0 = blockIdx.x * 32, d0 = blockIdx.y * 32;
    int tx = threadIdx.x, ty = threadIdx.y;
#pragma unroll
    for (int i = 0; i < 32; i += 8)
        tile[ty + i][tx] = f[((size_t)bb * NPTS + n0 + ty + i) * DMODEL + d0 + tx];
    __syncthreads();
#pragma unroll
    for (int i = 0; i < 32; i += 8)
        out[((size_t)bb * DMODEL + d0 + ty + i) * NPTS + n0 + tx] = tile[tx][ty + i];
}

// ---------------- launch ----------------------------------------------------
extern "C" void kernel_launch(void* const* d_in, const int* in_sizes, int n_in,
                              void* d_out, int out_size) {
    const float* coords     = (const float*)d_in[0];
    const float* features   = (const float*)d_in[1];
    const float* ln1_g      = (const float*)d_in[2];
    const float* ln1_b      = (const float*)d_in[3];
    const float* w_qkv      = (const float*)d_in[4];
    const float* w_attn_out = (const float*)d_in[5];
    const float* b_attn_out = (const float*)d_in[6];
    const float* ga_wq      = (const float*)d_in[7];
    const float* ga_wk      = (const float*)d_in[8];
    const float* ga_wv      = (const float*)d_in[9];
    const float* merge_w    = (const float*)d_in[10];
    const float* merge_b    = (const float*)d_in[11];
    const float* ln2_g      = (const float*)d_in[12];
    const float* ln2_b      = (const float*)d_in[13];
    const float* ff_w1      = (const float*)d_in[14];
    const float* ff_b1      = (const float*)d_in[15];
    const float* ff_w2      = (const float*)d_in[16];
    const float* ff_b2      = (const float*)d_in[17];
    float* out = (float*)d_out;

    float *pf, *pnf, *pqkv, *pattn, *pgq, *pgk, *pgv, *pmerged, *ph, *pt;
    int* pidx;
    cudaGetSymbolAddress((void**)&pf, g_f);
    cudaGetSymbolAddress((void**)&pnf, g_nf);
    cudaGetSymbolAddress((void**)&pqkv, g_qkv);
    cudaGetSymbolAddress((void**)&pattn, g_attn);
    cudaGetSymbolAddress((void**)&pgq, g_gq);
    cudaGetSymbolAddress((void**)&pgk, g_gk);
    cudaGetSymbolAddress((void**)&pgv, g_gv);
    cudaGetSymbolAddress((void**)&pmerged, g_merged);
    cudaGetSymbolAddress((void**)&ph, g_h);
    cudaGetSymbolAddress((void**)&pt, g_t);
    cudaGetSymbolAddress((void**)&pidx, g_idx);

    cudaFuncSetAttribute(attn_tc, cudaFuncAttributeMaxDynamicSharedMemorySize, ATT_SMEM);
    cudaFuncSetAttribute(gemm_tc<0>, cudaFuncAttributeMaxDynamicSharedMemorySize, GEMM_SMEM);
    cudaFuncSetAttribute(gemm_tc<1>, cudaFuncAttributeMaxDynamicSharedMemorySize, GEMM_SMEM);
    cudaFuncSetAttribute(gemm_tc<2>, cudaFuncAttributeMaxDynamicSharedMemorySize, GEMM_SMEM);

    prep_ln1<<<MTOK, 128>>>(features, ln1_g, ln1_b, pf, pnf);
    knn_kernel<<<dim3(NPTS / 256, BATCH), 256>>>(coords, pidx);
    gemm_tc<0><<<dim3(1152 / 64, MTOK / 128), 256, GEMM_SMEM>>>(pnf, w_qkv, nullptr, pqkv, MTOK, 384, 1152, 1152);
    attn_tc<<<dim3(NPTS / 64, NHEAD, BATCH), 256, ATT_SMEM>>>(pqkv, pattn);
    gemm_tc<0><<<dim3(384 / 64, MTOK / 128), 256, GEMM_SMEM>>>(pattn, w_attn_out, b_attn_out, pmerged, MTOK, 384, 384, 768);
    gemm_tc<0><<<dim3(384 / 64, MTOK / 128), 256, GEMM_SMEM>>>(pnf, ga_wq, nullptr, pgq, MTOK, 384, 384, 384);
    gemm_tc<0><<<dim3(384 / 64, MTOK / 128), 256, GEMM_SMEM>>>(pnf, ga_wk, nullptr, pgk, MTOK, 384, 384, 384);
    gemm_tc<0><<<dim3(384 / 64, MTOK / 128), 256, GEMM_SMEM>>>(pnf, ga_wv, nullptr, pgv, MTOK, 384, 384, 384);
    geom_kernel<<<MTOK, 256>>>(pgq, pgk, pgv, pidx, pmerged);
    gemm_tc<2><<<dim3(384 / 64, MTOK / 128), 256, GEMM_SMEM>>>(pmerged, merge_w, merge_b, pf, MTOK, 768, 384, 384);
    ln2_k<<<MTOK, 128>>>(pf, ln2_g, ln2_b, ph);
    gemm_tc<1><<<dim3(768 / 64, MTOK / 128), 256, GEMM_SMEM>>>(ph, ff_w1, ff_b1, pt, MTOK, 384, 768, 768);
    gemm_tc<2><<<dim3(384 / 64, MTOK / 128), 256, GEMM_SMEM>>>(pt, ff_w2, ff_b2, pf, MTOK, 768, 384, 384);
    out_transpose<<<dim3(NPTS / 32, DMODEL / 32, BATCH), dim3(32, 8)>>>(pf, out);
}

// round 7
// speedup vs baseline: 2.1940x; 1.2777x over previous
#include <cuda_runtime.h>
#include <cuda_bf16.h>
#include <math.h>

#define BATCH 8
#define NPTS 2048
#define DMODEL 384
#define NHEAD 6
#define DHEAD 64
#define KNN 8
#define MTOK (BATCH * NPTS)   // 16384

// ---------------- scratch (device globals; no allocation allowed) ----------
__device__ float g_f[MTOK * DMODEL];
__device__ float g_nf[MTOK * DMODEL];
__device__ float g_qkv[MTOK * 3 * DMODEL];
__device__ float g_attn[MTOK * DMODEL];
__device__ float g_gq[MTOK * DMODEL];
__device__ float g_gk[MTOK * DMODEL];
__device__ float g_gv[MTOK * DMODEL];
__device__ float g_merged[MTOK * 2 * DMODEL];
__device__ float g_h[MTOK * DMODEL];
__device__ float g_t[MTOK * 2 * DMODEL];
__device__ int   g_idx[MTOK * KNN];

// ---------------- helpers ---------------------------------------------------
__device__ __forceinline__ float tf32r(float x) {
    unsigned r; asm("cvt.rna.tf32.f32 %0, %1;" : "=r"(r) : "f"(x));
    return __uint_as_float(r);
}

__device__ __forceinline__ void mma_tf32(float* c, const unsigned* a, unsigned b0, unsigned b1) {
    asm volatile("mma.sync.aligned.m16n8k8.row.col.f32.tf32.tf32.f32 "
        "{%0,%1,%2,%3}, {%4,%5,%6,%7}, {%8,%9}, {%0,%1,%2,%3};"
        : "+f"(c[0]), "+f"(c[1]), "+f"(c[2]), "+f"(c[3])
        : "r"(a[0]), "r"(a[1]), "r"(a[2]), "r"(a[3]), "r"(b0), "r"(b1));
}

__device__ __forceinline__ void mma_tf32f(float* c, const float4& a, float b0f, float b1f) {
    asm volatile("mma.sync.aligned.m16n8k8.row.col.f32.tf32.tf32.f32 "
        "{%0,%1,%2,%3}, {%4,%5,%6,%7}, {%8,%9}, {%0,%1,%2,%3};"
        : "+f"(c[0]), "+f"(c[1]), "+f"(c[2]), "+f"(c[3])
        : "r"(__float_as_uint(a.x)), "r"(__float_as_uint(a.y)),
          "r"(__float_as_uint(a.z)), "r"(__float_as_uint(a.w)),
          "r"(__float_as_uint(b0f)), "r"(__float_as_uint(b1f)));
}

__device__ __forceinline__ void cp16(void* dst, const void* src) {
    unsigned d = (unsigned)__cvta_generic_to_shared(dst);
    asm volatile("cp.async.ca.shared.global [%0], [%1], 16;\n" :: "r"(d), "l"(src));
}
#define CP_COMMIT() asm volatile("cp.async.commit_group;\n" ::: "memory")
#define CP_WAIT(N)  asm volatile("cp.async.wait_group %0;\n" :: "n"(N) : "memory")

// ---------------- LN1 + transpose ------------------------------------------
__global__ void prep_ln1(const float* __restrict__ feat,
                         const float* __restrict__ g, const float* __restrict__ b,
                         float* __restrict__ f, float* __restrict__ nf) {
    int m = blockIdx.x;
    int bb = m >> 11, n = m & 2047;
    const float* src = feat + (size_t)bb * DMODEL * NPTS + n;
    float v[3];
    float s = 0.f, s2 = 0.f;
#pragma unroll
    for (int i = 0; i < 3; i++) {
        int d = threadIdx.x + i * 128;
        float x = src[(size_t)d * NPTS];
        v[i] = x; s += x; s2 += x * x;
    }
#pragma unroll
    for (int o = 16; o; o >>= 1) {
        s  += __shfl_xor_sync(0xffffffffu, s, o);
        s2 += __shfl_xor_sync(0xffffffffu, s2, o);
    }
    __shared__ float sh[8];
    int w = threadIdx.x >> 5;
    if ((threadIdx.x & 31) == 0) { sh[w] = s; sh[4 + w] = s2; }
    __syncthreads();
    s  = sh[0] + sh[1] + sh[2] + sh[3];
    s2 = sh[4] + sh[5] + sh[6] + sh[7];
    float mean = s * (1.f / DMODEL);
    float var  = s2 * (1.f / DMODEL) - mean * mean;
    float rstd = rsqrtf(var + 1e-5f);
#pragma unroll
    for (int i = 0; i < 3; i++) {
        int d = threadIdx.x + i * 128;
        float x = v[i];
        f[(size_t)m * DMODEL + d]  = x;
        nf[(size_t)m * DMODEL + d] = (x - mean) * rstd * g[d] + b[d];
    }
}

// ---------------- LN2 -------------------------------------------------------
__global__ void ln2_k(const float* __restrict__ f,
                      const float* __restrict__ g, const float* __restrict__ b,
                      float* __restrict__ h) {
    int m = blockIdx.x;
    const float* row = f + (size_t)m * DMODEL;
    float v[3];
    float s = 0.f, s2 = 0.f;
#pragma unroll
    for (int i = 0; i < 3; i++) {
        int d = threadIdx.x + i * 128;
        float x = row[d];
        v[i] = x; s += x; s2 += x * x;
    }
#pragma unroll
    for (int o = 16; o; o >>= 1) {
        s  += __shfl_xor_sync(0xffffffffu, s, o);
        s2 += __shfl_xor_sync(0xffffffffu, s2, o);
    }
    __shared__ float sh[8];
    int w = threadIdx.x >> 5;
    if ((threadIdx.x & 31) == 0) { sh[w] = s; sh[4 + w] = s2; }
    __syncthreads();
    s  = sh[0] + sh[1] + sh[2] + sh[3];
    s2 = sh[4] + sh[5] + sh[6] + sh[7];
    float mean = s * (1.f / DMODEL);
    float var  = s2 * (1.f / DMODEL) - mean * mean;
    float rstd = rsqrtf(var + 1e-5f);
#pragma unroll
    for (int i = 0; i < 3; i++) {
        int d = threadIdx.x + i * 128;
        h[(size_t)m * DMODEL + d] = (v[i] - mean) * rstd * g[d] + b[d];
    }
}

// ---------------- brute force KNN top-8 ------------------------------------
__global__ void knn_kernel(const float* __restrict__ coords, int* __restrict__ idxout) {
    int bb = blockIdx.y;
    __shared__ float cx[NPTS], cy[NPTS], cz[NPTS], sq[NPTS];
    const float* cb = coords + (size_t)bb * 3 * NPTS;
    for (int i = threadIdx.x; i < NPTS; i += 256) {
        float x = cb[i], y = cb[NPTS + i], z = cb[2 * NPTS + i];
        cx[i] = x; cy[i] = y; cz[i] = z;
        sq[i] = x * x + y * y + z * z;
    }
    __syncthreads();
    int q = blockIdx.x * 256 + threadIdx.x;
    float qx = cx[q], qy = cy[q], qz = cz[q], qsq = sq[q];
    float bd[KNN]; int bi[KNN];
#pragma unroll
    for (int k = 0; k < KNN; k++) { bd[k] = 3.0e38f; bi[k] = 0; }
    for (int mi = 0; mi < NPTS; mi++) {
        float d = qsq + sq[mi] - 2.f * (qx * cx[mi] + qy * cy[mi] + qz * cz[mi]);
        if (d < bd[KNN - 1]) {
            int p = KNN - 1;
            while (p > 0 && bd[p - 1] > d) { bd[p] = bd[p - 1]; bi[p] = bi[p - 1]; p--; }
            bd[p] = d; bi[p] = mi;
        }
    }
#pragma unroll
    for (int k = 0; k < KNN; k++)
        idxout[((size_t)bb * NPTS + q) * KNN + k] = bi[k];
}

// ---------------- GEMM with fragment-packed smem ----------------------------
// Block 128x64, 8 warps (4 wm x 2 wn), warp tile 32x32, BK=32.
// AF: [4 steps][8 row-groups][32 lanes] float4 (pre-packed a0..a3)  = 16KB
// BF: [4 steps][8 col-groups][32 lanes] float2 (pre-packed b0,b1)   =  8KB
#define GEMM_SMEM ((4096 + 2048) * 4)

template <int EPI>
__global__ __launch_bounds__(256)
void gemm_tc(const float* __restrict__ A, const float* __restrict__ W,
             const float* __restrict__ bias, float* __restrict__ C,
             int M, int K, int N, int ldc) {
    extern __shared__ float sm[];
    float4* AF = (float4*)sm;
    float2* BF = (float2*)(sm + 4096);

    int tid = threadIdx.x;
    int w = tid >> 5, lane = tid & 31;
    int gid = lane >> 2, tig = lane & 3;
    int wm = w >> 1, wn = w & 1;
    int rowBase = blockIdx.y * 128, colBase = blockIdx.x * 64;
    int gT = w;  // staging task group 0..7

    const float* aSrc = A + (size_t)(rowBase + gT * 16 + gid) * K;
    const float* wSrc = W + colBase + gT * 8 + gid;

    float4 av[4]; float2 bv[4];
#pragma unroll
    for (int s = 0; s < 4; s++) {
        av[s].x = tf32r(aSrc[s * 8 + tig]);
        av[s].y = tf32r(aSrc[(size_t)8 * K + s * 8 + tig]);
        av[s].z = tf32r(aSrc[s * 8 + tig + 4]);
        av[s].w = tf32r(aSrc[(size_t)8 * K + s * 8 + tig + 4]);
        bv[s].x = tf32r(wSrc[(size_t)(s * 8 + tig) * N]);
        bv[s].y = tf32r(wSrc[(size_t)(s * 8 + tig + 4) * N]);
    }

    float c[2][4][4];
#pragma unroll
    for (int mt = 0; mt < 2; mt++)
#pragma unroll
        for (int j = 0; j < 4; j++)
#pragma unroll
            for (int e = 0; e < 4; e++) c[mt][j][e] = 0.f;

    for (int k0 = 0; k0 < K; k0 += 32) {
        __syncthreads();
#pragma unroll
        for (int s = 0; s < 4; s++) {
            AF[(s * 8 + gT) * 32 + lane] = av[s];
            BF[(s * 8 + gT) * 32 + lane] = bv[s];
        }
        __syncthreads();
        if (k0 + 32 < K) {
            const float* aN = aSrc + k0 + 32;
            const float* wN = wSrc + (size_t)(k0 + 32) * N;
#pragma unroll
            for (int s = 0; s < 4; s++) {
                av[s].x = tf32r(aN[s * 8 + tig]);
                av[s].y = tf32r(aN[(size_t)8 * K + s * 8 + tig]);
                av[s].z = tf32r(aN[s * 8 + tig + 4]);
                av[s].w = tf32r(aN[(size_t)8 * K + s * 8 + tig + 4]);
                bv[s].x = tf32r(wN[(size_t)(s * 8 + tig) * N]);
                bv[s].y = tf32r(wN[(size_t)(s * 8 + tig + 4) * N]);
            }
        }
#pragma unroll
        for (int s = 0; s < 4; s++) {
            float4 a0 = AF[(s * 8 + wm * 2 + 0) * 32 + lane];
            float4 a1 = AF[(s * 8 + wm * 2 + 1) * 32 + lane];
#pragma unroll
            for (int j = 0; j < 4; j++) {
                float2 b = BF[(s * 8 + wn * 4 + j) * 32 + lane];
                mma_tf32f(c[0][j], a0, b.x, b.y);
                mma_tf32f(c[1][j], a1, b.x, b.y);
            }
        }
    }
#pragma unroll
    for (int mt = 0; mt < 2; mt++) {
#pragma unroll
        for (int j = 0; j < 4; j++) {
            int r = rowBase + wm * 32 + mt * 16 + gid;
            int cc = colBase + wn * 32 + j * 8 + tig * 2;
            float b0 = bias ? bias[cc] : 0.f;
            float b1 = bias ? bias[cc + 1] : 0.f;
#pragma unroll
            for (int half = 0; half < 2; half++) {
                int rr = r + half * 8;
                float v0 = c[mt][j][half * 2 + 0] + b0;
                float v1 = c[mt][j][half * 2 + 1] + b1;
                if (EPI == 1) {
                    float x3 = v0 * v0 * v0;
                    v0 = 0.5f * v0 * (1.f + tanhf(0.7978845608028654f * (v0 + 0.044715f * x3)));
                    x3 = v1 * v1 * v1;
                    v1 = 0.5f * v1 * (1.f + tanhf(0.7978845608028654f * (v1 + 0.044715f * x3)));
                }
                float2* dst = (float2*)(C + (size_t)rr * ldc + cc);
                if (EPI == 2) {
                    float2 old = *dst;
                    dst->x = old.x + v0; dst->y = old.y + v1;
                } else {
                    *dst = make_float2(v0, v1);
                }
            }
        }
    }
}

// ---------------- flash attention: register softmax + cp.async --------------
// CTA: 128 q-rows x one (b,h). 8 warps; warp = 16q x full 64-kv chunk.
// smem: Q[128][68] + double-buffered {K[64][68], V[64][68]}  = 104448 B
#define AQ 68
#define ATT_SMEM ((128 * AQ + 4 * 64 * AQ) * 4)

__global__ __launch_bounds__(256, 2)
void attn_tc(const float* __restrict__ qkv, float* __restrict__ attn_o) {
    extern __shared__ float sm[];
    float* Qs = sm;
    float* KV = sm + 128 * AQ;   // buf stride 2*4352; K then V

    int qt = blockIdx.x, h = blockIdx.y, bb = blockIdx.z;
    int tid = threadIdx.x;
    int w = tid >> 5, lane = tid & 31;
    int gid = lane >> 2, tig = lane & 3;
    int qs = w * 16;
    const float* base = qkv + (size_t)bb * NPTS * 1152;

    // --- issue Q loads (group 0) ---
#pragma unroll
    for (int i = 0; i < 8; i++) {
        int t = tid + i * 256;
        int r = t >> 4, c4 = t & 15;
        cp16(Qs + r * AQ + c4 * 4,
             base + (size_t)(qt * 128 + r) * 1152 + h * 64 + c4 * 4);
    }
    CP_COMMIT();
    // --- issue chunk 0 (group 1) ---
#pragma unroll
    for (int i = 0; i < 8; i++) {
        int t = tid + i * 256;
        int isV = t >> 10;
        int r = (t >> 4) & 63, c4 = t & 15;
        cp16(KV + isV * 4352 + r * AQ + c4 * 4,
             base + (size_t)r * 1152 + (isV ? 768 : 384) + h * 64 + c4 * 4);
    }
    CP_COMMIT();

    CP_WAIT(1);          // Q arrived
    __syncthreads();

    // --- preload Q fragments (with 1/8 softmax scale folded in) ---
    unsigned qf[8][4];
#pragma unroll
    for (int s = 0; s < 8; s++) {
        qf[s][0] = __float_as_uint(Qs[(qs + gid) * AQ + s * 8 + tig] * 0.125f);
        qf[s][1] = __float_as_uint(Qs[(qs + gid + 8) * AQ + s * 8 + tig] * 0.125f);
        qf[s][2] = __float_as_uint(Qs[(qs + gid) * AQ + s * 8 + tig + 4] * 0.125f);
        qf[s][3] = __float_as_uint(Qs[(qs + gid + 8) * AQ + s * 8 + tig + 4] * 0.125f);
    }

    float oc[8][4];
#pragma unroll
    for (int j = 0; j < 8; j++)
#pragma unroll
        for (int e = 0; e < 4; e++) oc[j][e] = 0.f;
    float m0 = -1e30f, m1 = -1e30f, l0 = 0.f, l1 = 0.f;

    int srcA = (lane & 28) | (tig >> 1);
    int srcB = srcA + 2;
    int par = tig & 1;

    for (int jt = 0; jt < NPTS / 64; jt++) {
        int buf = jt & 1;
        CP_WAIT(0);              // chunk jt arrived (this thread's copies)
        __syncthreads();         // all threads' copies visible; prev compute done
        if (jt + 1 < NPTS / 64) {
            int nb = buf ^ 1;
#pragma unroll
            for (int i = 0; i < 8; i++) {
                int t = tid + i * 256;
                int isV = t >> 10;
                int r = (t >> 4) & 63, c4 = t & 15;
                cp16(KV + nb * 8704 + isV * 4352 + r * AQ + c4 * 4,
                     base + (size_t)((jt + 1) * 64 + r) * 1152 + (isV ? 768 : 384) + h * 64 + c4 * 4);
            }
            CP_COMMIT();
        }
        const unsigned* Ku = (const unsigned*)(KV + buf * 8704);
        const unsigned* Vu = Ku + 4352;

        // --- S = (Q/8) @ K^T : 16q x 64kv in registers ---
        float ps[8][4];
#pragma unroll
        for (int j = 0; j < 8; j++)
#pragma unroll
            for (int e = 0; e < 4; e++) ps[j][e] = 0.f;
#pragma unroll
        for (int s = 0; s < 8; s++) {
#pragma unroll
            for (int j = 0; j < 8; j++) {
                unsigned b0 = Ku[(j * 8 + gid) * AQ + s * 8 + tig];
                unsigned b1 = Ku[(j * 8 + gid) * AQ + s * 8 + tig + 4];
                mma_tf32(ps[j], qf[s], b0, b1);
            }
        }

        // --- online softmax, fully in registers (rows gid / gid+8) ---
        float mx0 = -1e30f, mx1 = -1e30f;
#pragma unroll
        for (int j = 0; j < 8; j++) {
            mx0 = fmaxf(mx0, fmaxf(ps[j][0], ps[j][1]));
            mx1 = fmaxf(mx1, fmaxf(ps[j][2], ps[j][3]));
        }
        mx0 = fmaxf(mx0, __shfl_xor_sync(0xffffffffu, mx0, 1));
        mx0 = fmaxf(mx0, __shfl_xor_sync(0xffffffffu, mx0, 2));
        mx1 = fmaxf(mx1, __shfl_xor_sync(0xffffffffu, mx1, 1));
        mx1 = fmaxf(mx1, __shfl_xor_sync(0xffffffffu, mx1, 2));
        float mn0 = fmaxf(m0, mx0), mn1 = fmaxf(m1, mx1);
        float cr0 = __expf(m0 - mn0), cr1 = __expf(m1 - mn1);
        float s0 = 0.f, s1 = 0.f;
#pragma unroll
        for (int j = 0; j < 8; j++) {
            ps[j][0] = __expf(ps[j][0] - mn0); s0 += ps[j][0];
            ps[j][1] = __expf(ps[j][1] - mn0); s0 += ps[j][1];
            ps[j][2] = __expf(ps[j][2] - mn1); s1 += ps[j][2];
            ps[j][3] = __expf(ps[j][3] - mn1); s1 += ps[j][3];
        }
        s0 += __shfl_xor_sync(0xffffffffu, s0, 1);
        s0 += __shfl_xor_sync(0xffffffffu, s0, 2);
        s1 += __shfl_xor_sync(0xffffffffu, s1, 1);
        s1 += __shfl_xor_sync(0xffffffffu, s1, 2);
        l0 = l0 * cr0 + s0; l1 = l1 * cr1 + s1;
        m0 = mn0; m1 = mn1;
#pragma unroll
        for (int j = 0; j < 8; j++) {
            oc[j][0] *= cr0; oc[j][1] *= cr0;
            oc[j][2] *= cr1; oc[j][3] *= cr1;
        }

        // --- O += P @ V ; P shuffled from accumulator layout to A-frag ---
#pragma unroll
        for (int t = 0; t < 8; t++) {
            float sA0 = __shfl_sync(0xffffffffu, ps[t][0], srcA);
            float sA1 = __shfl_sync(0xffffffffu, ps[t][1], srcA);
            float sA2 = __shfl_sync(0xffffffffu, ps[t][2], srcA);
            float sA3 = __shfl_sync(0xffffffffu, ps[t][3], srcA);
            float sB0 = __shfl_sync(0xffffffffu, ps[t][0], srcB);
            float sB1 = __shfl_sync(0xffffffffu, ps[t][1], srcB);
            float sB2 = __shfl_sync(0xffffffffu, ps[t][2], srcB);
            float sB3 = __shfl_sync(0xffffffffu, ps[t][3], srcB);
            unsigned af[4];
            af[0] = __float_as_uint(par ? sA1 : sA0);
            af[1] = __float_as_uint(par ? sA3 : sA2);
            af[2] = __float_as_uint(par ? sB1 : sB0);
            af[3] = __float_as_uint(par ? sB3 : sB2);
#pragma unroll
            for (int j = 0; j < 8; j++) {
                unsigned b0 = Vu[(t * 8 + tig) * AQ + j * 8 + gid];
                unsigned b1 = Vu[(t * 8 + tig + 4) * AQ + j * 8 + gid];
                mma_tf32(oc[j], af, b0, b1);
            }
        }
    }

    // --- normalize & store ---
    float inv0 = 1.f / l0, inv1 = 1.f / l1;
    int r0 = bb * NPTS + qt * 128 + qs + gid;
#pragma unroll
    for (int j = 0; j < 8; j++) {
        int cc = h * 64 + j * 8 + tig * 2;
        float2* d0 = (float2*)(attn_o + (size_t)r0 * DMODEL + cc);
        *d0 = make_float2(oc[j][0] * inv0, oc[j][1] * inv0);
        float2* d1 = (float2*)(attn_o + (size_t)(r0 + 8) * DMODEL + cc);
        *d1 = make_float2(oc[j][2] * inv1, oc[j][3] * inv1);
    }
}

// ---------------- geom branch: gather + softmax(K=8) -----------------------
__global__ void geom_kernel(const float* __restrict__ gq, const float* __restrict__ gk,
                            const float* __restrict__ gv, const int* __restrict__ idx,
                            float* __restrict__ merged) {
    int m = blockIdx.x;
    int bb = m >> 11;
    __shared__ float dots[KNN];
    __shared__ int nb[KNN];
    int tid = threadIdx.x, w = tid >> 5, lane = tid & 31;
    if (tid < KNN) nb[tid] = idx[(size_t)m * KNN + tid];
    __syncthreads();
    const float* qrow = gq + (size_t)m * DMODEL;
    const float* krow = gk + ((size_t)bb * NPTS + nb[w]) * DMODEL;
    float s = 0.f;
    for (int d = lane; d < DMODEL; d += 32) s += qrow[d] * krow[d];
#pragma unroll
    for (int o = 16; o; o >>= 1) s += __shfl_xor_sync(0xffffffffu, s, o);
    if (lane == 0) dots[w] = s * 0.05103103630798287f;
    __syncthreads();
    float mx = dots[0];
#pragma unroll
    for (int k = 1; k < KNN; k++) mx = fmaxf(mx, dots[k]);
    float p[KNN], sum = 0.f;
#pragma unroll
    for (int k = 0; k < KNN; k++) { p[k] = expf(dots[k] - mx); sum += p[k]; }
    float inv = 1.f / sum;
    for (int d = tid; d < DMODEL; d += 256) {
        float a = 0.f;
#pragma unroll
        for (int k = 0; k < KNN; k++)
            a += p[k] * gv[((size_t)bb * NPTS + nb[k]) * DMODEL + d];
        merged[(size_t)m * 768 + 384 + d] = a * inv;
    }
}

// ---------------- output transpose -----------------------------------------
__global__ void out_transpose(const float* __restrict__ f, float* __restrict__ out) {
    __shared__ float tile[32][33];
    int bb = blockIdx.z;
    int n0 = blockIdx.x * 32, d0 = blockIdx.y * 32;
    int tx = threadIdx.x, ty = threadIdx.y;
#pragma unroll
    for (int i = 0; i < 32; i += 8)
        tile[ty + i][tx] = f[((size_t)bb * NPTS + n0 + ty + i) * DMODEL + d0 + tx];
    __syncthreads();
#pragma unroll
    for (int i = 0; i < 32; i += 8)
        out[((size_t)bb * DMODEL + d0 + ty + i) * NPTS + n0 + tx] = tile[tx][ty + i];
}

// ---------------- launch ----------------------------------------------------
extern "C" void kernel_launch(void* const* d_in, const int* in_sizes, int n_in,
                              void* d_out, int out_size) {
    const float* coords     = (const float*)d_in[0];
    const float* features   = (const float*)d_in[1];
    const float* ln1_g      = (const float*)d_in[2];
    const float* ln1_b      = (const float*)d_in[3];
    const float* w_qkv      = (const float*)d_in[4];
    const float* w_attn_out = (const float*)d_in[5];
    const float* b_attn_out = (const float*)d_in[6];
    const float* ga_wq      = (const float*)d_in[7];
    const float* ga_wk      = (const float*)d_in[8];
    const float* ga_wv      = (const float*)d_in[9];
    const float* merge_w    = (const float*)d_in[10];
    const float* merge_b    = (const float*)d_in[11];
    const float* ln2_g      = (const float*)d_in[12];
    const float* ln2_b      = (const float*)d_in[13];
    const float* ff_w1      = (const float*)d_in[14];
    const float* ff_b1      = (const float*)d_in[15];
    const float* ff_w2      = (const float*)d_in[16];
    const float* ff_b2      = (const float*)d_in[17];
    float* out = (float*)d_out;

    float *pf, *pnf, *pqkv, *pattn, *pgq, *pgk, *pgv, *pmerged, *ph, *pt;
    int* pidx;
    cudaGetSymbolAddress((void**)&pf, g_f);
    cudaGetSymbolAddress((void**)&pnf, g_nf);
    cudaGetSymbolAddress((void**)&pqkv, g_qkv);
    cudaGetSymbolAddress((void**)&pattn, g_attn);
    cudaGetSymbolAddress((void**)&pgq, g_gq);
    cudaGetSymbolAddress((void**)&pgk, g_gk);
    cudaGetSymbolAddress((void**)&pgv, g_gv);
    cudaGetSymbolAddress((void**)&pmerged, g_merged);
    cudaGetSymbolAddress((void**)&ph, g_h);
    cudaGetSymbolAddress((void**)&pt, g_t);
    cudaGetSymbolAddress((void**)&pidx, g_idx);

    cudaFuncSetAttribute(attn_tc, cudaFuncAttributeMaxDynamicSharedMemorySize, ATT_SMEM);

    prep_ln1<<<MTOK, 128>>>(features, ln1_g, ln1_b, pf, pnf);
    knn_kernel<<<dim3(NPTS / 256, BATCH), 256>>>(coords, pidx);
    gemm_tc<0><<<dim3(1152 / 64, MTOK / 128), 256, GEMM_SMEM>>>(pnf, w_qkv, nullptr, pqkv, MTOK, 384, 1152, 1152);
    attn_tc<<<dim3(NPTS / 128, NHEAD, BATCH), 256, ATT_SMEM>>>(pqkv, pattn);
    gemm_tc<0><<<dim3(384 / 64, MTOK / 128), 256, GEMM_SMEM>>>(pattn, w_attn_out, b_attn_out, pmerged, MTOK, 384, 384, 768);
    gemm_tc<0><<<dim3(384 / 64, MTOK / 128), 256, GEMM_SMEM>>>(pnf, ga_wq, nullptr, pgq, MTOK, 384, 384, 384);
    gemm_tc<0><<<dim3(384 / 64, MTOK / 128), 256, GEMM_SMEM>>>(pnf, ga_wk, nullptr, pgk, MTOK, 384, 384, 384);
    gemm_tc<0><<<dim3(384 / 64, MTOK / 128), 256, GEMM_SMEM>>>(pnf, ga_wv, nullptr, pgv, MTOK, 384, 384, 384);
    geom_kernel<<<MTOK, 256>>>(pgq, pgk, pgv, pidx, pmerged);
    gemm_tc<2><<<dim3(384 / 64, MTOK / 128), 256, GEMM_SMEM>>>(pmerged, merge_w, merge_b, pf, MTOK, 768, 384, 384);
    ln2_k<<<MTOK, 128>>>(pf, ln2_g, ln2_b, ph);
    gemm_tc<1><<<dim3(768 / 64, MTOK / 128), 256, GEMM_SMEM>>>(ph, ff_w1, ff_b1, pt, MTOK, 384, 768, 768);
    gemm_tc<2><<<dim3(384 / 64, MTOK / 128), 256, GEMM_SMEM>>>(pt, ff_w2, ff_b2, pf, MTOK, 768, 384, 384);
    out_transpose<<<dim3(NPTS / 32, DMODEL / 32, BATCH), dim3(32, 8)>>>(pf, out);
}

// round 9
// speedup vs baseline: 3.0384x; 1.3848x over previous
#include <cuda_runtime.h>
#include <cuda_bf16.h>
#include <math.h>

#define BATCH 8
#define NPTS 2048
#define DMODEL 384
#define NHEAD 6
#define DHEAD 64
#define KNN 8
#define MTOK (BATCH * NPTS)   // 16384

// ---------------- scratch (device globals; no allocation allowed) ----------
__device__ float g_f[MTOK * DMODEL];
__device__ float g_nf[MTOK * DMODEL];
__device__ float g_qkv[MTOK * 3 * DMODEL];
__device__ float g_attn[MTOK * DMODEL];
__device__ float g_gq[MTOK * DMODEL];
__device__ float g_gk[MTOK * DMODEL];
__device__ float g_gv[MTOK * DMODEL];
__device__ float g_merged[MTOK * 2 * DMODEL];
__device__ float g_h[MTOK * DMODEL];
__device__ float g_t[MTOK * 2 * DMODEL];
__device__ int   g_idx[MTOK * KNN];

// ---------------- helpers ---------------------------------------------------
__device__ __forceinline__ float tf32r(float x) {
    unsigned r; asm("cvt.rna.tf32.f32 %0, %1;" : "=r"(r) : "f"(x));
    return __uint_as_float(r);
}

__device__ __forceinline__ void mma_tf32(float* c, const unsigned* a, unsigned b0, unsigned b1) {
    asm volatile("mma.sync.aligned.m16n8k8.row.col.f32.tf32.tf32.f32 "
        "{%0,%1,%2,%3}, {%4,%5,%6,%7}, {%8,%9}, {%0,%1,%2,%3};"
        : "+f"(c[0]), "+f"(c[1]), "+f"(c[2]), "+f"(c[3])
        : "r"(a[0]), "r"(a[1]), "r"(a[2]), "r"(a[3]), "r"(b0), "r"(b1));
}

__device__ __forceinline__ void cp16(void* dst, const void* src) {
    unsigned d = (unsigned)__cvta_generic_to_shared(dst);
    asm volatile("cp.async.ca.shared.global [%0], [%1], 16;\n" :: "r"(d), "l"(src));
}
#define CP_COMMIT() asm volatile("cp.async.commit_group;\n" ::: "memory")
#define CP_WAIT(N)  asm volatile("cp.async.wait_group %0;\n" :: "n"(N) : "memory")

// ---------------- LN1 + transpose ------------------------------------------
__global__ void prep_ln1(const float* __restrict__ feat,
                         const float* __restrict__ g, const float* __restrict__ b,
                         float* __restrict__ f, float* __restrict__ nf) {
    int m = blockIdx.x;
    int bb = m >> 11, n = m & 2047;
    const float* src = feat + (size_t)bb * DMODEL * NPTS + n;
    float v[3];
    float s = 0.f, s2 = 0.f;
#pragma unroll
    for (int i = 0; i < 3; i++) {
        int d = threadIdx.x + i * 128;
        float x = src[(size_t)d * NPTS];
        v[i] = x; s += x; s2 += x * x;
    }
#pragma unroll
    for (int o = 16; o; o >>= 1) {
        s  += __shfl_xor_sync(0xffffffffu, s, o);
        s2 += __shfl_xor_sync(0xffffffffu, s2, o);
    }
    __shared__ float sh[8];
    int w = threadIdx.x >> 5;
    if ((threadIdx.x & 31) == 0) { sh[w] = s; sh[4 + w] = s2; }
    __syncthreads();
    s  = sh[0] + sh[1] + sh[2] + sh[3];
    s2 = sh[4] + sh[5] + sh[6] + sh[7];
    float mean = s * (1.f / DMODEL);
    float var  = s2 * (1.f / DMODEL) - mean * mean;
    float rstd = rsqrtf(var + 1e-5f);
#pragma unroll
    for (int i = 0; i < 3; i++) {
        int d = threadIdx.x + i * 128;
        float x = v[i];
        f[(size_t)m * DMODEL + d]  = x;
        nf[(size_t)m * DMODEL + d] = (x - mean) * rstd * g[d] + b[d];
    }
}

// ---------------- LN2 -------------------------------------------------------
__global__ void ln2_k(const float* __restrict__ f,
                      const float* __restrict__ g, const float* __restrict__ b,
                      float* __restrict__ h) {
    int m = blockIdx.x;
    const float* row = f + (size_t)m * DMODEL;
    float v[3];
    float s = 0.f, s2 = 0.f;
#pragma unroll
    for (int i = 0; i < 3; i++) {
        int d = threadIdx.x + i * 128;
        float x = row[d];
        v[i] = x; s += x; s2 += x * x;
    }
#pragma unroll
    for (int o = 16; o; o >>= 1) {
        s  += __shfl_xor_sync(0xffffffffu, s, o);
        s2 += __shfl_xor_sync(0xffffffffu, s2, o);
    }
    __shared__ float sh[8];
    int w = threadIdx.x >> 5;
    if ((threadIdx.x & 31) == 0) { sh[w] = s; sh[4 + w] = s2; }
    __syncthreads();
    s  = sh[0] + sh[1] + sh[2] + sh[3];
    s2 = sh[4] + sh[5] + sh[6] + sh[7];
    float mean = s * (1.f / DMODEL);
    float var  = s2 * (1.f / DMODEL) - mean * mean;
    float rstd = rsqrtf(var + 1e-5f);
#pragma unroll
    for (int i = 0; i < 3; i++) {
        int d = threadIdx.x + i * 128;
        h[(size_t)m * DMODEL + d] = (v[i] - mean) * rstd * g[d] + b[d];
    }
}

// ---------------- brute force KNN top-8 ------------------------------------
__global__ void knn_kernel(const float* __restrict__ coords, int* __restrict__ idxout) {
    int bb = blockIdx.y;
    __shared__ float cx[NPTS], cy[NPTS], cz[NPTS], sq[NPTS];
    const float* cb = coords + (size_t)bb * 3 * NPTS;
    for (int i = threadIdx.x; i < NPTS; i += 256) {
        float x = cb[i], y = cb[NPTS + i], z = cb[2 * NPTS + i];
        cx[i] = x; cy[i] = y; cz[i] = z;
        sq[i] = x * x + y * y + z * z;
    }
    __syncthreads();
    int q = blockIdx.x * 256 + threadIdx.x;
    float qx = cx[q], qy = cy[q], qz = cz[q], qsq = sq[q];
    float bd[KNN]; int bi[KNN];
#pragma unroll
    for (int k = 0; k < KNN; k++) { bd[k] = 3.0e38f; bi[k] = 0; }
    for (int mi = 0; mi < NPTS; mi++) {
        float d = qsq + sq[mi] - 2.f * (qx * cx[mi] + qy * cy[mi] + qz * cz[mi]);
        if (d < bd[KNN - 1]) {
            int p = KNN - 1;
            while (p > 0 && bd[p - 1] > d) { bd[p] = bd[p - 1]; bi[p] = bi[p - 1]; p--; }
            bd[p] = d; bi[p] = mi;
        }
    }
#pragma unroll
    for (int k = 0; k < KNN; k++)
        idxout[((size_t)bb * NPTS + q) * KNN + k] = bi[k];
}

// ---------------- GEMM v3: cp.async double-buffered, warp 64x32 -------------
// Block 128x128, 8 warps (2 wm x 4 wn), warp tile 64x32, K-block 32.
// smem: A[2][128][36] + B[2][32][132]  = 70656 B -> 2 CTAs/SM
// A stored [row][k] (stride 36), B stored [k][col] (stride 132); raw f32
// (HMMA truncates to tf32 in hardware).
#define GA_ST 36
#define GB_ST 132
#define GA_BUF (128 * GA_ST)
#define GB_BUF (32 * GB_ST)
#define GEMM_SMEM ((2 * GA_BUF + 2 * GB_BUF) * 4)

template <int EPI>
__global__ __launch_bounds__(256, 2)
void gemm_tc(const float* __restrict__ A, const float* __restrict__ W,
             const float* __restrict__ bias, float* __restrict__ C,
             int M, int K, int N, int ldc) {
    extern __shared__ float sm[];
    float* Ab = sm;                  // 2 buffers
    float* Bb = sm + 2 * GA_BUF;

    int tid = threadIdx.x;
    int w = tid >> 5, lane = tid & 31;
    int gid = lane >> 2, tig = lane & 3;
    int wm = w >> 2, wn = w & 3;
    int rowBase = blockIdx.y * 128, colBase = blockIdx.x * 128;

    // --- issue k-block 0 copies ---
#pragma unroll
    for (int i = 0; i < 4; i++) {
        int e = tid + i * 256;
        int r = e >> 3, c = (e & 7) * 4;
        cp16(Ab + r * GA_ST + c, A + (size_t)(rowBase + r) * K + c);
    }
#pragma unroll
    for (int i = 0; i < 4; i++) {
        int e = tid + i * 256;
        int kk = e >> 5, c = (e & 31) * 4;
        cp16(Bb + kk * GB_ST + c, W + (size_t)kk * N + colBase + c);
    }
    CP_COMMIT();

    float c[4][4][4];
#pragma unroll
    for (int mt = 0; mt < 4; mt++)
#pragma unroll
        for (int j = 0; j < 4; j++)
#pragma unroll
            for (int e = 0; e < 4; e++) c[mt][j][e] = 0.f;

    int nblk = K / 32;
    for (int kb = 0; kb < nblk; kb++) {
        int buf = kb & 1;
        CP_WAIT(0);
        __syncthreads();
        if (kb + 1 < nblk) {
            int nb = buf ^ 1;
            int k0 = (kb + 1) * 32;
#pragma unroll
            for (int i = 0; i < 4; i++) {
                int e = tid + i * 256;
                int r = e >> 3, cc = (e & 7) * 4;
                cp16(Ab + nb * GA_BUF + r * GA_ST + cc,
                     A + (size_t)(rowBase + r) * K + k0 + cc);
            }
#pragma unroll
            for (int i = 0; i < 4; i++) {
                int e = tid + i * 256;
                int kk = e >> 5, cc = (e & 31) * 4;
                cp16(Bb + nb * GB_BUF + kk * GB_ST + cc,
                     W + (size_t)(k0 + kk) * N + colBase + cc);
            }
            CP_COMMIT();
        }
        const unsigned* Au = (const unsigned*)(Ab + buf * GA_BUF);
        const unsigned* Bu = (const unsigned*)(Bb + buf * GB_BUF);
#pragma unroll
        for (int ks = 0; ks < 32; ks += 8) {
            unsigned af[4][4];
#pragma unroll
            for (int mt = 0; mt < 4; mt++) {
                int r0 = wm * 64 + mt * 16 + gid;
                af[mt][0] = Au[r0 * GA_ST + ks + tig];
                af[mt][1] = Au[(r0 + 8) * GA_ST + ks + tig];
                af[mt][2] = Au[r0 * GA_ST + ks + tig + 4];
                af[mt][3] = Au[(r0 + 8) * GA_ST + ks + tig + 4];
            }
#pragma unroll
            for (int j = 0; j < 4; j++) {
                int nc = wn * 32 + j * 8 + gid;
                unsigned b0 = Bu[(ks + tig) * GB_ST + nc];
                unsigned b1 = Bu[(ks + tig + 4) * GB_ST + nc];
#pragma unroll
                for (int mt = 0; mt < 4; mt++)
                    mma_tf32(c[mt][j], af[mt], b0, b1);
            }
        }
    }
#pragma unroll
    for (int mt = 0; mt < 4; mt++) {
#pragma unroll
        for (int j = 0; j < 4; j++) {
            int r = rowBase + wm * 64 + mt * 16 + gid;
            int cc = colBase + wn * 32 + j * 8 + tig * 2;
            float b0 = bias ? bias[cc] : 0.f;
            float b1 = bias ? bias[cc + 1] : 0.f;
#pragma unroll
            for (int half = 0; half < 2; half++) {
                int rr = r + half * 8;
                float v0 = c[mt][j][half * 2 + 0] + b0;
                float v1 = c[mt][j][half * 2 + 1] + b1;
                if (EPI == 1) {
                    float x3 = v0 * v0 * v0;
                    v0 = 0.5f * v0 * (1.f + tanhf(0.7978845608028654f * (v0 + 0.044715f * x3)));
                    x3 = v1 * v1 * v1;
                    v1 = 0.5f * v1 * (1.f + tanhf(0.7978845608028654f * (v1 + 0.044715f * x3)));
                }
                float2* dst = (float2*)(C + (size_t)rr * ldc + cc);
                if (EPI == 2) {
                    float2 old = *dst;
                    dst->x = old.x + v0; dst->y = old.y + v1;
                } else {
                    *dst = make_float2(v0, v1);
                }
            }
        }
    }
}

// ---------------- flash attention: register softmax + cp.async --------------
// CTA: 128 q-rows x one (b,h). 8 warps; warp = 16q x full 64-kv chunk.
// smem: Q[128][68] + double-buffered {K[64][68], V[64][68]}  = 104448 B
#define AQ 68
#define ATT_SMEM ((128 * AQ + 4 * 64 * AQ) * 4)

__global__ __launch_bounds__(256, 2)
void attn_tc(const float* __restrict__ qkv, float* __restrict__ attn_o) {
    extern __shared__ float sm[];
    float* Qs = sm;
    float* KV = sm + 128 * AQ;   // buf stride 2*4352; K then V

    int qt = blockIdx.x, h = blockIdx.y, bb = blockIdx.z;
    int tid = threadIdx.x;
    int w = tid >> 5, lane = tid & 31;
    int gid = lane >> 2, tig = lane & 3;
    int qs = w * 16;
    const float* base = qkv + (size_t)bb * NPTS * 1152;

    // --- issue Q loads (group 0) ---
#pragma unroll
    for (int i = 0; i < 8; i++) {
        int t = tid + i * 256;
        int r = t >> 4, c4 = t & 15;
        cp16(Qs + r * AQ + c4 * 4,
             base + (size_t)(qt * 128 + r) * 1152 + h * 64 + c4 * 4);
    }
    CP_COMMIT();
    // --- issue chunk 0 (group 1) ---
#pragma unroll
    for (int i = 0; i < 8; i++) {
        int t = tid + i * 256;
        int isV = t >> 10;
        int r = (t >> 4) & 63, c4 = t & 15;
        cp16(KV + isV * 4352 + r * AQ + c4 * 4,
             base + (size_t)r * 1152 + (isV ? 768 : 384) + h * 64 + c4 * 4);
    }
    CP_COMMIT();

    CP_WAIT(1);          // Q arrived
    __syncthreads();

    // --- preload Q fragments (with 1/8 softmax scale folded in) ---
    unsigned qf[8][4];
#pragma unroll
    for (int s = 0; s < 8; s++) {
        qf[s][0] = __float_as_uint(Qs[(qs + gid) * AQ + s * 8 + tig] * 0.125f);
        qf[s][1] = __float_as_uint(Qs[(qs + gid + 8) * AQ + s * 8 + tig] * 0.125f);
        qf[s][2] = __float_as_uint(Qs[(qs + gid) * AQ + s * 8 + tig + 4] * 0.125f);
        qf[s][3] = __float_as_uint(Qs[(qs + gid + 8) * AQ + s * 8 + tig + 4] * 0.125f);
    }

    float oc[8][4];
#pragma unroll
    for (int j = 0; j < 8; j++)
#pragma unroll
        for (int e = 0; e < 4; e++) oc[j][e] = 0.f;
    float m0 = -1e30f, m1 = -1e30f, l0 = 0.f, l1 = 0.f;

    int srcA = (lane & 28) | (tig >> 1);
    int srcB = srcA + 2;
    int par = tig & 1;

    for (int jt = 0; jt < NPTS / 64; jt++) {
        int buf = jt & 1;
        CP_WAIT(0);              // chunk jt arrived (this thread's copies)
        __syncthreads();         // all threads' copies visible; prev compute done
        if (jt + 1 < NPTS / 64) {
            int nb = buf ^ 1;
#pragma unroll
            for (int i = 0; i < 8; i++) {
                int t = tid + i * 256;
                int isV = t >> 10;
                int r = (t >> 4) & 63, c4 = t & 15;
                cp16(KV + nb * 8704 + isV * 4352 + r * AQ + c4 * 4,
                     base + (size_t)((jt + 1) * 64 + r) * 1152 + (isV ? 768 : 384) + h * 64 + c4 * 4);
            }
            CP_COMMIT();
        }
        const unsigned* Ku = (const unsigned*)(KV + buf * 8704);
        const unsigned* Vu = Ku + 4352;

        // --- S = (Q/8) @ K^T : 16q x 64kv in registers ---
        float ps[8][4];
#pragma unroll
        for (int j = 0; j < 8; j++)
#pragma unroll
            for (int e = 0; e < 4; e++) ps[j][e] = 0.f;
#pragma unroll
        for (int s = 0; s < 8; s++) {
#pragma unroll
            for (int j = 0; j < 8; j++) {
                unsigned b0 = Ku[(j * 8 + gid) * AQ + s * 8 + tig];
                unsigned b1 = Ku[(j * 8 + gid) * AQ + s * 8 + tig + 4];
                mma_tf32(ps[j], qf[s], b0, b1);
            }
        }

        // --- online softmax, fully in registers (rows gid / gid+8) ---
        float mx0 = -1e30f, mx1 = -1e30f;
#pragma unroll
        for (int j = 0; j < 8; j++) {
            mx0 = fmaxf(mx0, fmaxf(ps[j][0], ps[j][1]));
            mx1 = fmaxf(mx1, fmaxf(ps[j][2], ps[j][3]));
        }
        mx0 = fmaxf(mx0, __shfl_xor_sync(0xffffffffu, mx0, 1));
        mx0 = fmaxf(mx0, __shfl_xor_sync(0xffffffffu, mx0, 2));
        mx1 = fmaxf(mx1, __shfl_xor_sync(0xffffffffu, mx1, 1));
        mx1 = fmaxf(mx1, __shfl_xor_sync(0xffffffffu, mx1, 2));
        float mn0 = fmaxf(m0, mx0), mn1 = fmaxf(m1, mx1);
        float cr0 = __expf(m0 - mn0), cr1 = __expf(m1 - mn1);
        float s0 = 0.f, s1 = 0.f;
#pragma unroll
        for (int j = 0; j < 8; j++) {
            ps[j][0] = __expf(ps[j][0] - mn0); s0 += ps[j][0];
            ps[j][1] = __expf(ps[j][1] - mn0); s0 += ps[j][1];
            ps[j][2] = __expf(ps[j][2] - mn1); s1 += ps[j][2];
            ps[j][3] = __expf(ps[j][3] - mn1); s1 += ps[j][3];
        }
        s0 += __shfl_xor_sync(0xffffffffu, s0, 1);
        s0 += __shfl_xor_sync(0xffffffffu, s0, 2);
        s1 += __shfl_xor_sync(0xffffffffu, s1, 1);
        s1 += __shfl_xor_sync(0xffffffffu, s1, 2);
        l0 = l0 * cr0 + s0; l1 = l1 * cr1 + s1;
        m0 = mn0; m1 = mn1;
#pragma unroll
        for (int j = 0; j < 8; j++) {
            oc[j][0] *= cr0; oc[j][1] *= cr0;
            oc[j][2] *= cr1; oc[j][3] *= cr1;
        }

        // --- O += P @ V ; P shuffled from accumulator layout to A-frag ---
#pragma unroll
        for (int t = 0; t < 8; t++) {
            float sA0 = __shfl_sync(0xffffffffu, ps[t][0], srcA);
            float sA1 = __shfl_sync(0xffffffffu, ps[t][1], srcA);
            float sA2 = __shfl_sync(0xffffffffu, ps[t][2], srcA);
            float sA3 = __shfl_sync(0xffffffffu, ps[t][3], srcA);
            float sB0 = __shfl_sync(0xffffffffu, ps[t][0], srcB);
            float sB1 = __shfl_sync(0xffffffffu, ps[t][1], srcB);
            float sB2 = __shfl_sync(0xffffffffu, ps[t][2], srcB);
            float sB3 = __shfl_sync(0xffffffffu, ps[t][3], srcB);
            unsigned af[4];
            af[0] = __float_as_uint(par ? sA1 : sA0);
            af[1] = __float_as_uint(par ? sA3 : sA2);
            af[2] = __float_as_uint(par ? sB1 : sB0);
            af[3] = __float_as_uint(par ? sB3 : sB2);
#pragma unroll
            for (int j = 0; j < 8; j++) {
                unsigned b0 = Vu[(t * 8 + tig) * AQ + j * 8 + gid];
                unsigned b1 = Vu[(t * 8 + tig + 4) * AQ + j * 8 + gid];
                mma_tf32(oc[j], af, b0, b1);
            }
        }
    }

    // --- normalize & store ---
    float inv0 = 1.f / l0, inv1 = 1.f / l1;
    int r0 = bb * NPTS + qt * 128 + qs + gid;
#pragma unroll
    for (int j = 0; j < 8; j++) {
        int cc = h * 64 + j * 8 + tig * 2;
        float2* d0 = (float2*)(attn_o + (size_t)r0 * DMODEL + cc);
        *d0 = make_float2(oc[j][0] * inv0, oc[j][1] * inv0);
        float2* d1 = (float2*)(attn_o + (size_t)(r0 + 8) * DMODEL + cc);
        *d1 = make_float2(oc[j][2] * inv1, oc[j][3] * inv1);
    }
}

// ---------------- geom branch: gather + softmax(K=8) -----------------------
__global__ void geom_kernel(const float* __restrict__ gq, const float* __restrict__ gk,
                            const float* __restrict__ gv, const int* __restrict__ idx,
                            float* __restrict__ merged) {
    int m = blockIdx.x;
    int bb = m >> 11;
    __shared__ float dots[KNN];
    __shared__ int nb[KNN];
    int tid = threadIdx.x, w = tid >> 5, lane = tid & 31;
    if (tid < KNN) nb[tid] = idx[(size_t)m * KNN + tid];
    __syncthreads();
    const float* qrow = gq + (size_t)m * DMODEL;
    const float* krow = gk + ((size_t)bb * NPTS + nb[w]) * DMODEL;
    float s = 0.f;
    for (int d = lane; d < DMODEL; d += 32) s += qrow[d] * krow[d];
#pragma unroll
    for (int o = 16; o; o >>= 1) s += __shfl_xor_sync(0xffffffffu, s, o);
    if (lane == 0) dots[w] = s * 0.05103103630798287f;
    __syncthreads();
    float mx = dots[0];
#pragma unroll
    for (int k = 1; k < KNN; k++) mx = fmaxf(mx, dots[k]);
    float p[KNN], sum = 0.f;
#pragma unroll
    for (int k = 0; k < KNN; k++) { p[k] = expf(dots[k] - mx); sum += p[k]; }
    float inv = 1.f / sum;
    for (int d = tid; d < DMODEL; d += 256) {
        float a = 0.f;
#pragma unroll
        for (int k = 0; k < KNN; k++)
            a += p[k] * gv[((size_t)bb * NPTS + nb[k]) * DMODEL + d];
        merged[(size_t)m * 768 + 384 + d] = a * inv;
    }
}

// ---------------- output transpose -----------------------------------------
__global__ void out_transpose(const float* __restrict__ f, float* __restrict__ out) {
    __shared__ float tile[32][33];
    int bb = blockIdx.z;
    int n0 = blockIdx.x * 32, d0 = blockIdx.y * 32;
    int tx = threadIdx.x, ty = threadIdx.y;
#pragma unroll
    for (int i = 0; i < 32; i += 8)
        tile[ty + i][tx] = f[((size_t)bb * NPTS + n0 + ty + i) * DMODEL + d0 + tx];
    __syncthreads();
#pragma unroll
    for (int i = 0; i < 32; i += 8)
        out[((size_t)bb * DMODEL + d0 + ty + i) * NPTS + n0 + tx] = tile[tx][ty + i];
}

// ---------------- launch ----------------------------------------------------
extern "C" void kernel_launch(void* const* d_in, const int* in_sizes, int n_in,
                              void* d_out, int out_size) {
    const float* coords     = (const float*)d_in[0];
    const float* features   = (const float*)d_in[1];
    const float* ln1_g      = (const float*)d_in[2];
    const float* ln1_b      = (const float*)d_in[3];
    const float* w_qkv      = (const float*)d_in[4];
    const float* w_attn_out = (const float*)d_in[5];
    const float* b_attn_out = (const float*)d_in[6];
    const float* ga_wq      = (const float*)d_in[7];
    const float* ga_wk      = (const float*)d_in[8];
    const float* ga_wv      = (const float*)d_in[9];
    const float* merge_w    = (const float*)d_in[10];
    const float* merge_b    = (const float*)d_in[11];
    const float* ln2_g      = (const float*)d_in[12];
    const float* ln2_b      = (const float*)d_in[13];
    const float* ff_w1      = (const float*)d_in[14];
    const float* ff_b1      = (const float*)d_in[15];
    const float* ff_w2      = (const float*)d_in[16];
    const float* ff_b2      = (const float*)d_in[17];
    float* out = (float*)d_out;

    float *pf, *pnf, *pqkv, *pattn, *pgq, *pgk, *pgv, *pmerged, *ph, *pt;
    int* pidx;
    cudaGetSymbolAddress((void**)&pf, g_f);
    cudaGetSymbolAddress((void**)&pnf, g_nf);
    cudaGetSymbolAddress((void**)&pqkv, g_qkv);
    cudaGetSymbolAddress((void**)&pattn, g_attn);
    cudaGetSymbolAddress((void**)&pgq, g_gq);
    cudaGetSymbolAddress((void**)&pgk, g_gk);
    cudaGetSymbolAddress((void**)&pgv, g_gv);
    cudaGetSymbolAddress((void**)&pmerged, g_merged);
    cudaGetSymbolAddress((void**)&ph, g_h);
    cudaGetSymbolAddress((void**)&pt, g_t);
    cudaGetSymbolAddress((void**)&pidx, g_idx);

    cudaFuncSetAttribute(attn_tc, cudaFuncAttributeMaxDynamicSharedMemorySize, ATT_SMEM);
    cudaFuncSetAttribute(gemm_tc<0>, cudaFuncAttributeMaxDynamicSharedMemorySize, GEMM_SMEM);
    cudaFuncSetAttribute(gemm_tc<1>, cudaFuncAttributeMaxDynamicSharedMemorySize, GEMM_SMEM);
    cudaFuncSetAttribute(gemm_tc<2>, cudaFuncAttributeMaxDynamicSharedMemorySize, GEMM_SMEM);

    prep_ln1<<<MTOK, 128>>>(features, ln1_g, ln1_b, pf, pnf);
    knn_kernel<<<dim3(NPTS / 256, BATCH), 256>>>(coords, pidx);
    gemm_tc<0><<<dim3(1152 / 128, MTOK / 128), 256, GEMM_SMEM>>>(pnf, w_qkv, nullptr, pqkv, MTOK, 384, 1152, 1152);
    attn_tc<<<dim3(NPTS / 128, NHEAD, BATCH), 256, ATT_SMEM>>>(pqkv, pattn);
    gemm_tc<0><<<dim3(384 / 128, MTOK / 128), 256, GEMM_SMEM>>>(pattn, w_attn_out, b_attn_out, pmerged, MTOK, 384, 384, 768);
    gemm_tc<0><<<dim3(384 / 128, MTOK / 128), 256, GEMM_SMEM>>>(pnf, ga_wq, nullptr, pgq, MTOK, 384, 384, 384);
    gemm_tc<0><<<dim3(384 / 128, MTOK / 128), 256, GEMM_SMEM>>>(pnf, ga_wk, nullptr, pgk, MTOK, 384, 384, 384);
    gemm_tc<0><<<dim3(384 / 128, MTOK / 128), 256, GEMM_SMEM>>>(pnf, ga_wv, nullptr, pgv, MTOK, 384, 384, 384);
    geom_kernel<<<MTOK, 256>>>(pgq, pgk, pgv, pidx, pmerged);
    gemm_tc<2><<<dim3(384 / 128, MTOK / 128), 256, GEMM_SMEM>>>(pmerged, merge_w, merge_b, pf, MTOK, 768, 384, 384);
    ln2_k<<<MTOK, 128>>>(pf, ln2_g, ln2_b, ph);
    gemm_tc<1><<<dim3(768 / 128, MTOK / 128), 256, GEMM_SMEM>>>(ph, ff_w1, ff_b1, pt, MTOK, 384, 768, 768);
    gemm_tc<2><<<dim3(384 / 128, MTOK / 128), 256, GEMM_SMEM>>>(pt, ff_w2, ff_b2, pf, MTOK, 768, 384, 384);
    out_transpose<<<dim3(NPTS / 32, DMODEL / 32, BATCH), dim3(32, 8)>>>(pf, out);
}

// round 11
// speedup vs baseline: 4.8362x; 1.5917x over previous
#include <cuda_runtime.h>
#include <cuda_fp16.h>
#include <math.h>

#define BATCH 8
#define NPTS 2048
#define DMODEL 384
#define NHEAD 6
#define KNN 8
#define MTOK (BATCH * NPTS)   // 16384

// ---------------- scratch (device globals; no allocation allowed) ----------
__device__ float  g_f[MTOK * DMODEL];            // residual, fp32
__device__ __half g_nf[MTOK * DMODEL];
__device__ __half g_qk[MTOK * 2 * DMODEL];       // [M][768]: Q | K
__device__ __half g_vt[BATCH * DMODEL * NPTS];   // V transposed: [b][h*64+d][n]
__device__ __half g_attn[MTOK * DMODEL];
__device__ __half g_gq[MTOK * DMODEL];
__device__ __half g_gk[MTOK * DMODEL];
__device__ __half g_gv[MTOK * DMODEL];
__device__ __half g_merged[MTOK * 2 * DMODEL];
__device__ __half g_h[MTOK * DMODEL];
__device__ __half g_t[MTOK * 2 * DMODEL];
__device__ int    g_idx[MTOK * KNN];
// pair-packed fp16 weights (u32 = half2 of rows k, k+1)
__device__ unsigned g_wqkv_p[192 * 1152];
__device__ unsigned g_wo_p[192 * 384];
__device__ unsigned g_gaq_p[192 * 384];
__device__ unsigned g_gak_p[192 * 384];
__device__ unsigned g_gav_p[192 * 384];
__device__ unsigned g_mrg_p[384 * 384];
__device__ unsigned g_ff1_p[192 * 768];
__device__ unsigned g_ff2_p[384 * 384];

// ---------------- helpers ---------------------------------------------------
__device__ __forceinline__ void mma_f16(float* c, const unsigned* a, unsigned b0, unsigned b1) {
    asm volatile("mma.sync.aligned.m16n8k16.row.col.f32.f16.f16.f32 "
        "{%0,%1,%2,%3}, {%4,%5,%6,%7}, {%8,%9}, {%0,%1,%2,%3};"
        : "+f"(c[0]), "+f"(c[1]), "+f"(c[2]), "+f"(c[3])
        : "r"(a[0]), "r"(a[1]), "r"(a[2]), "r"(a[3]), "r"(b0), "r"(b1));
}

__device__ __forceinline__ unsigned h2u(float a, float b) {
    __half2 h = __floats2half2_rn(a, b);
    return *(unsigned*)&h;
}

__device__ __forceinline__ void cp16(void* dst, const void* src) {
    unsigned d = (unsigned)__cvta_generic_to_shared(dst);
    asm volatile("cp.async.ca.shared.global [%0], [%1], 16;\n" :: "r"(d), "l"(src));
}
#define CP_COMMIT() asm volatile("cp.async.commit_group;\n" ::: "memory")
#define CP_WAIT(N)  asm volatile("cp.async.wait_group %0;\n" :: "n"(N) : "memory")

__device__ __forceinline__ float gelu_f(float v) {
    float u = 0.7978845608028654f * (v + 0.044715f * v * v * v);
    float t = 1.f - 2.f / (__expf(2.f * u) + 1.f);   // tanh(u)
    return 0.5f * v * (1.f + t);
}

// ---------------- weight pair-pack conversion -------------------------------
__global__ void cvt_pairs(const float* __restrict__ src, unsigned* __restrict__ dst,
                          int K2, int N) {
    int e = blockIdx.x * 256 + threadIdx.x;
    if (e >= K2 * N) return;
    int kp = e / N, n = e - kp * N;
    dst[e] = h2u(src[(size_t)(2 * kp) * N + n], src[(size_t)(2 * kp + 1) * N + n]);
}

// ---------------- LN1 + transpose ------------------------------------------
__global__ void prep_ln1(const float* __restrict__ feat,
                         const float* __restrict__ g, const float* __restrict__ b,
                         float* __restrict__ f, __half* __restrict__ nf) {
    int m = blockIdx.x;
    int bb = m >> 11, n = m & 2047;
    const float* src = feat + (size_t)bb * DMODEL * NPTS + n;
    float v[3];
    float s = 0.f, s2 = 0.f;
#pragma unroll
    for (int i = 0; i < 3; i++) {
        int d = threadIdx.x + i * 128;
        float x = src[(size_t)d * NPTS];
        v[i] = x; s += x; s2 += x * x;
    }
#pragma unroll
    for (int o = 16; o; o >>= 1) {
        s  += __shfl_xor_sync(0xffffffffu, s, o);
        s2 += __shfl_xor_sync(0xffffffffu, s2, o);
    }
    __shared__ float sh[8];
    int w = threadIdx.x >> 5;
    if ((threadIdx.x & 31) == 0) { sh[w] = s; sh[4 + w] = s2; }
    __syncthreads();
    s  = sh[0] + sh[1] + sh[2] + sh[3];
    s2 = sh[4] + sh[5] + sh[6] + sh[7];
    float mean = s * (1.f / DMODEL);
    float var  = s2 * (1.f / DMODEL) - mean * mean;
    float rstd = rsqrtf(var + 1e-5f);
#pragma unroll
    for (int i = 0; i < 3; i++) {
        int d = threadIdx.x + i * 128;
        float x = v[i];
        f[(size_t)m * DMODEL + d]  = x;
        nf[(size_t)m * DMODEL + d] = __float2half((x - mean) * rstd * g[d] + b[d]);
    }
}

// ---------------- LN2: f fp32 -> h fp16 ------------------------------------
__global__ void ln2_k(const float* __restrict__ f,
                      const float* __restrict__ g, const float* __restrict__ b,
                      __half* __restrict__ h) {
    int m = blockIdx.x;
    const float* row = f + (size_t)m * DMODEL;
    float v[3];
    float s = 0.f, s2 = 0.f;
#pragma unroll
    for (int i = 0; i < 3; i++) {
        int d = threadIdx.x + i * 128;
        float x = row[d];
        v[i] = x; s += x; s2 += x * x;
    }
#pragma unroll
    for (int o = 16; o; o >>= 1) {
        s  += __shfl_xor_sync(0xffffffffu, s, o);
        s2 += __shfl_xor_sync(0xffffffffu, s2, o);
    }
    __shared__ float sh[8];
    int w = threadIdx.x >> 5;
    if ((threadIdx.x & 31) == 0) { sh[w] = s; sh[4 + w] = s2; }
    __syncthreads();
    s  = sh[0] + sh[1] + sh[2] + sh[3];
    s2 = sh[4] + sh[5] + sh[6] + sh[7];
    float mean = s * (1.f / DMODEL);
    float var  = s2 * (1.f / DMODEL) - mean * mean;
    float rstd = rsqrtf(var + 1e-5f);
#pragma unroll
    for (int i = 0; i < 3; i++) {
        int d = threadIdx.x + i * 128;
        h[(size_t)m * DMODEL + d] = __float2half((v[i] - mean) * rstd * g[d] + b[d]);
    }
}

// ---------------- brute force KNN top-8 ------------------------------------
__global__ void knn_kernel(const float* __restrict__ coords, int* __restrict__ idxout) {
    int bb = blockIdx.y;
    __shared__ float cx[NPTS], cy[NPTS], cz[NPTS], sq[NPTS];
    const float* cb = coords + (size_t)bb * 3 * NPTS;
    for (int i = threadIdx.x; i < NPTS; i += 256) {
        float x = cb[i], y = cb[NPTS + i], z = cb[2 * NPTS + i];
        cx[i] = x; cy[i] = y; cz[i] = z;
        sq[i] = x * x + y * y + z * z;
    }
    __syncthreads();
    int q = blockIdx.x * 256 + threadIdx.x;
    float qx = cx[q], qy = cy[q], qz = cz[q], qsq = sq[q];
    float bd[KNN]; int bi[KNN];
#pragma unroll
    for (int k = 0; k < KNN; k++) { bd[k] = 3.0e38f; bi[k] = 0; }
    for (int mi = 0; mi < NPTS; mi++) {
        float d = qsq + sq[mi] - 2.f * (qx * cx[mi] + qy * cy[mi] + qz * cz[mi]);
        if (d < bd[KNN - 1]) {
            int p = KNN - 1;
            while (p > 0 && bd[p - 1] > d) { bd[p] = bd[p - 1]; bi[p] = bi[p - 1]; p--; }
            bd[p] = d; bi[p] = mi;
        }
    }
#pragma unroll
    for (int k = 0; k < KNN; k++)
        idxout[((size_t)bb * NPTS + q) * KNN + k] = bi[k];
}

// ---------------- fp16 GEMM: C[M,N] = A[M,K] @ W[K,N] -----------------------
// Block 128x128, 8 warps (2 wm x 4 wn), warp tile 64x32, K-block 32 (2x k16).
// A half [row][k], row stride 20 u32 = 80 B (16B-aligned for cp.async!).
// B pair-packed [kpair][n] stride 136 u32 = 544 B (16B-aligned).
// EPI: 0 half store(+bias), 1 half gelu(+bias), 2 float +=(+bias),
//      3 QKV special: cols<768 -> qk half, cols>=768 -> vt (transposed half)
#define GA_ST 20
#define GB_ST 136
#define GA_BUF (128 * GA_ST)
#define GB_BUF (16 * GB_ST)
#define GEMM_SMEM ((2 * GA_BUF + 2 * GB_BUF) * 4)

template <int EPI>
__global__ __launch_bounds__(256, 2)
void gemm_f16(const __half* __restrict__ A, const unsigned* __restrict__ Wp,
              const float* __restrict__ bias, void* Cv, __half* __restrict__ vt,
              int M, int K, int N, int ldc) {
    extern __shared__ unsigned smu[];
    unsigned* Ab = smu;
    unsigned* Bb = smu + 2 * GA_BUF;

    int tid = threadIdx.x;
    int w = tid >> 5, lane = tid & 31;
    int gid = lane >> 2, tig = lane & 3;
    int wm = w >> 2, wn = w & 3;
    int rowBase = blockIdx.y * 128, colBase = blockIdx.x * 128;

    // k-block 0 copies
#pragma unroll
    for (int i = 0; i < 2; i++) {
        int e = tid + i * 256;
        int r = e >> 2, c = e & 3;
        cp16(Ab + r * GA_ST + c * 4, A + (size_t)(rowBase + r) * K + c * 8);
    }
#pragma unroll
    for (int i = 0; i < 2; i++) {
        int e = tid + i * 256;
        int r = e >> 5, c = e & 31;
        cp16(Bb + r * GB_ST + c * 4, Wp + (size_t)r * N + colBase + c * 4);
    }
    CP_COMMIT();

    float c[4][4][4];
#pragma unroll
    for (int mt = 0; mt < 4; mt++)
#pragma unroll
        for (int j = 0; j < 4; j++)
#pragma unroll
            for (int e = 0; e < 4; e++) c[mt][j][e] = 0.f;

    int nblk = K / 32;
    for (int kb = 0; kb < nblk; kb++) {
        int buf = kb & 1;
        CP_WAIT(0);
        __syncthreads();
        if (kb + 1 < nblk) {
            int nb = buf ^ 1;
            int k0 = (kb + 1) * 32;
#pragma unroll
            for (int i = 0; i < 2; i++) {
                int e = tid + i * 256;
                int r = e >> 2, cc = e & 3;
                cp16(Ab + nb * GA_BUF + r * GA_ST + cc * 4,
                     A + (size_t)(rowBase + r) * K + k0 + cc * 8);
            }
#pragma unroll
            for (int i = 0; i < 2; i++) {
                int e = tid + i * 256;
                int r = e >> 5, cc = e & 31;
                cp16(Bb + nb * GB_BUF + r * GB_ST + cc * 4,
                     Wp + (size_t)(k0 / 2 + r) * N + colBase + cc * 4);
            }
            CP_COMMIT();
        }
        const unsigned* Au = Ab + buf * GA_BUF;
        const unsigned* Bu = Bb + buf * GB_BUF;
#pragma unroll
        for (int ksg = 0; ksg < 2; ksg++) {
            int ks8 = ksg * 8;
            unsigned af[4][4];
#pragma unroll
            for (int mt = 0; mt < 4; mt++) {
                int r0 = wm * 64 + mt * 16 + gid;
                af[mt][0] = Au[r0 * GA_ST + ks8 + tig];
                af[mt][1] = Au[(r0 + 8) * GA_ST + ks8 + tig];
                af[mt][2] = Au[r0 * GA_ST + ks8 + tig + 4];
                af[mt][3] = Au[(r0 + 8) * GA_ST + ks8 + tig + 4];
            }
#pragma unroll
            for (int j = 0; j < 4; j++) {
                int nc = wn * 32 + j * 8 + gid;
                unsigned b0 = Bu[(ks8 + tig) * GB_ST + nc];
                unsigned b1 = Bu[(ks8 + tig + 4) * GB_ST + nc];
#pragma unroll
                for (int mt = 0; mt < 4; mt++)
                    mma_f16(c[mt][j], af[mt], b0, b1);
            }
        }
    }
    // epilogue
#pragma unroll
    for (int mt = 0; mt < 4; mt++) {
#pragma unroll
        for (int j = 0; j < 4; j++) {
            int r = rowBase + wm * 64 + mt * 16 + gid;
            int cc = colBase + wn * 32 + j * 8 + tig * 2;
            float b0 = bias ? bias[cc] : 0.f;
            float b1 = bias ? bias[cc + 1] : 0.f;
#pragma unroll
            for (int half = 0; half < 2; half++) {
                int rr = r + half * 8;
                float v0 = c[mt][j][half * 2 + 0] + b0;
                float v1 = c[mt][j][half * 2 + 1] + b1;
                if (EPI == 1) { v0 = gelu_f(v0); v1 = gelu_f(v1); }
                if (EPI == 2) {
                    float2* dst = (float2*)((float*)Cv + (size_t)rr * ldc + cc);
                    float2 old = *dst;
                    dst->x = old.x + v0; dst->y = old.y + v1;
                } else if (EPI == 3) {
                    if (cc < 768) {
                        *(unsigned*)((__half*)Cv + (size_t)rr * 768 + cc) = h2u(v0, v1);
                    } else {
                        int bb = rr >> 11, n = rr & 2047;
                        size_t base = ((size_t)bb * DMODEL + (cc - 768)) * NPTS + n;
                        vt[base] = __float2half(v0);
                        vt[base + NPTS] = __float2half(v1);
                    }
                } else {
                    *(unsigned*)((__half*)Cv + (size_t)rr * ldc + cc) = h2u(v0, v1);
                }
            }
        }
    }
}

// ---------------- fp16 flash attention --------------------------------------
// CTA: 128 q-rows x one (b,h). 8 warps; warp = 16q x full 64-kv chunk.
// smem (u32): Q[128][36] + 2 x {K[64][36], V^T[64][36]}  = 55296 B
#define AQH 36
#define ATT_SMEM ((128 * AQH + 4 * 64 * AQH) * 4)

__global__ __launch_bounds__(256, 2)
void attn_tc(const __half* __restrict__ qk, const __half* __restrict__ vt,
             __half* __restrict__ attn_o) {
    extern __shared__ unsigned smu[];
    unsigned* Qu = smu;
    unsigned* KV = smu + 128 * AQH;   // per buf: K 64*36 then V 64*36

    int qt = blockIdx.x, h = blockIdx.y, bb = blockIdx.z;
    int tid = threadIdx.x;
    int w = tid >> 5, lane = tid & 31;
    int gid = lane >> 2, tig = lane & 3;
    int qs = w * 16;
    const __half* qbase = qk + (size_t)bb * NPTS * 768;
    const __half* vbase = vt + ((size_t)bb * DMODEL + h * 64) * NPTS;

    // Q loads (group 0)
#pragma unroll
    for (int i = 0; i < 4; i++) {
        int t = tid + i * 256;
        int r = t >> 3, c = t & 7;
        cp16(Qu + r * AQH + c * 4,
             qbase + (size_t)(qt * 128 + r) * 768 + h * 64 + c * 8);
    }
    CP_COMMIT();
    // chunk 0 (group 1)
#pragma unroll
    for (int i = 0; i < 2; i++) {
        int t = tid + i * 256;
        int r = t >> 3, c = t & 7;
        cp16(KV + r * AQH + c * 4,
             qbase + (size_t)r * 768 + 384 + h * 64 + c * 8);
        cp16(KV + (64 + r) * AQH + c * 4,
             vbase + (size_t)r * NPTS + c * 8);
    }
    CP_COMMIT();

    CP_WAIT(1);
    __syncthreads();

    // preload Q fragments (4 k16-groups over d=64)
    unsigned qa[4][4];
#pragma unroll
    for (int s2 = 0; s2 < 4; s2++) {
        qa[s2][0] = Qu[(qs + gid) * AQH + s2 * 8 + tig];
        qa[s2][1] = Qu[(qs + gid + 8) * AQH + s2 * 8 + tig];
        qa[s2][2] = Qu[(qs + gid) * AQH + s2 * 8 + tig + 4];
        qa[s2][3] = Qu[(qs + gid + 8) * AQH + s2 * 8 + tig + 4];
    }

    float oc[8][4];
#pragma unroll
    for (int j = 0; j < 8; j++)
#pragma unroll
        for (int e = 0; e < 4; e++) oc[j][e] = 0.f;
    float m0 = -1e30f, m1 = -1e30f, l0 = 0.f, l1 = 0.f;

    for (int jt = 0; jt < NPTS / 64; jt++) {
        int buf = jt & 1;
        CP_WAIT(0);
        __syncthreads();
        if (jt + 1 < NPTS / 64) {
            int nb = buf ^ 1;
#pragma unroll
            for (int i = 0; i < 2; i++) {
                int t = tid + i * 256;
                int r = t >> 3, c = t & 7;
                cp16(KV + nb * 4608 + r * AQH + c * 4,
                     qbase + (size_t)((jt + 1) * 64 + r) * 768 + 384 + h * 64 + c * 8);
                cp16(KV + nb * 4608 + (64 + r) * AQH + c * 4,
                     vbase + (size_t)r * NPTS + (jt + 1) * 64 + c * 8);
            }
            CP_COMMIT();
        }
        const unsigned* Ku = KV + buf * 4608;
        const unsigned* Vu = Ku + 64 * AQH;

        // --- S = Q @ K^T : 16q x 64kv ---
        float ps[8][4];
#pragma unroll
        for (int j = 0; j < 8; j++)
#pragma unroll
            for (int e = 0; e < 4; e++) ps[j][e] = 0.f;
#pragma unroll
        for (int s2 = 0; s2 < 4; s2++) {
#pragma unroll
            for (int j = 0; j < 8; j++) {
                unsigned b0 = Ku[(j * 8 + gid) * AQH + s2 * 8 + tig];
                unsigned b1 = Ku[(j * 8 + gid) * AQH + s2 * 8 + tig + 4];
                mma_f16(ps[j], qa[s2], b0, b1);
            }
        }
#pragma unroll
        for (int j = 0; j < 8; j++) {
            ps[j][0] *= 0.125f; ps[j][1] *= 0.125f;
            ps[j][2] *= 0.125f; ps[j][3] *= 0.125f;
        }

        // --- online softmax in registers ---
        float mx0 = -1e30f, mx1 = -1e30f;
#pragma unroll
        for (int j = 0; j < 8; j++) {
            mx0 = fmaxf(mx0, fmaxf(ps[j][0], ps[j][1]));
            mx1 = fmaxf(mx1, fmaxf(ps[j][2], ps[j][3]));
        }
        mx0 = fmaxf(mx0, __shfl_xor_sync(0xffffffffu, mx0, 1));
        mx0 = fmaxf(mx0, __shfl_xor_sync(0xffffffffu, mx0, 2));
        mx1 = fmaxf(mx1, __shfl_xor_sync(0xffffffffu, mx1, 1));
        mx1 = fmaxf(mx1, __shfl_xor_sync(0xffffffffu, mx1, 2));
        float mn0 = fmaxf(m0, mx0), mn1 = fmaxf(m1, mx1);
        float cr0 = __expf(m0 - mn0), cr1 = __expf(m1 - mn1);
        float s0 = 0.f, s1 = 0.f;
#pragma unroll
        for (int j = 0; j < 8; j++) {
            ps[j][0] = __expf(ps[j][0] - mn0); s0 += ps[j][0];
            ps[j][1] = __expf(ps[j][1] - mn0); s0 += ps[j][1];
            ps[j][2] = __expf(ps[j][2] - mn1); s1 += ps[j][2];
            ps[j][3] = __expf(ps[j][3] - mn1); s1 += ps[j][3];
        }
        s0 += __shfl_xor_sync(0xffffffffu, s0, 1);
        s0 += __shfl_xor_sync(0xffffffffu, s0, 2);
        s1 += __shfl_xor_sync(0xffffffffu, s1, 1);
        s1 += __shfl_xor_sync(0xffffffffu, s1, 2);
        l0 = l0 * cr0 + s0; l1 = l1 * cr1 + s1;
        m0 = mn0; m1 = mn1;
#pragma unroll
        for (int j = 0; j < 8; j++) {
            oc[j][0] *= cr0; oc[j][1] *= cr0;
            oc[j][2] *= cr1; oc[j][3] *= cr1;
        }

        // --- O += P @ V^T : accumulator layout == fp16 A-frag layout ---
#pragma unroll
        for (int j2 = 0; j2 < 4; j2++) {
            unsigned pa[4];
            pa[0] = h2u(ps[2 * j2][0], ps[2 * j2][1]);
            pa[1] = h2u(ps[2 * j2][2], ps[2 * j2][3]);
            pa[2] = h2u(ps[2 * j2 + 1][0], ps[2 * j2 + 1][1]);
            pa[3] = h2u(ps[2 * j2 + 1][2], ps[2 * j2 + 1][3]);
#pragma unroll
            for (int jd = 0; jd < 8; jd++) {
                unsigned b0 = Vu[(jd * 8 + gid) * AQH + j2 * 8 + tig];
                unsigned b1 = Vu[(jd * 8 + gid) * AQH + j2 * 8 + tig + 4];
                mma_f16(oc[jd], pa, b0, b1);
            }
        }
    }

    // --- normalize & store fp16 ---
    float inv0 = 1.f / l0, inv1 = 1.f / l1;
    int r0 = bb * NPTS + qt * 128 + qs + gid;
#pragma unroll
    for (int j = 0; j < 8; j++) {
        int cc = h * 64 + j * 8 + tig * 2;
        *(unsigned*)(attn_o + (size_t)r0 * DMODEL + cc) = h2u(oc[j][0] * inv0, oc[j][1] * inv0);
        *(unsigned*)(attn_o + (size_t)(r0 + 8) * DMODEL + cc) = h2u(oc[j][2] * inv1, oc[j][3] * inv1);
    }
}

// ---------------- geom branch: gather + softmax(K=8), fp16 ------------------
__global__ void geom_kernel(const __half* __restrict__ gq, const __half* __restrict__ gk,
                            const __half* __restrict__ gv, const int* __restrict__ idx,
                            __half* __restrict__ merged) {
    int m = blockIdx.x;
    int bb = m >> 11;
    __shared__ float dots[KNN];
    __shared__ int nb[KNN];
    int tid = threadIdx.x, w = tid >> 5, lane = tid & 31;
    if (tid < KNN) nb[tid] = idx[(size_t)m * KNN + tid];
    __syncthreads();
    const __half2* qrow = (const __half2*)(gq + (size_t)m * DMODEL);
    const __half2* krow = (const __half2*)(gk + ((size_t)bb * NPTS + nb[w]) * DMODEL);
    float s = 0.f;
    for (int d = lane; d < DMODEL / 2; d += 32) {
        float2 q2 = __half22float2(qrow[d]);
        float2 k2 = __half22float2(krow[d]);
        s += q2.x * k2.x + q2.y * k2.y;
    }
#pragma unroll
    for (int o = 16; o; o >>= 1) s += __shfl_xor_sync(0xffffffffu, s, o);
    if (lane == 0) dots[w] = s * 0.05103103630798287f;
    __syncthreads();
    float mx = dots[0];
#pragma unroll
    for (int k = 1; k < KNN; k++) mx = fmaxf(mx, dots[k]);
    float p[KNN], sum = 0.f;
#pragma unroll
    for (int k = 0; k < KNN; k++) { p[k] = __expf(dots[k] - mx); sum += p[k]; }
    float inv = 1.f / sum;
    for (int d = tid; d < DMODEL; d += 256) {
        float a = 0.f;
#pragma unroll
        for (int k = 0; k < KNN; k++)
            a += p[k] * __half2float(gv[((size_t)bb * NPTS + nb[k]) * DMODEL + d]);
        merged[(size_t)m * 768 + 384 + d] = __float2half(a * inv);
    }
}

// ---------------- output transpose -----------------------------------------
__global__ void out_transpose(const float* __restrict__ f, float* __restrict__ out) {
    __shared__ float tile[32][33];
    int bb = blockIdx.z;
    int n0 = blockIdx.x * 32, d0 = blockIdx.y * 32;
    int tx = threadIdx.x, ty = threadIdx.y;
#pragma unroll
    for (int i = 0; i < 32; i += 8)
        tile[ty + i][tx] = f[((size_t)bb * NPTS + n0 + ty + i) * DMODEL + d0 + tx];
    __syncthreads();
#pragma unroll
    for (int i = 0; i < 32; i += 8)
        out[((size_t)bb * DMODEL + d0 + ty + i) * NPTS + n0 + tx] = tile[tx][ty + i];
}

// ---------------- launch ----------------------------------------------------
extern "C" void kernel_launch(void* const* d_in, const int* in_sizes, int n_in,
                              void* d_out, int out_size) {
    const float* coords     = (const float*)d_in[0];
    const float* features   = (const float*)d_in[1];
    const float* ln1_g      = (const float*)d_in[2];
    const float* ln1_b      = (const float*)d_in[3];
    const float* w_qkv      = (const float*)d_in[4];
    const float* w_attn_out = (const float*)d_in[5];
    const float* b_attn_out = (const float*)d_in[6];
    const float* ga_wq      = (const float*)d_in[7];
    const float* ga_wk      = (const float*)d_in[8];
    const float* ga_wv      = (const float*)d_in[9];
    const float* merge_w    = (const float*)d_in[10];
    const float* merge_b    = (const float*)d_in[11];
    const float* ln2_g      = (const float*)d_in[12];
    const float* ln2_b      = (const float*)d_in[13];
    const float* ff_w1      = (const float*)d_in[14];
    const float* ff_b1      = (const float*)d_in[15];
    const float* ff_w2      = (const float*)d_in[16];
    const float* ff_b2      = (const float*)d_in[17];
    float* out = (float*)d_out;

    float* pf; __half *pnf, *pqk, *pvt, *pattn, *pgq, *pgk, *pgv, *pmerged, *ph, *pt;
    int* pidx;
    unsigned *pwqkv, *pwo, *pgaq, *pgak, *pgav, *pmrg, *pff1, *pff2;
    cudaGetSymbolAddress((void**)&pf, g_f);
    cudaGetSymbolAddress((void**)&pnf, g_nf);
    cudaGetSymbolAddress((void**)&pqk, g_qk);
    cudaGetSymbolAddress((void**)&pvt, g_vt);
    cudaGetSymbolAddress((void**)&pattn, g_attn);
    cudaGetSymbolAddress((void**)&pgq, g_gq);
    cudaGetSymbolAddress((void**)&pgk, g_gk);
    cudaGetSymbolAddress((void**)&pgv, g_gv);
    cudaGetSymbolAddress((void**)&pmerged, g_merged);
    cudaGetSymbolAddress((void**)&ph, g_h);
    cudaGetSymbolAddress((void**)&pt, g_t);
    cudaGetSymbolAddress((void**)&pidx, g_idx);
    cudaGetSymbolAddress((void**)&pwqkv, g_wqkv_p);
    cudaGetSymbolAddress((void**)&pwo, g_wo_p);
    cudaGetSymbolAddress((void**)&pgaq, g_gaq_p);
    cudaGetSymbolAddress((void**)&pgak, g_gak_p);
    cudaGetSymbolAddress((void**)&pgav, g_gav_p);
    cudaGetSymbolAddress((void**)&pmrg, g_mrg_p);
    cudaGetSymbolAddress((void**)&pff1, g_ff1_p);
    cudaGetSymbolAddress((void**)&pff2, g_ff2_p);

    cudaFuncSetAttribute(attn_tc, cudaFuncAttributeMaxDynamicSharedMemorySize, ATT_SMEM);
    cudaFuncSetAttribute(gemm_f16<0>, cudaFuncAttributeMaxDynamicSharedMemorySize, GEMM_SMEM);
    cudaFuncSetAttribute(gemm_f16<1>, cudaFuncAttributeMaxDynamicSharedMemorySize, GEMM_SMEM);
    cudaFuncSetAttribute(gemm_f16<2>, cudaFuncAttributeMaxDynamicSharedMemorySize, GEMM_SMEM);
    cudaFuncSetAttribute(gemm_f16<3>, cudaFuncAttributeMaxDynamicSharedMemorySize, GEMM_SMEM);

    // weight packing (graph-capturable, deterministic)
    cvt_pairs<<<(192 * 1152 + 255) / 256, 256>>>(w_qkv, pwqkv, 192, 1152);
    cvt_pairs<<<(192 * 384 + 255) / 256, 256>>>(w_attn_out, pwo, 192, 384);
    cvt_pairs<<<(192 * 384 + 255) / 256, 256>>>(ga_wq, pgaq, 192, 384);
    cvt_pairs<<<(192 * 384 + 255) / 256, 256>>>(ga_wk, pgak, 192, 384);
    cvt_pairs<<<(192 * 384 + 255) / 256, 256>>>(ga_wv, pgav, 192, 384);
    cvt_pairs<<<(384 * 384 + 255) / 256, 256>>>(merge_w, pmrg, 384, 384);
    cvt_pairs<<<(192 * 768 + 255) / 256, 256>>>(ff_w1, pff1, 192, 768);
    cvt_pairs<<<(384 * 384 + 255) / 256, 256>>>(ff_w2, pff2, 384, 384);

    prep_ln1<<<MTOK, 128>>>(features, ln1_g, ln1_b, pf, pnf);
    knn_kernel<<<dim3(NPTS / 256, BATCH), 256>>>(coords, pidx);
    gemm_f16<3><<<dim3(9, MTOK / 128), 256, GEMM_SMEM>>>(pnf, pwqkv, nullptr, pqk, pvt, MTOK, 384, 1152, 768);
    attn_tc<<<dim3(NPTS / 128, NHEAD, BATCH), 256, ATT_SMEM>>>(pqk, pvt, pattn);
    gemm_f16<0><<<dim3(3, MTOK / 128), 256, GEMM_SMEM>>>(pattn, pwo, b_attn_out, pmerged, nullptr, MTOK, 384, 384, 768);
    gemm_f16<0><<<dim3(3, MTOK / 128), 256, GEMM_SMEM>>>(pnf, pgaq, nullptr, pgq, nullptr, MTOK, 384, 384, 384);
    gemm_f16<0><<<dim3(3, MTOK / 128), 256, GEMM_SMEM>>>(pnf, pgak, nullptr, pgk, nullptr, MTOK, 384, 384, 384);
    gemm_f16<0><<<dim3(3, MTOK / 128), 256, GEMM_SMEM>>>(pnf, pgav, nullptr, pgv, nullptr, MTOK, 384, 384, 384);
    geom_kernel<<<MTOK, 256>>>(pgq, pgk, pgv, pidx, pmerged);
    gemm_f16<2><<<dim3(3, MTOK / 128), 256, GEMM_SMEM>>>(pmerged, pmrg, merge_b, pf, nullptr, MTOK, 768, 384, 384);
    ln2_k<<<MTOK, 128>>>(pf, ln2_g, ln2_b, ph);
    gemm_f16<1><<<dim3(6, MTOK / 128), 256, GEMM_SMEM>>>(ph, pff1, ff_b1, pt, nullptr, MTOK, 384, 768, 768);
    gemm_f16<2><<<dim3(3, MTOK / 128), 256, GEMM_SMEM>>>(pt, pff2, ff_b2, pf, nullptr, MTOK, 768, 384, 384);
    out_transpose<<<dim3(NPTS / 32, DMODEL / 32, BATCH), dim3(32, 8)>>>(pf, out);
}

// round 13
// speedup vs baseline: 5.0393x; 1.0420x over previous
#include <cuda_runtime.h>
#include <cuda_fp16.h>
#include <math.h>

#define BATCH 8
#define NPTS 2048
#define DMODEL 384
#define NHEAD 6
#define KNN 8
#define MTOK (BATCH * NPTS)   // 16384

// ---------------- scratch (device globals; no allocation allowed) ----------
__device__ float  g_f[MTOK * DMODEL];            // residual, fp32
__device__ __half g_nf[MTOK * DMODEL];
__device__ __half g_qk[MTOK * 2 * DMODEL];       // [M][768]: Q | K
__device__ __half g_vt[BATCH * DMODEL * NPTS];   // V transposed: [b][h*64+d][n]
__device__ __half g_attn[MTOK * DMODEL];
__device__ __half g_gqkv[MTOK * 3 * DMODEL];     // [M][1152]: gq | gk | gv
__device__ __half g_merged[MTOK * 2 * DMODEL];
__device__ __half g_h[MTOK * DMODEL];
__device__ __half g_t[MTOK * 2 * DMODEL];
__device__ int    g_idx[MTOK * KNN];
// pair-packed fp16 weights (u32 = half2 of rows k, k+1)
__device__ unsigned g_wqkv_p[192 * 1152];
__device__ unsigned g_wo_p[192 * 384];
__device__ unsigned g_ga_p[192 * 1152];          // wq | wk | wv side by side
__device__ unsigned g_mrg_p[384 * 384];
__device__ unsigned g_ff1_p[192 * 768];
__device__ unsigned g_ff2_p[384 * 384];

// ---------------- helpers ---------------------------------------------------
__device__ __forceinline__ void mma_f16(float* c, const unsigned* a, unsigned b0, unsigned b1) {
    asm volatile("mma.sync.aligned.m16n8k16.row.col.f32.f16.f16.f32 "
        "{%0,%1,%2,%3}, {%4,%5,%6,%7}, {%8,%9}, {%0,%1,%2,%3};"
        : "+f"(c[0]), "+f"(c[1]), "+f"(c[2]), "+f"(c[3])
        : "r"(a[0]), "r"(a[1]), "r"(a[2]), "r"(a[3]), "r"(b0), "r"(b1));
}

__device__ __forceinline__ unsigned h2u(float a, float b) {
    __half2 h = __floats2half2_rn(a, b);
    return *(unsigned*)&h;
}

__device__ __forceinline__ void cp16(void* dst, const void* src) {
    unsigned d = (unsigned)__cvta_generic_to_shared(dst);
    asm volatile("cp.async.ca.shared.global [%0], [%1], 16;\n" :: "r"(d), "l"(src));
}
#define CP_COMMIT() asm volatile("cp.async.commit_group;\n" ::: "memory")
#define CP_WAIT(N)  asm volatile("cp.async.wait_group %0;\n" :: "n"(N) : "memory")

__device__ __forceinline__ float gelu_f(float v) {
    float u = 0.7978845608028654f * (v + 0.044715f * v * v * v);
    float t = 1.f - 2.f / (__expf(2.f * u) + 1.f);   // tanh(u)
    return 0.5f * v * (1.f + t);
}

// ---------------- combined weight pack (ONE launch) --------------------------
__device__ __forceinline__ unsigned packp(const float* s, int e, int N) {
    int kp = e / N, n = e - kp * N;
    return h2u(s[(size_t)(2 * kp) * N + n], s[(size_t)(2 * kp + 1) * N + n]);
}

__global__ void cvt_all(const float* wqkv, const float* wo,
                        const float* gaq, const float* gak, const float* gav,
                        const float* mrg, const float* ff1, const float* ff2,
                        unsigned* dqkv, unsigned* dwo, unsigned* dga,
                        unsigned* dmrg, unsigned* dff1, unsigned* dff2) {
    int e = blockIdx.x * 256 + threadIdx.x;
    if (e < 221184) { dqkv[e] = packp(wqkv, e, 1152); return; }
    e -= 221184;
    if (e < 73728) { dwo[e] = packp(wo, e, 384); return; }
    e -= 73728;
    if (e < 221184) {   // ga: three [384,384] weights packed to N=1152
        int kp = e / 1152, n = e - kp * 1152;
        int gsel = n / 384, nn = n - gsel * 384;
        const float* src = gsel == 0 ? gaq : (gsel == 1 ? gak : gav);
        dga[e] = h2u(src[(size_t)(2 * kp) * 384 + nn], src[(size_t)(2 * kp + 1) * 384 + nn]);
        return;
    }
    e -= 221184;
    if (e < 147456) { dmrg[e] = packp(mrg, e, 384); return; }
    e -= 147456;
    if (e < 147456) { dff1[e] = packp(ff1, e, 768); return; }
    e -= 147456;
    if (e < 147456) { dff2[e] = packp(ff2, e, 384); return; }
}

// ---------------- LN1 + transpose ------------------------------------------
__global__ void prep_ln1(const float* __restrict__ feat,
                         const float* __restrict__ g, const float* __restrict__ b,
                         float* __restrict__ f, __half* __restrict__ nf) {
    int m = blockIdx.x;
    int bb = m >> 11, n = m & 2047;
    const float* src = feat + (size_t)bb * DMODEL * NPTS + n;
    float v[3];
    float s = 0.f, s2 = 0.f;
#pragma unroll
    for (int i = 0; i < 3; i++) {
        int d = threadIdx.x + i * 128;
        float x = src[(size_t)d * NPTS];
        v[i] = x; s += x; s2 += x * x;
    }
#pragma unroll
    for (int o = 16; o; o >>= 1) {
        s  += __shfl_xor_sync(0xffffffffu, s, o);
        s2 += __shfl_xor_sync(0xffffffffu, s2, o);
    }
    __shared__ float sh[8];
    int w = threadIdx.x >> 5;
    if ((threadIdx.x & 31) == 0) { sh[w] = s; sh[4 + w] = s2; }
    __syncthreads();
    s  = sh[0] + sh[1] + sh[2] + sh[3];
    s2 = sh[4] + sh[5] + sh[6] + sh[7];
    float mean = s * (1.f / DMODEL);
    float var  = s2 * (1.f / DMODEL) - mean * mean;
    float rstd = rsqrtf(var + 1e-5f);
#pragma unroll
    for (int i = 0; i < 3; i++) {
        int d = threadIdx.x + i * 128;
        float x = v[i];
        f[(size_t)m * DMODEL + d]  = x;
        nf[(size_t)m * DMODEL + d] = __float2half((x - mean) * rstd * g[d] + b[d]);
    }
}

// ---------------- LN2: f fp32 -> h fp16 ------------------------------------
__global__ void ln2_k(const float* __restrict__ f,
                      const float* __restrict__ g, const float* __restrict__ b,
                      __half* __restrict__ h) {
    int m = blockIdx.x;
    const float* row = f + (size_t)m * DMODEL;
    float v[3];
    float s = 0.f, s2 = 0.f;
#pragma unroll
    for (int i = 0; i < 3; i++) {
        int d = threadIdx.x + i * 128;
        float x = row[d];
        v[i] = x; s += x; s2 += x * x;
    }
#pragma unroll
    for (int o = 16; o; o >>= 1) {
        s  += __shfl_xor_sync(0xffffffffu, s, o);
        s2 += __shfl_xor_sync(0xffffffffu, s2, o);
    }
    __shared__ float sh[8];
    int w = threadIdx.x >> 5;
    if ((threadIdx.x & 31) == 0) { sh[w] = s; sh[4 + w] = s2; }
    __syncthreads();
    s  = sh[0] + sh[1] + sh[2] + sh[3];
    s2 = sh[4] + sh[5] + sh[6] + sh[7];
    float mean = s * (1.f / DMODEL);
    float var  = s2 * (1.f / DMODEL) - mean * mean;
    float rstd = rsqrtf(var + 1e-5f);
#pragma unroll
    for (int i = 0; i < 3; i++) {
        int d = threadIdx.x + i * 128;
        h[(size_t)m * DMODEL + d] = __float2half((v[i] - mean) * rstd * g[d] + b[d]);
    }
}

// ---------------- brute force KNN top-8 ------------------------------------
__global__ void knn_kernel(const float* __restrict__ coords, int* __restrict__ idxout) {
    int bb = blockIdx.y;
    __shared__ float cx[NPTS], cy[NPTS], cz[NPTS], sq[NPTS];
    const float* cb = coords + (size_t)bb * 3 * NPTS;
    for (int i = threadIdx.x; i < NPTS; i += 256) {
        float x = cb[i], y = cb[NPTS + i], z = cb[2 * NPTS + i];
        cx[i] = x; cy[i] = y; cz[i] = z;
        sq[i] = x * x + y * y + z * z;
    }
    __syncthreads();
    int q = blockIdx.x * 256 + threadIdx.x;
    float qx = cx[q], qy = cy[q], qz = cz[q], qsq = sq[q];
    float bd[KNN]; int bi[KNN];
#pragma unroll
    for (int k = 0; k < KNN; k++) { bd[k] = 3.0e38f; bi[k] = 0; }
    for (int mi = 0; mi < NPTS; mi++) {
        float d = qsq + sq[mi] - 2.f * (qx * cx[mi] + qy * cy[mi] + qz * cz[mi]);
        if (d < bd[KNN - 1]) {
            int p = KNN - 1;
            while (p > 0 && bd[p - 1] > d) { bd[p] = bd[p - 1]; bi[p] = bi[p - 1]; p--; }
            bd[p] = d; bi[p] = mi;
        }
    }
#pragma unroll
    for (int k = 0; k < KNN; k++)
        idxout[((size_t)bb * NPTS + q) * KNN + k] = bi[k];
}

// ---------------- fp16 GEMM: C[M,N] = A[M,K] @ W[K,N] -----------------------
// Block 128x128, 8 warps (2 wm x 4 wn), warp tile 64x32, K-block 32 (2x k16).
// A half [row][k], row stride 20 u32 = 80 B (16B-aligned for cp.async).
// B pair-packed [kpair][n] stride 136 u32 = 544 B.
// EPI: 0 half store(+bias), 1 half gelu(+bias), 2 float +=(+bias),
//      3 QKV: cols<768 -> qk half, cols>=768 -> vt (transposed half)
//      4 final: read f (Cv), add, write fp32 TRANSPOSED to fout [B,D,N]
#define GA_ST 20
#define GB_ST 136
#define GA_BUF (128 * GA_ST)
#define GB_BUF (16 * GB_ST)
#define GEMM_SMEM ((2 * GA_BUF + 2 * GB_BUF) * 4)

template <int EPI>
__global__ __launch_bounds__(256, 2)
void gemm_f16(const __half* __restrict__ A, const unsigned* __restrict__ Wp,
              const float* __restrict__ bias, void* Cv, __half* __restrict__ vt,
              float* __restrict__ fout, int M, int K, int N, int ldc) {
    extern __shared__ unsigned smu[];
    unsigned* Ab = smu;
    unsigned* Bb = smu + 2 * GA_BUF;

    int tid = threadIdx.x;
    int w = tid >> 5, lane = tid & 31;
    int gid = lane >> 2, tig = lane & 3;
    int wm = w >> 2, wn = w & 3;
    int rowBase = blockIdx.y * 128, colBase = blockIdx.x * 128;

    // k-block 0 copies
#pragma unroll
    for (int i = 0; i < 2; i++) {
        int e = tid + i * 256;
        int r = e >> 2, c = e & 3;
        cp16(Ab + r * GA_ST + c * 4, A + (size_t)(rowBase + r) * K + c * 8);
    }
#pragma unroll
    for (int i = 0; i < 2; i++) {
        int e = tid + i * 256;
        int r = e >> 5, c = e & 31;
        cp16(Bb + r * GB_ST + c * 4, Wp + (size_t)r * N + colBase + c * 4);
    }
    CP_COMMIT();

    float c[4][4][4];
#pragma unroll
    for (int mt = 0; mt < 4; mt++)
#pragma unroll
        for (int j = 0; j < 4; j++)
#pragma unroll
            for (int e = 0; e < 4; e++) c[mt][j][e] = 0.f;

    int nblk = K / 32;
    for (int kb = 0; kb < nblk; kb++) {
        int buf = kb & 1;
        CP_WAIT(0);
        __syncthreads();
        if (kb + 1 < nblk) {
            int nb = buf ^ 1;
            int k0 = (kb + 1) * 32;
#pragma unroll
            for (int i = 0; i < 2; i++) {
                int e = tid + i * 256;
                int r = e >> 2, cc = e & 3;
                cp16(Ab + nb * GA_BUF + r * GA_ST + cc * 4,
                     A + (size_t)(rowBase + r) * K + k0 + cc * 8);
            }
#pragma unroll
            for (int i = 0; i < 2; i++) {
                int e = tid + i * 256;
                int r = e >> 5, cc = e & 31;
                cp16(Bb + nb * GB_BUF + r * GB_ST + cc * 4,
                     Wp + (size_t)(k0 / 2 + r) * N + colBase + cc * 4);
            }
            CP_COMMIT();
        }
        const unsigned* Au = Ab + buf * GA_BUF;
        const unsigned* Bu = Bb + buf * GB_BUF;
#pragma unroll
        for (int ksg = 0; ksg < 2; ksg++) {
            int ks8 = ksg * 8;
            unsigned af[4][4];
#pragma unroll
            for (int mt = 0; mt < 4; mt++) {
                int r0 = wm * 64 + mt * 16 + gid;
                af[mt][0] = Au[r0 * GA_ST + ks8 + tig];
                af[mt][1] = Au[(r0 + 8) * GA_ST + ks8 + tig];
                af[mt][2] = Au[r0 * GA_ST + ks8 + tig + 4];
                af[mt][3] = Au[(r0 + 8) * GA_ST + ks8 + tig + 4];
            }
#pragma unroll
            for (int j = 0; j < 4; j++) {
                int nc = wn * 32 + j * 8 + gid;
                unsigned b0 = Bu[(ks8 + tig) * GB_ST + nc];
                unsigned b1 = Bu[(ks8 + tig + 4) * GB_ST + nc];
#pragma unroll
                for (int mt = 0; mt < 4; mt++)
                    mma_f16(c[mt][j], af[mt], b0, b1);
            }
        }
    }
    // epilogue
#pragma unroll
    for (int mt = 0; mt < 4; mt++) {
#pragma unroll
        for (int j = 0; j < 4; j++) {
            int r = rowBase + wm * 64 + mt * 16 + gid;
            int cc = colBase + wn * 32 + j * 8 + tig * 2;
            float b0 = bias ? bias[cc] : 0.f;
            float b1 = bias ? bias[cc + 1] : 0.f;
#pragma unroll
            for (int half = 0; half < 2; half++) {
                int rr = r + half * 8;
                float v0 = c[mt][j][half * 2 + 0] + b0;
                float v1 = c[mt][j][half * 2 + 1] + b1;
                if (EPI == 1) { v0 = gelu_f(v0); v1 = gelu_f(v1); }
                if (EPI == 2) {
                    float2* dst = (float2*)((float*)Cv + (size_t)rr * ldc + cc);
                    float2 old = *dst;
                    dst->x = old.x + v0; dst->y = old.y + v1;
                } else if (EPI == 3) {
                    if (cc < 768) {
                        *(unsigned*)((__half*)Cv + (size_t)rr * 768 + cc) = h2u(v0, v1);
                    } else {
                        int bb = rr >> 11, n = rr & 2047;
                        size_t base = ((size_t)bb * DMODEL + (cc - 768)) * NPTS + n;
                        vt[base] = __float2half(v0);
                        vt[base + NPTS] = __float2half(v1);
                    }
                } else if (EPI == 4) {
                    const float* fsrc = (const float*)Cv;
                    float o0 = fsrc[(size_t)rr * DMODEL + cc] + v0;
                    float o1 = fsrc[(size_t)rr * DMODEL + cc + 1] + v1;
                    int bb = rr >> 11, n = rr & 2047;
                    fout[((size_t)bb * DMODEL + cc) * NPTS + n] = o0;
                    fout[((size_t)bb * DMODEL + cc + 1) * NPTS + n] = o1;
                } else {
                    *(unsigned*)((__half*)Cv + (size_t)rr * ldc + cc) = h2u(v0, v1);
                }
            }
        }
    }
}

// ---------------- fp16 flash attention --------------------------------------
// CTA: 128 q-rows x one (b,h). 8 warps; warp = 16q x full 64-kv chunk.
// smem (u32): Q[128][36] + 2 x {K[64][36], V^T[64][36]}  = 55296 B
#define AQH 36
#define ATT_SMEM ((128 * AQH + 4 * 64 * AQH) * 4)

__global__ __launch_bounds__(256, 2)
void attn_tc(const __half* __restrict__ qk, const __half* __restrict__ vt,
             __half* __restrict__ attn_o) {
    extern __shared__ unsigned smu[];
    unsigned* Qu = smu;
    unsigned* KV = smu + 128 * AQH;   // per buf: K 64*36 then V 64*36

    int qt = blockIdx.x, h = blockIdx.y, bb = blockIdx.z;
    int tid = threadIdx.x;
    int w = tid >> 5, lane = tid & 31;
    int gid = lane >> 2, tig = lane & 3;
    int qs = w * 16;
    const __half* qbase = qk + (size_t)bb * NPTS * 768;
    const __half* vbase = vt + ((size_t)bb * DMODEL + h * 64) * NPTS;

    // Q loads (group 0)
#pragma unroll
    for (int i = 0; i < 4; i++) {
        int t = tid + i * 256;
        int r = t >> 3, c = t & 7;
        cp16(Qu + r * AQH + c * 4,
             qbase + (size_t)(qt * 128 + r) * 768 + h * 64 + c * 8);
    }
    CP_COMMIT();
    // chunk 0 (group 1)
#pragma unroll
    for (int i = 0; i < 2; i++) {
        int t = tid + i * 256;
        int r = t >> 3, c = t & 7;
        cp16(KV + r * AQH + c * 4,
             qbase + (size_t)r * 768 + 384 + h * 64 + c * 8);
        cp16(KV + (64 + r) * AQH + c * 4,
             vbase + (size_t)r * NPTS + c * 8);
    }
    CP_COMMIT();

    CP_WAIT(1);
    __syncthreads();

    // preload Q fragments (4 k16-groups over d=64)
    unsigned qa[4][4];
#pragma unroll
    for (int s2 = 0; s2 < 4; s2++) {
        qa[s2][0] = Qu[(qs + gid) * AQH + s2 * 8 + tig];
        qa[s2][1] = Qu[(qs + gid + 8) * AQH + s2 * 8 + tig];
        qa[s2][2] = Qu[(qs + gid) * AQH + s2 * 8 + tig + 4];
        qa[s2][3] = Qu[(qs + gid + 8) * AQH + s2 * 8 + tig + 4];
    }

    float oc[8][4];
#pragma unroll
    for (int j = 0; j < 8; j++)
#pragma unroll
        for (int e = 0; e < 4; e++) oc[j][e] = 0.f;
    float m0 = -1e30f, m1 = -1e30f, l0 = 0.f, l1 = 0.f;

    for (int jt = 0; jt < NPTS / 64; jt++) {
        int buf = jt & 1;
        CP_WAIT(0);
        __syncthreads();
        if (jt + 1 < NPTS / 64) {
            int nb = buf ^ 1;
#pragma unroll
            for (int i = 0; i < 2; i++) {
                int t = tid + i * 256;
                int r = t >> 3, c = t & 7;
                cp16(KV + nb * 4608 + r * AQH + c * 4,
                     qbase + (size_t)((jt + 1) * 64 + r) * 768 + 384 + h * 64 + c * 8);
                cp16(KV + nb * 4608 + (64 + r) * AQH + c * 4,
                     vbase + (size_t)r * NPTS + (jt + 1) * 64 + c * 8);
            }
            CP_COMMIT();
        }
        const unsigned* Ku = KV + buf * 4608;
        const unsigned* Vu = Ku + 64 * AQH;

        // --- S = Q @ K^T : 16q x 64kv ---
        float ps[8][4];
#pragma unroll
        for (int j = 0; j < 8; j++)
#pragma unroll
            for (int e = 0; e < 4; e++) ps[j][e] = 0.f;
#pragma unroll
        for (int s2 = 0; s2 < 4; s2++) {
#pragma unroll
            for (int j = 0; j < 8; j++) {
                unsigned b0 = Ku[(j * 8 + gid) * AQH + s2 * 8 + tig];
                unsigned b1 = Ku[(j * 8 + gid) * AQH + s2 * 8 + tig + 4];
                mma_f16(ps[j], qa[s2], b0, b1);
            }
        }
#pragma unroll
        for (int j = 0; j < 8; j++) {
            ps[j][0] *= 0.125f; ps[j][1] *= 0.125f;
            ps[j][2] *= 0.125f; ps[j][3] *= 0.125f;
        }

        // --- online softmax in registers ---
        float mx0 = -1e30f, mx1 = -1e30f;
#pragma unroll
        for (int j = 0; j < 8; j++) {
            mx0 = fmaxf(mx0, fmaxf(ps[j][0], ps[j][1]));
            mx1 = fmaxf(mx1, fmaxf(ps[j][2], ps[j][3]));
        }
        mx0 = fmaxf(mx0, __shfl_xor_sync(0xffffffffu, mx0, 1));
        mx0 = fmaxf(mx0, __shfl_xor_sync(0xffffffffu, mx0, 2));
        mx1 = fmaxf(mx1, __shfl_xor_sync(0xffffffffu, mx1, 1));
        mx1 = fmaxf(mx1, __shfl_xor_sync(0xffffffffu, mx1, 2));
        float mn0 = fmaxf(m0, mx0), mn1 = fmaxf(m1, mx1);
        float cr0 = __expf(m0 - mn0), cr1 = __expf(m1 - mn1);
        float s0 = 0.f, s1 = 0.f;
#pragma unroll
        for (int j = 0; j < 8; j++) {
            ps[j][0] = __expf(ps[j][0] - mn0); s0 += ps[j][0];
            ps[j][1] = __expf(ps[j][1] - mn0); s0 += ps[j][1];
            ps[j][2] = __expf(ps[j][2] - mn1); s1 += ps[j][2];
            ps[j][3] = __expf(ps[j][3] - mn1); s1 += ps[j][3];
        }
        s0 += __shfl_xor_sync(0xffffffffu, s0, 1);
        s0 += __shfl_xor_sync(0xffffffffu, s0, 2);
        s1 += __shfl_xor_sync(0xffffffffu, s1, 1);
        s1 += __shfl_xor_sync(0xffffffffu, s1, 2);
        l0 = l0 * cr0 + s0; l1 = l1 * cr1 + s1;
        m0 = mn0; m1 = mn1;
#pragma unroll
        for (int j = 0; j < 8; j++) {
            oc[j][0] *= cr0; oc[j][1] *= cr0;
            oc[j][2] *= cr1; oc[j][3] *= cr1;
        }

        // --- O += P @ V^T : accumulator layout == fp16 A-frag layout ---
#pragma unroll
        for (int j2 = 0; j2 < 4; j2++) {
            unsigned pa[4];
            pa[0] = h2u(ps[2 * j2][0], ps[2 * j2][1]);
            pa[1] = h2u(ps[2 * j2][2], ps[2 * j2][3]);
            pa[2] = h2u(ps[2 * j2 + 1][0], ps[2 * j2 + 1][1]);
            pa[3] = h2u(ps[2 * j2 + 1][2], ps[2 * j2 + 1][3]);
#pragma unroll
            for (int jd = 0; jd < 8; jd++) {
                unsigned b0 = Vu[(jd * 8 + gid) * AQH + j2 * 8 + tig];
                unsigned b1 = Vu[(jd * 8 + gid) * AQH + j2 * 8 + tig + 4];
                mma_f16(oc[jd], pa, b0, b1);
            }
        }
    }

    // --- normalize & store fp16 ---
    float inv0 = 1.f / l0, inv1 = 1.f / l1;
    int r0 = bb * NPTS + qt * 128 + qs + gid;
#pragma unroll
    for (int j = 0; j < 8; j++) {
        int cc = h * 64 + j * 8 + tig * 2;
        *(unsigned*)(attn_o + (size_t)r0 * DMODEL + cc) = h2u(oc[j][0] * inv0, oc[j][1] * inv0);
        *(unsigned*)(attn_o + (size_t)(r0 + 8) * DMODEL + cc) = h2u(oc[j][2] * inv1, oc[j][3] * inv1);
    }
}

// ---------------- geom branch: gather + softmax(K=8), half2 -----------------
__global__ void geom_kernel(const __half* __restrict__ gqkv, const int* __restrict__ idx,
                            __half* __restrict__ merged) {
    int m = blockIdx.x;
    int bb = m >> 11;
    __shared__ float dots[KNN];
    __shared__ int nb[KNN];
    int tid = threadIdx.x, w = tid >> 5, lane = tid & 31;
    if (tid < KNN) nb[tid] = idx[(size_t)m * KNN + tid];
    __syncthreads();
    const __half2* qrow = (const __half2*)(gqkv + (size_t)m * 1152);
    const __half2* krow = (const __half2*)(gqkv + ((size_t)bb * NPTS + nb[w]) * 1152 + 384);
    float s = 0.f;
    for (int d = lane; d < 192; d += 32) {
        float2 q2 = __half22float2(qrow[d]);
        float2 k2 = __half22float2(krow[d]);
        s += q2.x * k2.x + q2.y * k2.y;
    }
#pragma unroll
    for (int o = 16; o; o >>= 1) s += __shfl_xor_sync(0xffffffffu, s, o);
    if (lane == 0) dots[w] = s * 0.05103103630798287f;
    __syncthreads();
    float mx = dots[0];
#pragma unroll
    for (int k = 1; k < KNN; k++) mx = fmaxf(mx, dots[k]);
    float p[KNN], sum = 0.f;
#pragma unroll
    for (int k = 0; k < KNN; k++) { p[k] = __expf(dots[k] - mx); sum += p[k]; }
    float inv = 1.f / sum;
    for (int d2 = tid; d2 < 192; d2 += 256) {
        float a0 = 0.f, a1 = 0.f;
#pragma unroll
        for (int k = 0; k < KNN; k++) {
            float2 v2 = __half22float2(*(const __half2*)(gqkv + ((size_t)bb * NPTS + nb[k]) * 1152 + 768 + 2 * d2));
            a0 += p[k] * v2.x; a1 += p[k] * v2.y;
        }
        *(__half2*)(merged + (size_t)m * 768 + 384 + 2 * d2) = __floats2half2_rn(a0 * inv, a1 * inv);
    }
}

// ---------------- launch ----------------------------------------------------
extern "C" void kernel_launch(void* const* d_in, const int* in_sizes, int n_in,
                              void* d_out, int out_size) {
    const float* coords     = (const float*)d_in[0];
    const float* features   = (const float*)d_in[1];
    const float* ln1_g      = (const float*)d_in[2];
    const float* ln1_b      = (const float*)d_in[3];
    const float* w_qkv      = (const float*)d_in[4];
    const float* w_attn_out = (const float*)d_in[5];
    const float* b_attn_out = (const float*)d_in[6];
    const float* ga_wq      = (const float*)d_in[7];
    const float* ga_wk      = (const float*)d_in[8];
    const float* ga_wv      = (const float*)d_in[9];
    const float* merge_w    = (const float*)d_in[10];
    const float* merge_b    = (const float*)d_in[11];
    const float* ln2_g      = (const float*)d_in[12];
    const float* ln2_b      = (const float*)d_in[13];
    const float* ff_w1      = (const float*)d_in[14];
    const float* ff_b1      = (const float*)d_in[15];
    const float* ff_w2      = (const float*)d_in[16];
    const float* ff_b2      = (const float*)d_in[17];
    float* out = (float*)d_out;

    float* pf; __half *pnf, *pqk, *pvt, *pattn, *pgqkv, *pmerged, *ph, *pt;
    int* pidx;
    unsigned *pwqkv, *pwo, *pga, *pmrg, *pff1, *pff2;
    cudaGetSymbolAddress((void**)&pf, g_f);
    cudaGetSymbolAddress((void**)&pnf, g_nf);
    cudaGetSymbolAddress((void**)&pqk, g_qk);
    cudaGetSymbolAddress((void**)&pvt, g_vt);
    cudaGetSymbolAddress((void**)&pattn, g_attn);
    cudaGetSymbolAddress((void**)&pgqkv, g_gqkv);
    cudaGetSymbolAddress((void**)&pmerged, g_merged);
    cudaGetSymbolAddress((void**)&ph, g_h);
    cudaGetSymbolAddress((void**)&pt, g_t);
    cudaGetSymbolAddress((void**)&pidx, g_idx);
    cudaGetSymbolAddress((void**)&pwqkv, g_wqkv_p);
    cudaGetSymbolAddress((void**)&pwo, g_wo_p);
    cudaGetSymbolAddress((void**)&pga, g_ga_p);
    cudaGetSymbolAddress((void**)&pmrg, g_mrg_p);
    cudaGetSymbolAddress((void**)&pff1, g_ff1_p);
    cudaGetSymbolAddress((void**)&pff2, g_ff2_p);

    cudaFuncSetAttribute(attn_tc, cudaFuncAttributeMaxDynamicSharedMemorySize, ATT_SMEM);
    cudaFuncSetAttribute(gemm_f16<0>, cudaFuncAttributeMaxDynamicSharedMemorySize, GEMM_SMEM);
    cudaFuncSetAttribute(gemm_f16<1>, cudaFuncAttributeMaxDynamicSharedMemorySize, GEMM_SMEM);
    cudaFuncSetAttribute(gemm_f16<2>, cudaFuncAttributeMaxDynamicSharedMemorySize, GEMM_SMEM);
    cudaFuncSetAttribute(gemm_f16<3>, cudaFuncAttributeMaxDynamicSharedMemorySize, GEMM_SMEM);
    cudaFuncSetAttribute(gemm_f16<4>, cudaFuncAttributeMaxDynamicSharedMemorySize, GEMM_SMEM);

    // one combined weight-pack launch (958464 pairs)
    cvt_all<<<3744, 256>>>(w_qkv, w_attn_out, ga_wq, ga_wk, ga_wv, merge_w, ff_w1, ff_w2,
                           pwqkv, pwo, pga, pmrg, pff1, pff2);

    prep_ln1<<<MTOK, 128>>>(features, ln1_g, ln1_b, pf, pnf);
    knn_kernel<<<dim3(NPTS / 256, BATCH), 256>>>(coords, pidx);
    gemm_f16<3><<<dim3(9, MTOK / 128), 256, GEMM_SMEM>>>(pnf, pwqkv, nullptr, pqk, pvt, nullptr, MTOK, 384, 1152, 768);
    attn_tc<<<dim3(NPTS / 128, NHEAD, BATCH), 256, ATT_SMEM>>>(pqk, pvt, pattn);
    gemm_f16<0><<<dim3(3, MTOK / 128), 256, GEMM_SMEM>>>(pattn, pwo, b_attn_out, pmerged, nullptr, nullptr, MTOK, 384, 384, 768);
    // combined gq|gk|gv projection (one launch, N=1152)
    gemm_f16<0><<<dim3(9, MTOK / 128), 256, GEMM_SMEM>>>(pnf, pga, nullptr, pgqkv, nullptr, nullptr, MTOK, 384, 1152, 1152);
    geom_kernel<<<MTOK, 256>>>(pgqkv, pidx, pmerged);
    gemm_f16<2><<<dim3(3, MTOK / 128), 256, GEMM_SMEM>>>(pmerged, pmrg, merge_b, pf, nullptr, nullptr, MTOK, 768, 384, 384);
    ln2_k<<<MTOK, 128>>>(pf, ln2_g, ln2_b, ph);
    gemm_f16<1><<<dim3(6, MTOK / 128), 256, GEMM_SMEM>>>(ph, pff1, ff_b1, pt, nullptr, nullptr, MTOK, 384, 768, 768);
    // final FFN GEMM: add residual f and write transposed fp32 output directly
    gemm_f16<4><<<dim3(3, MTOK / 128), 256, GEMM_SMEM>>>(pt, pff2, ff_b2, pf, nullptr, out, MTOK, 768, 384, 384);
}

// round 17
// speedup vs baseline: 5.1384x; 1.0197x over previous
#include <cuda_runtime.h>
#include <cuda_fp16.h>
#include <math.h>

#define BATCH 8
#define NPTS 2048
#define DMODEL 384
#define NHEAD 6
#define KNN 8
#define MTOK (BATCH * NPTS)   // 16384

// ---------------- scratch (device globals; no allocation allowed) ----------
__device__ float  g_f[MTOK * DMODEL];            // residual, fp32
__device__ __half g_nf[MTOK * DMODEL];
__device__ __half g_qk[MTOK * 2 * DMODEL];       // [M][768]: Q | K
__device__ __half g_vt[BATCH * DMODEL * NPTS];   // V transposed: [b][h*64+d][n]
__device__ __half g_attn[MTOK * DMODEL];
__device__ __half g_gqkv[MTOK * 3 * DMODEL];     // [M][1152]: gq | gk | gv
__device__ __half g_merged[MTOK * 2 * DMODEL];
__device__ __half g_h[MTOK * DMODEL];
__device__ __half g_t[MTOK * 2 * DMODEL];
__device__ int    g_idx[MTOK * KNN];
// pair-packed fp16 weights (u32 = half2 of rows k, k+1)
__device__ unsigned g_wqkv_p[192 * 1152];
__device__ unsigned g_wo_p[192 * 384];
__device__ unsigned g_ga_p[192 * 1152];          // wq | wk | wv side by side
__device__ unsigned g_mrg_p[384 * 384];
__device__ unsigned g_ff1_p[192 * 768];
__device__ unsigned g_ff2_p[384 * 384];

// ---------------- helpers ---------------------------------------------------
__device__ __forceinline__ void mma_f16(float* c, const unsigned* a, unsigned b0, unsigned b1) {
    asm volatile("mma.sync.aligned.m16n8k16.row.col.f32.f16.f16.f32 "
        "{%0,%1,%2,%3}, {%4,%5,%6,%7}, {%8,%9}, {%0,%1,%2,%3};"
        : "+f"(c[0]), "+f"(c[1]), "+f"(c[2]), "+f"(c[3])
        : "r"(a[0]), "r"(a[1]), "r"(a[2]), "r"(a[3]), "r"(b0), "r"(b1));
}

__device__ __forceinline__ unsigned h2u(float a, float b) {
    __half2 h = __floats2half2_rn(a, b);
    return *(unsigned*)&h;
}

__device__ __forceinline__ void cp16(void* dst, const void* src) {
    unsigned d = (unsigned)__cvta_generic_to_shared(dst);
    asm volatile("cp.async.ca.shared.global [%0], [%1], 16;\n" :: "r"(d), "l"(src));
}
#define CP_COMMIT() asm volatile("cp.async.commit_group;\n" ::: "memory")
#define CP_WAIT(N)  asm volatile("cp.async.wait_group %0;\n" :: "n"(N) : "memory")

__device__ __forceinline__ float gelu_f(float v) {
    float u = 0.7978845608028654f * (v + 0.044715f * v * v * v);
    float t = 1.f - 2.f / (__expf(2.f * u) + 1.f);   // tanh(u)
    return 0.5f * v * (1.f + t);
}

// ---------------- combined weight pack (ONE launch) --------------------------
__device__ __forceinline__ unsigned packp(const float* s, int e, int N) {
    int kp = e / N, n = e - kp * N;
    return h2u(s[(size_t)(2 * kp) * N + n], s[(size_t)(2 * kp + 1) * N + n]);
}

__global__ void cvt_all(const float* wqkv, const float* wo,
                        const float* gaq, const float* gak, const float* gav,
                        const float* mrg, const float* ff1, const float* ff2,
                        unsigned* dqkv, unsigned* dwo, unsigned* dga,
                        unsigned* dmrg, unsigned* dff1, unsigned* dff2) {
    int e = blockIdx.x * 256 + threadIdx.x;
    if (e < 221184) { dqkv[e] = packp(wqkv, e, 1152); return; }
    e -= 221184;
    if (e < 73728) { dwo[e] = packp(wo, e, 384); return; }
    e -= 73728;
    if (e < 221184) {   // ga: three [384,384] weights packed to N=1152
        int kp = e / 1152, n = e - kp * 1152;
        int gsel = n / 384, nn = n - gsel * 384;
        const float* src = gsel == 0 ? gaq : (gsel == 1 ? gak : gav);
        dga[e] = h2u(src[(size_t)(2 * kp) * 384 + nn], src[(size_t)(2 * kp + 1) * 384 + nn]);
        return;
    }
    e -= 221184;
    if (e < 147456) { dmrg[e] = packp(mrg, e, 384); return; }
    e -= 147456;
    if (e < 147456) { dff1[e] = packp(ff1, e, 768); return; }
    e -= 147456;
    if (e < 147456) { dff2[e] = packp(ff2, e, 384); return; }
}

// ---------------- coalesced LN1: block = (batch, 32-point strip) -------------
// smem: tile[384][33] fp32 + partial sums; loads coalesced along n.
#define LN1_SMEM ((384 * 33 + 16 * 33 + 64) * 4)
__global__ __launch_bounds__(256)
void ln1_coal(const float* __restrict__ feat,
              const float* __restrict__ g, const float* __restrict__ b,
              float* __restrict__ f, __half* __restrict__ nf) {
    extern __shared__ float sm[];
    float* tile = sm;                   // [384][33]
    float* rs   = sm + 384 * 33;        // [8][33] partial s
    float* rs2  = rs + 8 * 33;          // [8][33] partial s2
    float* mst  = rs2 + 8 * 33;         // [32] mean
    float* rst  = mst + 32;             // [32] rstd

    int bb = blockIdx.y, n0 = blockIdx.x * 32;
    int tid = threadIdx.x;
    int n = tid & 31, dw = tid >> 5;    // fixed n per thread; d-wave
    const float* src = feat + (size_t)bb * DMODEL * NPTS + n0;

    float s = 0.f, s2 = 0.f;
#pragma unroll
    for (int i = 0; i < 48; i++) {
        int d = dw + i * 8;
        float v = src[(size_t)d * NPTS + n];
        tile[d * 33 + n] = v;
        s += v; s2 += v * v;
    }
    rs[dw * 33 + n] = s; rs2[dw * 33 + n] = s2;
    __syncthreads();
    if (tid < 32) {
        float ts = 0.f, ts2 = 0.f;
#pragma unroll
        for (int i = 0; i < 8; i++) { ts += rs[i * 33 + tid]; ts2 += rs2[i * 33 + tid]; }
        float mean = ts * (1.f / DMODEL);
        float var = ts2 * (1.f / DMODEL) - mean * mean;
        mst[tid] = mean; rst[tid] = rsqrtf(var + 1e-5f);
    }
    __syncthreads();
    // coalesced writes: warp covers consecutive d for one n
    int wn = tid >> 7;      // 0..1 : two n per pass
    int d0 = tid & 127;
#pragma unroll
    for (int i = 0; i < 16; i++) {
        int nn = i * 2 + wn;
        float mean = mst[nn], rstd = rst[nn];
        size_t m = (size_t)(bb * NPTS + n0 + nn) * DMODEL;
#pragma unroll
        for (int j = 0; j < 3; j++) {
            int d = d0 + j * 128;
            float v = tile[d * 33 + nn];
            f[m + d] = v;
            nf[m + d] = __float2half((v - mean) * rstd * g[d] + b[d]);
        }
    }
}

// ---------------- LN2: f fp32 -> h fp16 ------------------------------------
__global__ void ln2_k(const float* __restrict__ f,
                      const float* __restrict__ g, const float* __restrict__ b,
                      __half* __restrict__ h) {
    int m = blockIdx.x;
    const float* row = f + (size_t)m * DMODEL;
    float v[3];
    float s = 0.f, s2 = 0.f;
#pragma unroll
    for (int i = 0; i < 3; i++) {
        int d = threadIdx.x + i * 128;
        float x = row[d];
        v[i] = x; s += x; s2 += x * x;
    }
#pragma unroll
    for (int o = 16; o; o >>= 1) {
        s  += __shfl_xor_sync(0xffffffffu, s, o);
        s2 += __shfl_xor_sync(0xffffffffu, s2, o);
    }
    __shared__ float sh[8];
    int w = threadIdx.x >> 5;
    if ((threadIdx.x & 31) == 0) { sh[w] = s; sh[4 + w] = s2; }
    __syncthreads();
    s  = sh[0] + sh[1] + sh[2] + sh[3];
    s2 = sh[4] + sh[5] + sh[6] + sh[7];
    float mean = s * (1.f / DMODEL);
    float var  = s2 * (1.f / DMODEL) - mean * mean;
    float rstd = rsqrtf(var + 1e-5f);
#pragma unroll
    for (int i = 0; i < 3; i++) {
        int d = threadIdx.x + i * 128;
        h[(size_t)m * DMODEL + d] = __float2half((v[i] - mean) * rstd * g[d] + b[d]);
    }
}

// ---------------- brute force KNN top-8 ------------------------------------
__global__ void knn_kernel(const float* __restrict__ coords, int* __restrict__ idxout) {
    int bb = blockIdx.y;
    __shared__ float cx[NPTS], cy[NPTS], cz[NPTS], sq[NPTS];
    const float* cb = coords + (size_t)bb * 3 * NPTS;
    for (int i = threadIdx.x; i < NPTS; i += 256) {
        float x = cb[i], y = cb[NPTS + i], z = cb[2 * NPTS + i];
        cx[i] = x; cy[i] = y; cz[i] = z;
        sq[i] = x * x + y * y + z * z;
    }
    __syncthreads();
    int q = blockIdx.x * 256 + threadIdx.x;
    float qx = cx[q], qy = cy[q], qz = cz[q], qsq = sq[q];
    float bd[KNN]; int bi[KNN];
#pragma unroll
    for (int k = 0; k < KNN; k++) { bd[k] = 3.0e38f; bi[k] = 0; }
    for (int mi = 0; mi < NPTS; mi++) {
        float d = qsq + sq[mi] - 2.f * (qx * cx[mi] + qy * cy[mi] + qz * cz[mi]);
        if (d < bd[KNN - 1]) {
            int p = KNN - 1;
            while (p > 0 && bd[p - 1] > d) { bd[p] = bd[p - 1]; bi[p] = bi[p - 1]; p--; }
            bd[p] = d; bi[p] = mi;
        }
    }
#pragma unroll
    for (int k = 0; k < KNN; k++)
        idxout[((size_t)bb * NPTS + q) * KNN + k] = bi[k];
}

// ---------------- fp16 GEMM, 3-stage cp.async pipeline ----------------------
// Block 128x128, 8 warps (2 wm x 4 wn), warp tile 64x32, K-block 32 (2x k16).
// A half [row][k], row stride 20 u32 = 80 B (16B-aligned).
// B pair-packed [kpair][n] stride 136 u32 = 544 B.
// EPI: 0 half store(+bias), 1 half gelu(+bias), 2 float +=(+bias),
//      3 QKV: cols<768 -> qk half, cols>=768 -> vt (transposed half)
//      4 final: read f (Cv), add, write fp32 TRANSPOSED to fout [B,D,N]
#define GA_ST 20
#define GB_ST 136
#define GA_BUF (128 * GA_ST)
#define GB_BUF (16 * GB_ST)
#define NSTAGE 3
#define GEMM_SMEM (NSTAGE * (GA_BUF + GB_BUF) * 4)

template <int EPI>
__global__ __launch_bounds__(256, 2)
void gemm_f16(const __half* __restrict__ A, const unsigned* __restrict__ Wp,
              const float* __restrict__ bias, void* Cv, __half* __restrict__ vt,
              float* __restrict__ fout, int M, int K, int N, int ldc) {
    extern __shared__ unsigned smu[];
    unsigned* Ab = smu;                       // NSTAGE bufs
    unsigned* Bb = smu + NSTAGE * GA_BUF;

    int tid = threadIdx.x;
    int w = tid >> 5, lane = tid & 31;
    int gid = lane >> 2, tig = lane & 3;
    int wm = w >> 2, wn = w & 3;
    int rowBase = blockIdx.y * 128, colBase = blockIdx.x * 128;
    int nblk = K / 32;

    // staging lambdas (manual)
    int ar = tid >> 2, ac = (tid & 3) * 4;    // A: 2 iters cover 128 rows
    int br = tid >> 5, bc = (tid & 31) * 4;   // B: 2 iters cover 16 kpairs

    // prologue: issue stages 0,1
#pragma unroll
    for (int st = 0; st < 2; st++) {
        if (st < nblk) {
            int k0 = st * 32;
#pragma unroll
            for (int i = 0; i < 2; i++) {
                cp16(Ab + st * GA_BUF + (ar + i * 64) * GA_ST + ac,
                     A + (size_t)(rowBase + ar + i * 64) * K + k0 + ac * 2);
                cp16(Bb + st * GB_BUF + (br + i * 8) * GB_ST + bc,
                     Wp + (size_t)(k0 / 2 + br + i * 8) * N + colBase + bc);
            }
        }
        CP_COMMIT();
    }

    float c[4][4][4];
#pragma unroll
    for (int mt = 0; mt < 4; mt++)
#pragma unroll
        for (int j = 0; j < 4; j++)
#pragma unroll
            for (int e = 0; e < 4; e++) c[mt][j][e] = 0.f;

    int stage = 0;
    for (int kb = 0; kb < nblk; kb++) {
        CP_WAIT(1);
        __syncthreads();
        // issue stage kb+2 into buffer (kb+2)%NSTAGE (== (kb-1)%NSTAGE, drained)
        if (kb + 2 < nblk) {
            int st = stage + 2; if (st >= NSTAGE) st -= NSTAGE;
            int k0 = (kb + 2) * 32;
#pragma unroll
            for (int i = 0; i < 2; i++) {
                cp16(Ab + st * GA_BUF + (ar + i * 64) * GA_ST + ac,
                     A + (size_t)(rowBase + ar + i * 64) * K + k0 + ac * 2);
                cp16(Bb + st * GB_BUF + (br + i * 8) * GB_ST + bc,
                     Wp + (size_t)(k0 / 2 + br + i * 8) * N + colBase + bc);
            }
        }
        CP_COMMIT();
        const unsigned* Au = Ab + stage * GA_BUF;
        const unsigned* Bu = Bb + stage * GB_BUF;
#pragma unroll
        for (int ksg = 0; ksg < 2; ksg++) {
            int ks8 = ksg * 8;
            unsigned af[4][4];
#pragma unroll
            for (int mt = 0; mt < 4; mt++) {
                int r0 = wm * 64 + mt * 16 + gid;
                af[mt][0] = Au[r0 * GA_ST + ks8 + tig];
                af[mt][1] = Au[(r0 + 8) * GA_ST + ks8 + tig];
                af[mt][2] = Au[r0 * GA_ST + ks8 + tig + 4];
                af[mt][3] = Au[(r0 + 8) * GA_ST + ks8 + tig + 4];
            }
#pragma unroll
            for (int j = 0; j < 4; j++) {
                int nc = wn * 32 + j * 8 + gid;
                unsigned b0 = Bu[(ks8 + tig) * GB_ST + nc];
                unsigned b1 = Bu[(ks8 + tig + 4) * GB_ST + nc];
#pragma unroll
                for (int mt = 0; mt < 4; mt++)
                    mma_f16(c[mt][j], af[mt], b0, b1);
            }
        }
        if (++stage == NSTAGE) stage = 0;
    }
    // epilogue
#pragma unroll
    for (int mt = 0; mt < 4; mt++) {
#pragma unroll
        for (int j = 0; j < 4; j++) {
            int r = rowBase + wm * 64 + mt * 16 + gid;
            int cc = colBase + wn * 32 + j * 8 + tig * 2;
            float b0 = bias ? bias[cc] : 0.f;
            float b1 = bias ? bias[cc + 1] : 0.f;
#pragma unroll
            for (int half = 0; half < 2; half++) {
                int rr = r + half * 8;
                float v0 = c[mt][j][half * 2 + 0] + b0;
                float v1 = c[mt][j][half * 2 + 1] + b1;
                if (EPI == 1) { v0 = gelu_f(v0); v1 = gelu_f(v1); }
                if (EPI == 2) {
                    float2* dst = (float2*)((float*)Cv + (size_t)rr * ldc + cc);
                    float2 old = *dst;
                    dst->x = old.x + v0; dst->y = old.y + v1;
                } else if (EPI == 3) {
                    if (cc < 768) {
                        *(unsigned*)((__half*)Cv + (size_t)rr * 768 + cc) = h2u(v0, v1);
                    } else {
                        int bb = rr >> 11, n = rr & 2047;
                        size_t base = ((size_t)bb * DMODEL + (cc - 768)) * NPTS + n;
                        vt[base] = __float2half(v0);
                        vt[base + NPTS] = __float2half(v1);
                    }
                } else if (EPI == 4) {
                    const float* fsrc = (const float*)Cv;
                    float o0 = fsrc[(size_t)rr * DMODEL + cc] + v0;
                    float o1 = fsrc[(size_t)rr * DMODEL + cc + 1] + v1;
                    int bb = rr >> 11, n = rr & 2047;
                    fout[((size_t)bb * DMODEL + cc) * NPTS + n] = o0;
                    fout[((size_t)bb * DMODEL + cc + 1) * NPTS + n] = o1;
                } else {
                    *(unsigned*)((__half*)Cv + (size_t)rr * ldc + cc) = h2u(v0, v1);
                }
            }
        }
    }
}

// ---------------- fp16 flash attention (exp2-domain softmax) -----------------
// CTA: 128 q-rows x one (b,h). 8 warps; warp = 16q x full 64-kv chunk.
// smem (u32): Q[128][36] + 2 x {K[64][36], V^T[64][36]}  = 55296 B
#define AQH 36
#define ATT_SMEM ((128 * AQH + 4 * 64 * AQH) * 4)
#define SC_L2 0.1803368801111244f   // 0.125 * log2(e)

__global__ __launch_bounds__(256, 2)
void attn_tc(const __half* __restrict__ qk, const __half* __restrict__ vt,
             __half* __restrict__ attn_o) {
    extern __shared__ unsigned smu[];
    unsigned* Qu = smu;
    unsigned* KV = smu + 128 * AQH;   // per buf: K 64*36 then V 64*36

    int qt = blockIdx.x, h = blockIdx.y, bb = blockIdx.z;
    int tid = threadIdx.x;
    int w = tid >> 5, lane = tid & 31;
    int gid = lane >> 2, tig = lane & 3;
    int qs = w * 16;
    const __half* qbase = qk + (size_t)bb * NPTS * 768;
    const __half* vbase = vt + ((size_t)bb * DMODEL + h * 64) * NPTS;

    // Q loads (group 0)
#pragma unroll
    for (int i = 0; i < 4; i++) {
        int t = tid + i * 256;
        int r = t >> 3, c = t & 7;
        cp16(Qu + r * AQH + c * 4,
             qbase + (size_t)(qt * 128 + r) * 768 + h * 64 + c * 8);
    }
    CP_COMMIT();
    // chunk 0 (group 1)
#pragma unroll
    for (int i = 0; i < 2; i++) {
        int t = tid + i * 256;
        int r = t >> 3, c = t & 7;
        cp16(KV + r * AQH + c * 4,
             qbase + (size_t)r * 768 + 384 + h * 64 + c * 8);
        cp16(KV + (64 + r) * AQH + c * 4,
             vbase + (size_t)r * NPTS + c * 8);
    }
    CP_COMMIT();

    CP_WAIT(1);
    __syncthreads();

    // preload Q fragments (4 k16-groups over d=64)
    unsigned qa[4][4];
#pragma unroll
    for (int s2 = 0; s2 < 4; s2++) {
        qa[s2][0] = Qu[(qs + gid) * AQH + s2 * 8 + tig];
        qa[s2][1] = Qu[(qs + gid + 8) * AQH + s2 * 8 + tig];
        qa[s2][2] = Qu[(qs + gid) * AQH + s2 * 8 + tig + 4];
        qa[s2][3] = Qu[(qs + gid + 8) * AQH + s2 * 8 + tig + 4];
    }

    float oc[8][4];
#pragma unroll
    for (int j = 0; j < 8; j++)
#pragma unroll
        for (int e = 0; e < 4; e++) oc[j][e] = 0.f;
    float m0 = -1e30f, m1 = -1e30f, l0 = 0.f, l1 = 0.f;

    for (int jt = 0; jt < NPTS / 64; jt++) {
        int buf = jt & 1;
        CP_WAIT(0);
        __syncthreads();
        if (jt + 1 < NPTS / 64) {
            int nb = buf ^ 1;
#pragma unroll
            for (int i = 0; i < 2; i++) {
                int t = tid + i * 256;
                int r = t >> 3, c = t & 7;
                cp16(KV + nb * 4608 + r * AQH + c * 4,
                     qbase + (size_t)((jt + 1) * 64 + r) * 768 + 384 + h * 64 + c * 8);
                cp16(KV + nb * 4608 + (64 + r) * AQH + c * 4,
                     vbase + (size_t)r * NPTS + (jt + 1) * 64 + c * 8);
            }
            CP_COMMIT();
        }
        const unsigned* Ku = KV + buf * 4608;
        const unsigned* Vu = Ku + 64 * AQH;

        // --- S = Q @ K^T : 16q x 64kv ---
        float ps[8][4];
#pragma unroll
        for (int j = 0; j < 8; j++)
#pragma unroll
            for (int e = 0; e < 4; e++) ps[j][e] = 0.f;
#pragma unroll
        for (int s2 = 0; s2 < 4; s2++) {
#pragma unroll
            for (int j = 0; j < 8; j++) {
                unsigned b0 = Ku[(j * 8 + gid) * AQH + s2 * 8 + tig];
                unsigned b1 = Ku[(j * 8 + gid) * AQH + s2 * 8 + tig + 4];
                mma_f16(ps[j], qa[s2], b0, b1);
            }
        }
        // scale into log2 domain
#pragma unroll
        for (int j = 0; j < 8; j++) {
            ps[j][0] *= SC_L2; ps[j][1] *= SC_L2;
            ps[j][2] *= SC_L2; ps[j][3] *= SC_L2;
        }

        // --- online softmax in registers (base-2) ---
        float mx0 = -1e30f, mx1 = -1e30f;
#pragma unroll
        for (int j = 0; j < 8; j++) {
            mx0 = fmaxf(mx0, fmaxf(ps[j][0], ps[j][1]));
            mx1 = fmaxf(mx1, fmaxf(ps[j][2], ps[j][3]));
        }
        mx0 = fmaxf(mx0, __shfl_xor_sync(0xffffffffu, mx0, 1));
        mx0 = fmaxf(mx0, __shfl_xor_sync(0xffffffffu, mx0, 2));
        mx1 = fmaxf(mx1, __shfl_xor_sync(0xffffffffu, mx1, 1));
        mx1 = fmaxf(mx1, __shfl_xor_sync(0xffffffffu, mx1, 2));
        float mn0 = fmaxf(m0, mx0), mn1 = fmaxf(m1, mx1);
        float cr0 = exp2f(m0 - mn0), cr1 = exp2f(m1 - mn1);
        float s0 = 0.f, s1 = 0.f;
#pragma unroll
        for (int j = 0; j < 8; j++) {
            ps[j][0] = exp2f(ps[j][0] - mn0); s0 += ps[j][0];
            ps[j][1] = exp2f(ps[j][1] - mn0); s0 += ps[j][1];
            ps[j][2] = exp2f(ps[j][2] - mn1); s1 += ps[j][2];
            ps[j][3] = exp2f(ps[j][3] - mn1); s1 += ps[j][3];
        }
        s0 += __shfl_xor_sync(0xffffffffu, s0, 1);
        s0 += __shfl_xor_sync(0xffffffffu, s0, 2);
        s1 += __shfl_xor_sync(0xffffffffu, s1, 1);
        s1 += __shfl_xor_sync(0xffffffffu, s1, 2);
        l0 = l0 * cr0 + s0; l1 = l1 * cr1 + s1;
        m0 = mn0; m1 = mn1;
#pragma unroll
        for (int j = 0; j < 8; j++) {
            oc[j][0] *= cr0; oc[j][1] *= cr0;
            oc[j][2] *= cr1; oc[j][3] *= cr1;
        }

        // --- O += P @ V^T : accumulator layout == fp16 A-frag layout ---
#pragma unroll
        for (int j2 = 0; j2 < 4; j2++) {
            unsigned pa[4];
            pa[0] = h2u(ps[2 * j2][0], ps[2 * j2][1]);
            pa[1] = h2u(ps[2 * j2][2], ps[2 * j2][3]);
            pa[2] = h2u(ps[2 * j2 + 1][0], ps[2 * j2 + 1][1]);
            pa[3] = h2u(ps[2 * j2 + 1][2], ps[2 * j2 + 1][3]);
#pragma unroll
            for (int jd = 0; jd < 8; jd++) {
                unsigned b0 = Vu[(jd * 8 + gid) * AQH + j2 * 8 + tig];
                unsigned b1 = Vu[(jd * 8 + gid) * AQH + j2 * 8 + tig + 4];
                mma_f16(oc[jd], pa, b0, b1);
            }
        }
    }

    // --- normalize & store fp16 ---
    float inv0 = 1.f / l0, inv1 = 1.f / l1;
    int r0 = bb * NPTS + qt * 128 + qs + gid;
#pragma unroll
    for (int j = 0; j < 8; j++) {
        int cc = h * 64 + j * 8 + tig * 2;
        *(unsigned*)(attn_o + (size_t)r0 * DMODEL + cc) = h2u(oc[j][0] * inv0, oc[j][1] * inv0);
        *(unsigned*)(attn_o + (size_t)(r0 + 8) * DMODEL + cc) = h2u(oc[j][2] * inv1, oc[j][3] * inv1);
    }
}

// ---------------- geom branch: gather + softmax(K=8), half2 -----------------
__global__ void geom_kernel(const __half* __restrict__ gqkv, const int* __restrict__ idx,
                            __half* __restrict__ merged) {
    int m = blockIdx.x;
    int bb = m >> 11;
    __shared__ float dots[KNN];
    __shared__ int nb[KNN];
    int tid = threadIdx.x, w = tid >> 5, lane = tid & 31;
    if (tid < KNN) nb[tid] = idx[(size_t)m * KNN + tid];
    __syncthreads();
    const __half2* qrow = (const __half2*)(gqkv + (size_t)m * 1152);
    const __half2* krow = (const __half2*)(gqkv + ((size_t)bb * NPTS + nb[w]) * 1152 + 384);
    float s = 0.f;
    for (int d = lane; d < 192; d += 32) {
        float2 q2 = __half22float2(qrow[d]);
        float2 k2 = __half22float2(krow[d]);
        s += q2.x * k2.x + q2.y * k2.y;
    }
#pragma unroll
    for (int o = 16; o; o >>= 1) s += __shfl_xor_sync(0xffffffffu, s, o);
    if (lane == 0) dots[w] = s * 0.05103103630798287f;
    __syncthreads();
    float mx = dots[0];
#pragma unroll
    for (int k = 1; k < KNN; k++) mx = fmaxf(mx, dots[k]);
    float p[KNN], sum = 0.f;
#pragma unroll
    for (int k = 0; k < KNN; k++) { p[k] = __expf(dots[k] - mx); sum += p[k]; }
    float inv = 1.f / sum;
    for (int d2 = tid; d2 < 192; d2 += 256) {
        float a0 = 0.f, a1 = 0.f;
#pragma unroll
        for (int k = 0; k < KNN; k++) {
            float2 v2 = __half22float2(*(const __half2*)(gqkv + ((size_t)bb * NPTS + nb[k]) * 1152 + 768 + 2 * d2));
            a0 += p[k] * v2.x; a1 += p[k] * v2.y;
        }
        *(__half2*)(merged + (size_t)m * 768 + 384 + 2 * d2) = __floats2half2_rn(a0 * inv, a1 * inv);
    }
}

// ---------------- launch ----------------------------------------------------
extern "C" void kernel_launch(void* const* d_in, const int* in_sizes, int n_in,
                              void* d_out, int out_size) {
    const float* coords     = (const float*)d_in[0];
    const float* features   = (const float*)d_in[1];
    const float* ln1_g      = (const float*)d_in[2];
    const float* ln1_b      = (const float*)d_in[3];
    const float* w_qkv      = (const float*)d_in[4];
    const float* w_attn_out = (const float*)d_in[5];
    const float* b_attn_out = (const float*)d_in[6];
    const float* ga_wq      = (const float*)d_in[7];
    const float* ga_wk      = (const float*)d_in[8];
    const float* ga_wv      = (const float*)d_in[9];
    const float* merge_w    = (const float*)d_in[10];
    const float* merge_b    = (const float*)d_in[11];
    const float* ln2_g      = (const float*)d_in[12];
    const float* ln2_b      = (const float*)d_in[13];
    const float* ff_w1      = (const float*)d_in[14];
    const float* ff_b1      = (const float*)d_in[15];
    const float* ff_w2      = (const float*)d_in[16];
    const float* ff_b2      = (const float*)d_in[17];
    float* out = (float*)d_out;

    float* pf; __half *pnf, *pqk, *pvt, *pattn, *pgqkv, *pmerged, *ph, *pt;
    int* pidx;
    unsigned *pwqkv, *pwo, *pga, *pmrg, *pff1, *pff2;
    cudaGetSymbolAddress((void**)&pf, g_f);
    cudaGetSymbolAddress((void**)&pnf, g_nf);
    cudaGetSymbolAddress((void**)&pqk, g_qk);
    cudaGetSymbolAddress((void**)&pvt, g_vt);
    cudaGetSymbolAddress((void**)&pattn, g_attn);
    cudaGetSymbolAddress((void**)&pgqkv, g_gqkv);
    cudaGetSymbolAddress((void**)&pmerged, g_merged);
    cudaGetSymbolAddress((void**)&ph, g_h);
    cudaGetSymbolAddress((void**)&pt, g_t);
    cudaGetSymbolAddress((void**)&pidx, g_idx);
    cudaGetSymbolAddress((void**)&pwqkv, g_wqkv_p);
    cudaGetSymbolAddress((void**)&pwo, g_wo_p);
    cudaGetSymbolAddress((void**)&pga, g_ga_p);
    cudaGetSymbolAddress((void**)&pmrg, g_mrg_p);
    cudaGetSymbolAddress((void**)&pff1, g_ff1_p);
    cudaGetSymbolAddress((void**)&pff2, g_ff2_p);

    cudaFuncSetAttribute(attn_tc, cudaFuncAttributeMaxDynamicSharedMemorySize, ATT_SMEM);
    cudaFuncSetAttribute(ln1_coal, cudaFuncAttributeMaxDynamicSharedMemorySize, LN1_SMEM);
    cudaFuncSetAttribute(gemm_f16<0>, cudaFuncAttributeMaxDynamicSharedMemorySize, GEMM_SMEM);
    cudaFuncSetAttribute(gemm_f16<1>, cudaFuncAttributeMaxDynamicSharedMemorySize, GEMM_SMEM);
    cudaFuncSetAttribute(gemm_f16<2>, cudaFuncAttributeMaxDynamicSharedMemorySize, GEMM_SMEM);
    cudaFuncSetAttribute(gemm_f16<3>, cudaFuncAttributeMaxDynamicSharedMemorySize, GEMM_SMEM);
    cudaFuncSetAttribute(gemm_f16<4>, cudaFuncAttributeMaxDynamicSharedMemorySize, GEMM_SMEM);

    // one combined weight-pack launch (958464 pairs)
    cvt_all<<<3744, 256>>>(w_qkv, w_attn_out, ga_wq, ga_wk, ga_wv, merge_w, ff_w1, ff_w2,
                           pwqkv, pwo, pga, pmrg, pff1, pff2);

    ln1_coal<<<dim3(NPTS / 32, BATCH), 256, LN1_SMEM>>>(features, ln1_g, ln1_b, pf, pnf);
    knn_kernel<<<dim3(NPTS / 256, BATCH), 256>>>(coords, pidx);
    gemm_f16<3><<<dim3(9, MTOK / 128), 256, GEMM_SMEM>>>(pnf, pwqkv, nullptr, pqk, pvt, nullptr, MTOK, 384, 1152, 768);
    attn_tc<<<dim3(NPTS / 128, NHEAD, BATCH), 256, ATT_SMEM>>>(pqk, pvt, pattn);
    gemm_f16<0><<<dim3(3, MTOK / 128), 256, GEMM_SMEM>>>(pattn, pwo, b_attn_out, pmerged, nullptr, nullptr, MTOK, 384, 384, 768);
    // combined gq|gk|gv projection (one launch, N=1152)
    gemm_f16<0><<<dim3(9, MTOK / 128), 256, GEMM_SMEM>>>(pnf, pga, nullptr, pgqkv, nullptr, nullptr, MTOK, 384, 1152, 1152);
    geom_kernel<<<MTOK, 256>>>(pgqkv, pidx, pmerged);
    gemm_f16<2><<<dim3(3, MTOK / 128), 256, GEMM_SMEM>>>(pmerged, pmrg, merge_b, pf, nullptr, nullptr, MTOK, 768, 384, 384);
    ln2_k<<<MTOK, 128>>>(pf, ln2_g, ln2_b, ph);
    gemm_f16<1><<<dim3(6, MTOK / 128), 256, GEMM_SMEM>>>(ph, pff1, ff_b1, pt, nullptr, nullptr, MTOK, 384, 768, 768);
    // final FFN GEMM: add residual f and write transposed fp32 output directly
    gemm_f16<4><<<dim3(3, MTOK / 128), 256, GEMM_SMEM>>>(pt, pff2, ff_b2, pf, nullptr, out, MTOK, 768, 384, 384);
}